// round 1
// baseline (speedup 1.0000x reference)
#include <cuda_runtime.h>
#include <math.h>

// Problem constants
#define B_   8
#define L_   2048
#define FIN  32
#define D    256
#define H_   8
#define DH   32
#define DFF  1024
#define S_   40
#define U_   40
#define NL   2

// ---------------- scratch (device globals; no allocation allowed) ----------------
__device__ float g_h  [B_*L_*D];      // residual stream
__device__ float g_q  [B_*L_*D];
__device__ float g_k  [B_*L_*D];
__device__ float g_v  [B_*L_*D];
__device__ float g_ctx[B_*L_*D];
__device__ float g_nx [B_*L_*D];      // attn-out / ffn-out
__device__ float g_ff [B_*L_*DFF];    // ffn intermediate
__device__ float g_M  [B_*H_*L_];
__device__ int   g_top[B_*H_*U_];
__device__ float g_vm [B_*H_*DH];

// ---------------- generic SGEMM: C = A(MxK) @ B(KxN) + bias, optional relu -------
// BM=BN=64, BK=16, 256 threads, 4x4 micro-tile per thread.
__global__ void sgemm_kernel(const float* __restrict__ A, const float* __restrict__ Bm,
                             const float* __restrict__ bias, float* __restrict__ C,
                             int M, int N, int K, int relu)
{
    __shared__ float As[64][17];   // padded: As[row][k]
    __shared__ float Bs[16][64];   // Bs[k][col]
    int tid  = threadIdx.x;
    int brow = blockIdx.y * 64;
    int bcol = blockIdx.x * 64;
    int tr = (tid >> 4) << 2;      // 0..60
    int tc = (tid & 15) << 2;      // 0..60
    float acc[4][4] = {};

    for (int k0 = 0; k0 < K; k0 += 16) {
        #pragma unroll
        for (int i = 0; i < 4; i++) {
            int e = tid + i * 256;          // 0..1023
            int r = e >> 4, c = e & 15;
            As[r][c] = A[(size_t)(brow + r) * K + (k0 + c)];
        }
        #pragma unroll
        for (int i = 0; i < 4; i++) {
            int e = tid + i * 256;
            int r = e >> 6, c = e & 63;
            Bs[r][c] = Bm[(size_t)(k0 + r) * N + (bcol + c)];
        }
        __syncthreads();
        #pragma unroll
        for (int kk = 0; kk < 16; kk++) {
            float a[4], b4[4];
            #pragma unroll
            for (int i = 0; i < 4; i++) a[i]  = As[tr + i][kk];
            #pragma unroll
            for (int j = 0; j < 4; j++) b4[j] = Bs[kk][tc + j];
            #pragma unroll
            for (int i = 0; i < 4; i++)
                #pragma unroll
                for (int j = 0; j < 4; j++)
                    acc[i][j] = fmaf(a[i], b4[j], acc[i][j]);
        }
        __syncthreads();
    }
    #pragma unroll
    for (int i = 0; i < 4; i++) {
        int r = brow + tr + i;
        #pragma unroll
        for (int j = 0; j < 4; j++) {
            float v = acc[i][j] + bias[bcol + tc + j];
            if (relu) v = fmaxf(v, 0.0f);
            C[(size_t)r * N + (bcol + tc + j)] = v;
        }
    }
}

// ---------------- sampled QK -> M score. One warp per (b,h,l), lane = d ----------
__global__ void qk_sample_kernel(const float* __restrict__ q, const float* __restrict__ k,
                                 const int* __restrict__ idx, float* __restrict__ Mout)
{
    int gw   = (blockIdx.x * blockDim.x + threadIdx.x) >> 5;
    int lane = threadIdx.x & 31;
    if (gw >= B_ * H_ * L_) return;
    int l  = gw & (L_ - 1);
    int bh = gw >> 11;
    int b  = bh >> 3, h = bh & 7;

    float qd = q[((size_t)b * L_ + l) * D + h * DH + lane];
    const float* kbase = k + (size_t)b * L_ * D + h * DH;
    const int*   irow  = idx + l * S_;

    float mx = -1e30f, sm = 0.0f;
    for (int s = 0; s < S_; s++) {
        int   ki = __ldg(&irow[s]);
        float p  = qd * __ldg(&kbase[(size_t)ki * D + lane]);
        #pragma unroll
        for (int off = 16; off; off >>= 1) p += __shfl_xor_sync(0xffffffffu, p, off);
        mx = fmaxf(mx, p);
        sm += p;
    }
    if (lane == 0) Mout[gw] = mx - sm * (1.0f / (float)L_);
}

// ---------------- top-40 per (b,h): iterative block argmax, tie -> lowest index ---
__global__ void topk_kernel(const float* __restrict__ Mv, int* __restrict__ top)
{
    int bh  = blockIdx.x;
    int tid = threadIdx.x;
    __shared__ float sv[L_];
    __shared__ float rv[256];
    __shared__ int   ri[256];

    for (int i = tid; i < L_; i += 256) sv[i] = Mv[(size_t)bh * L_ + i];
    __syncthreads();

    for (int r = 0; r < U_; r++) {
        float bv = -1e30f; int bi = 0x7fffffff;
        for (int i = tid; i < L_; i += 256) {
            float v = sv[i];
            if (v > bv || (v == bv && i < bi)) { bv = v; bi = i; }
        }
        rv[tid] = bv; ri[tid] = bi;
        __syncthreads();
        for (int s = 128; s; s >>= 1) {
            if (tid < s) {
                float ov = rv[tid + s]; int oi = ri[tid + s];
                if (ov > rv[tid] || (ov == rv[tid] && oi < ri[tid])) { rv[tid] = ov; ri[tid] = oi; }
            }
            __syncthreads();
        }
        if (tid == 0) { top[bh * U_ + r] = ri[0]; sv[ri[0]] = -1e30f; }
        __syncthreads();
    }
}

// ---------------- v mean over L per (b,h) -----------------------------------------
__global__ void vmean_kernel(const float* __restrict__ v, float* __restrict__ vm)
{
    int bh = blockIdx.x; int b = bh >> 3, h = bh & 7;
    int tid = threadIdx.x;
    int d = tid & 31, seg = tid >> 5;     // 8 segments
    const float* vb = v + (size_t)b * L_ * D + h * DH + d;
    float acc = 0.0f;
    for (int l = seg; l < L_; l += 8) acc += vb[(size_t)l * D];
    __shared__ float sp[8][32];
    sp[seg][d] = acc;
    __syncthreads();
    if (tid < 32) {
        float s = 0.0f;
        #pragma unroll
        for (int i = 0; i < 8; i++) s += sp[i][tid];
        vm[bh * DH + tid] = s * (1.0f / (float)L_);
    }
}

// ---------------- fill ctx with broadcast v-mean ----------------------------------
__global__ void ctxfill_kernel(const float* __restrict__ vm, float* __restrict__ ctx)
{
    int i = blockIdx.x * blockDim.x + threadIdx.x;
    if (i >= B_ * L_ * D) return;
    int dfull = i & (D - 1);
    int b = i / (L_ * D);
    int h = dfull >> 5, d = dfull & 31;
    ctx[i] = vm[((b << 3) + h) * DH + d];
}

// ---------------- reduced attention for top queries, scatter into ctx -------------
// One block per (b,h,u). 256 threads. Softmax row lives in smem.
__global__ void attn_topq_kernel(const float* __restrict__ q, const float* __restrict__ k,
                                 const float* __restrict__ v, const int* __restrict__ top,
                                 float* __restrict__ ctx)
{
    int blk = blockIdx.x;                 // B*H*U
    int u   = blk % U_;
    int bh  = blk / U_;
    int b   = bh >> 3, h = bh & 7;
    int tid = threadIdx.x;

    __shared__ float s_attn[L_];
    __shared__ float s_q[DH];
    __shared__ float s_red[256];
    __shared__ float s_part[8][DH];

    int ql = top[bh * U_ + u];
    if (tid < DH) s_q[tid] = q[((size_t)b * L_ + ql) * D + h * DH + tid];
    __syncthreads();

    const float* kb = k + (size_t)b * L_ * D + h * DH;
    const float scale = rsqrtf((float)DH);
    float lmax = -1e30f;
    for (int l = tid; l < L_; l += 256) {
        const float4* kr = (const float4*)(kb + (size_t)l * D);
        float dot = 0.0f;
        #pragma unroll
        for (int j = 0; j < 8; j++) {
            float4 kv = __ldg(&kr[j]);
            dot += s_q[4*j+0]*kv.x + s_q[4*j+1]*kv.y + s_q[4*j+2]*kv.z + s_q[4*j+3]*kv.w;
        }
        dot *= scale;
        s_attn[l] = dot;
        lmax = fmaxf(lmax, dot);
    }
    s_red[tid] = lmax; __syncthreads();
    for (int s = 128; s; s >>= 1) { if (tid < s) s_red[tid] = fmaxf(s_red[tid], s_red[tid + s]); __syncthreads(); }
    float gmax = s_red[0];
    __syncthreads();

    float lsum = 0.0f;
    for (int l = tid; l < L_; l += 256) {
        float e = __expf(s_attn[l] - gmax);
        s_attn[l] = e;
        lsum += e;
    }
    s_red[tid] = lsum; __syncthreads();
    for (int s = 128; s; s >>= 1) { if (tid < s) s_red[tid] += s_red[tid + s]; __syncthreads(); }
    float inv = 1.0f / s_red[0];
    __syncthreads();

    int d = tid & 31, seg = tid >> 5;
    const float* vb = v + (size_t)b * L_ * D + h * DH + d;
    float acc = 0.0f;
    for (int l = seg; l < L_; l += 8) acc += s_attn[l] * vb[(size_t)l * D];
    s_part[seg][d] = acc;
    __syncthreads();
    if (tid < DH) {
        float s = 0.0f;
        #pragma unroll
        for (int i = 0; i < 8; i++) s += s_part[i][tid];
        ctx[((size_t)b * L_ + ql) * D + h * DH + tid] = s * inv;
    }
}

// ---------------- residual add + LayerNorm (in-place into h) ----------------------
__global__ void add_ln_kernel(float* __restrict__ h, const float* __restrict__ r,
                              const float* __restrict__ g, const float* __restrict__ bb)
{
    int row = blockIdx.x;
    int tid = threadIdx.x;   // 256 == D
    float val = h[(size_t)row * D + tid] + r[(size_t)row * D + tid];
    __shared__ float s_red[256];
    s_red[tid] = val; __syncthreads();
    for (int s = 128; s; s >>= 1) { if (tid < s) s_red[tid] += s_red[tid + s]; __syncthreads(); }
    float mu = s_red[0] * (1.0f / (float)D);
    __syncthreads();
    float dv = val - mu;
    s_red[tid] = dv * dv; __syncthreads();
    for (int s = 128; s; s >>= 1) { if (tid < s) s_red[tid] += s_red[tid + s]; __syncthreads(); }
    float var = s_red[0] * (1.0f / (float)D);
    h[(size_t)row * D + tid] = dv * rsqrtf(var + 1e-5f) * g[tid] + bb[tid];
}

// ---------------- final MLP head: out[b] = relu(h[b,-1]@W1+b1)@W2+b2 --------------
__global__ void head_kernel(const float* __restrict__ h, const float* __restrict__ w1,
                            const float* __restrict__ b1, const float* __restrict__ w2,
                            const float* __restrict__ b2, float* __restrict__ out)
{
    int b = blockIdx.x;
    int j = threadIdx.x;  // 64
    const float* last = h + ((size_t)b * L_ + (L_ - 1)) * D;
    float acc = b1[j];
    for (int d = 0; d < D; d++) acc = fmaf(last[d], w1[d * 64 + j], acc);
    acc = fmaxf(acc, 0.0f) * w2[j];
    __shared__ float s[64];
    s[j] = acc; __syncthreads();
    for (int st = 32; st; st >>= 1) { if (j < st) s[j] += s[j + st]; __syncthreads(); }
    if (j == 0) out[b] = s[0] + b2[0];
}

// ===================================================================================
extern "C" void kernel_launch(void* const* d_in, const int* in_sizes, int n_in,
                              void* d_out, int out_size)
{
    const float* x     = (const float*)d_in[0];
    const int*   idx   = (const int*)  d_in[1];
    const float* w_in  = (const float*)d_in[2];
    const float* b_in  = (const float*)d_in[3];
    const float* wq    = (const float*)d_in[4];
    const float* bq    = (const float*)d_in[5];
    const float* wk    = (const float*)d_in[6];
    const float* bk    = (const float*)d_in[7];
    const float* wv    = (const float*)d_in[8];
    const float* bv    = (const float*)d_in[9];
    const float* wo    = (const float*)d_in[10];
    const float* bo    = (const float*)d_in[11];
    const float* w_ff1 = (const float*)d_in[12];
    const float* b_ff1 = (const float*)d_in[13];
    const float* w_ff2 = (const float*)d_in[14];
    const float* b_ff2 = (const float*)d_in[15];
    const float* ln1_g = (const float*)d_in[16];
    const float* ln1_b = (const float*)d_in[17];
    const float* ln2_g = (const float*)d_in[18];
    const float* ln2_b = (const float*)d_in[19];
    const float* w_fc1 = (const float*)d_in[20];
    const float* b_fc1 = (const float*)d_in[21];
    const float* w_fc2 = (const float*)d_in[22];
    const float* b_fc2 = (const float*)d_in[23];
    float* out = (float*)d_out;

    float *h, *q, *k, *v, *ctx, *nx, *ff, *Mv, *vm; int* top;
    cudaGetSymbolAddress((void**)&h,   g_h);
    cudaGetSymbolAddress((void**)&q,   g_q);
    cudaGetSymbolAddress((void**)&k,   g_k);
    cudaGetSymbolAddress((void**)&v,   g_v);
    cudaGetSymbolAddress((void**)&ctx, g_ctx);
    cudaGetSymbolAddress((void**)&nx,  g_nx);
    cudaGetSymbolAddress((void**)&ff,  g_ff);
    cudaGetSymbolAddress((void**)&Mv,  g_M);
    cudaGetSymbolAddress((void**)&top, g_top);
    cudaGetSymbolAddress((void**)&vm,  g_vm);

    const int Mrows = B_ * L_;                     // 16384
    dim3 gD (D   / 64, Mrows / 64);                // N=256
    dim3 gFF(DFF / 64, Mrows / 64);                // N=1024

    // input projection: h = x @ w_in + b_in
    sgemm_kernel<<<gD, 256>>>(x, w_in, b_in, h, Mrows, D, FIN, 0);

    for (int layer = 0; layer < NL; layer++) {
        const float* wqL = wq + (size_t)layer * D * D;
        const float* wkL = wk + (size_t)layer * D * D;
        const float* wvL = wv + (size_t)layer * D * D;
        const float* woL = wo + (size_t)layer * D * D;
        const float* f1L = w_ff1 + (size_t)layer * D * DFF;
        const float* f2L = w_ff2 + (size_t)layer * DFF * D;
        const int*   ixL = idx + (size_t)layer * L_ * S_;

        sgemm_kernel<<<gD, 256>>>(h, wqL, bq + layer * D, q, Mrows, D, D, 0);
        sgemm_kernel<<<gD, 256>>>(h, wkL, bk + layer * D, k, Mrows, D, D, 0);
        sgemm_kernel<<<gD, 256>>>(h, wvL, bv + layer * D, v, Mrows, D, D, 0);

        // M score over sampled keys
        qk_sample_kernel<<<(B_ * H_ * L_ * 32) / 256, 256>>>(q, k, ixL, Mv);
        // top-40 queries per (b,h)
        topk_kernel<<<B_ * H_, 256>>>(Mv, top);
        // v mean and broadcast fill
        vmean_kernel<<<B_ * H_, 256>>>(v, vm);
        ctxfill_kernel<<<(B_ * L_ * D) / 256, 256>>>(vm, ctx);
        // full attention for reduced queries, scattered into ctx
        attn_topq_kernel<<<B_ * H_ * U_, 256>>>(q, k, v, top, ctx);

        // output projection + residual LN
        sgemm_kernel<<<gD, 256>>>(ctx, woL, bo + layer * D, nx, Mrows, D, D, 0);
        add_ln_kernel<<<Mrows, 256>>>(h, nx, ln1_g + layer * D, ln1_b + layer * D);

        // FFN + residual LN
        sgemm_kernel<<<gFF, 256>>>(h, f1L, b_ff1 + layer * DFF, ff, Mrows, DFF, D, 1);
        sgemm_kernel<<<gD, 256>>>(ff, f2L, b_ff2 + layer * D, nx, Mrows, D, DFF, 0);
        add_ln_kernel<<<Mrows, 256>>>(h, nx, ln2_g + layer * D, ln2_b + layer * D);
    }

    head_kernel<<<B_, 64>>>(h, w_fc1, b_fc1, w_fc2, b_fc2, out);
}

// round 3
// speedup vs baseline: 1.7886x; 1.7886x over previous
#include <cuda_runtime.h>
#include <cuda_bf16.h>
#include <cstdint>
#include <math.h>

// Problem constants
#define B_   8
#define L_   2048
#define FIN  32
#define D    256
#define H_   8
#define DH   32
#define DFF  1024
#define S_   40
#define U_   40
#define NL   2

// ---------------- scratch (device globals; no allocation allowed) ----------------
__device__ float g_h  [B_*L_*D];
__device__ float g_q  [B_*L_*D];
__device__ float g_k  [B_*L_*D];
__device__ float g_v  [B_*L_*D];
__device__ float g_ctx[B_*L_*D];
__device__ float g_nx [B_*L_*D];
__device__ float g_ff [B_*L_*DFF];
__device__ float g_M  [B_*H_*L_];
__device__ int   g_top[B_*H_*U_];
__device__ float g_vm [B_*H_*DH];
__device__ float g_wt [FIN*D + 4*D*D + D*DFF + DFF*D];   // transposed weights

// =========================== bf16 split helpers ===================================
__device__ __forceinline__ void split4(float4 x, uint32_t& h01, uint32_t& h23,
                                       uint32_t& l01, uint32_t& l23)
{
    __nv_bfloat162 h0 = __float22bfloat162_rn(make_float2(x.x, x.y));
    __nv_bfloat162 h1 = __float22bfloat162_rn(make_float2(x.z, x.w));
    float2 hf0 = __bfloat1622float2(h0);
    float2 hf1 = __bfloat1622float2(h1);
    __nv_bfloat162 l0 = __float22bfloat162_rn(make_float2(x.x - hf0.x, x.y - hf0.y));
    __nv_bfloat162 l1 = __float22bfloat162_rn(make_float2(x.z - hf1.x, x.w - hf1.y));
    h01 = *(uint32_t*)&h0; h23 = *(uint32_t*)&h1;
    l01 = *(uint32_t*)&l0; l23 = *(uint32_t*)&l1;
}

#define MMA_BF16(c, a, b)                                                        \
    asm volatile("mma.sync.aligned.m16n8k16.row.col.f32.bf16.bf16.f32 "          \
        "{%0,%1,%2,%3}, {%4,%5,%6,%7}, {%8,%9}, {%0,%1,%2,%3};"                  \
        : "+f"((c)[0]), "+f"((c)[1]), "+f"((c)[2]), "+f"((c)[3])                  \
        : "r"((a)[0]), "r"((a)[1]), "r"((a)[2]), "r"((a)[3]),                     \
          "r"((b)[0]), "r"((b)[1]))

// =================== mma.sync bf16x3 GEMM: C = A @ Bt^T + bias ====================
// A: [M,K] fp32 row-major. Bt: [N,K] fp32 row-major (pre-transposed weight).
// Block tile 128x128, K chunk 32. 8 warps: 4(M)x2(N), warp tile 32x64.
#define RS 18   // smem row stride in uint32 (36 bf16 = 32 data + 4 pad)

__global__ __launch_bounds__(256, 1)
void mma_gemm_kernel(const float* __restrict__ A, const float* __restrict__ Bt,
                     const float* __restrict__ bias, float* __restrict__ C,
                     int M, int N, int K, int relu)
{
    __shared__ uint32_t Ah[128][RS], Al[128][RS], Bh[128][RS], Bl[128][RS];
    int tid  = threadIdx.x;
    int brow = blockIdx.y * 128;
    int bcol = blockIdx.x * 128;
    int w = tid >> 5, lane = tid & 31;
    int gid = lane >> 2, tig = lane & 3;
    int moff = (w >> 1) * 32, noff = (w & 1) * 64;
    float acc[2][8][4] = {};

    for (int k0c = 0; k0c < K; k0c += 32) {
        __syncthreads();
        #pragma unroll
        for (int i = 0; i < 4; i++) {
            int e   = tid + i * 256;          // 0..1023 float4 slots
            int row = e >> 3;
            int c4  = (e & 7) << 2;           // 0..28
            float4 xa = *(const float4*)(A  + (size_t)(brow + row) * K + k0c + c4);
            float4 xb = *(const float4*)(Bt + (size_t)(bcol + row) * K + k0c + c4);
            int cc = c4 >> 1;
            split4(xa, Ah[row][cc], Ah[row][cc + 1], Al[row][cc], Al[row][cc + 1]);
            split4(xb, Bh[row][cc], Bh[row][cc + 1], Bl[row][cc], Bl[row][cc + 1]);
        }
        __syncthreads();

        #pragma unroll
        for (int ks = 0; ks < 2; ks++) {
            int kb = ks * 8;     // uint32 col base for this k16 step
            uint32_t afh[2][4], afl[2][4], bfh[8][2], bfl[8][2];
            #pragma unroll
            for (int mt = 0; mt < 2; mt++) {
                int r = moff + mt * 16 + gid;
                afh[mt][0] = Ah[r][kb + tig];     afh[mt][1] = Ah[r + 8][kb + tig];
                afh[mt][2] = Ah[r][kb + tig + 4]; afh[mt][3] = Ah[r + 8][kb + tig + 4];
                afl[mt][0] = Al[r][kb + tig];     afl[mt][1] = Al[r + 8][kb + tig];
                afl[mt][2] = Al[r][kb + tig + 4]; afl[mt][3] = Al[r + 8][kb + tig + 4];
            }
            #pragma unroll
            for (int nt = 0; nt < 8; nt++) {
                int n = noff + nt * 8 + gid;
                bfh[nt][0] = Bh[n][kb + tig]; bfh[nt][1] = Bh[n][kb + tig + 4];
                bfl[nt][0] = Bl[n][kb + tig]; bfl[nt][1] = Bl[n][kb + tig + 4];
            }
            #pragma unroll
            for (int mt = 0; mt < 2; mt++)
                #pragma unroll
                for (int nt = 0; nt < 8; nt++) {
                    MMA_BF16(acc[mt][nt], afh[mt], bfh[nt]);
                    MMA_BF16(acc[mt][nt], afh[mt], bfl[nt]);
                    MMA_BF16(acc[mt][nt], afl[mt], bfh[nt]);
                }
        }
    }

    // epilogue: bias + optional relu, direct stores
    #pragma unroll
    for (int mt = 0; mt < 2; mt++) {
        int r0 = brow + moff + mt * 16 + gid;
        #pragma unroll
        for (int nt = 0; nt < 8; nt++) {
            int c = bcol + noff + nt * 8 + tig * 2;
            float b0 = bias[c], b1 = bias[c + 1];
            float2 o0 = make_float2(acc[mt][nt][0] + b0, acc[mt][nt][1] + b1);
            float2 o1 = make_float2(acc[mt][nt][2] + b0, acc[mt][nt][3] + b1);
            if (relu) {
                o0.x = fmaxf(o0.x, 0.f); o0.y = fmaxf(o0.y, 0.f);
                o1.x = fmaxf(o1.x, 0.f); o1.y = fmaxf(o1.y, 0.f);
            }
            *(float2*)(C + (size_t)r0 * N + c)       = o0;
            *(float2*)(C + (size_t)(r0 + 8) * N + c) = o1;
        }
    }
}

// ---------------- weight transpose: out[N,K] = in[K,N]^T --------------------------
__global__ void transpose_kernel(const float* __restrict__ in, float* __restrict__ out,
                                 int K, int N)
{
    __shared__ float t[32][33];
    int nb = blockIdx.x * 32, kb = blockIdx.y * 32;
    int tx = threadIdx.x, ty = threadIdx.y;
    #pragma unroll
    for (int i = ty; i < 32; i += 8)
        t[i][tx] = in[(size_t)(kb + i) * N + nb + tx];
    __syncthreads();
    #pragma unroll
    for (int i = ty; i < 32; i += 8)
        out[(size_t)(nb + i) * K + kb + tx] = t[tx][i];
}

// ---------------- sampled QK -> M score ------------------------------------------
__global__ void qk_sample_kernel(const float* __restrict__ q, const float* __restrict__ k,
                                 const int* __restrict__ idx, float* __restrict__ Mout)
{
    int gw   = (blockIdx.x * blockDim.x + threadIdx.x) >> 5;
    int lane = threadIdx.x & 31;
    if (gw >= B_ * H_ * L_) return;
    int l  = gw & (L_ - 1);
    int bh = gw >> 11;
    int b  = bh >> 3, h = bh & 7;

    float qd = q[((size_t)b * L_ + l) * D + h * DH + lane];
    const float* kbase = k + (size_t)b * L_ * D + h * DH;
    const int*   irow  = idx + l * S_;

    float mx = -1e30f, sm = 0.0f;
    for (int s = 0; s < S_; s++) {
        int   ki = __ldg(&irow[s]);
        float p  = qd * __ldg(&kbase[(size_t)ki * D + lane]);
        #pragma unroll
        for (int off = 16; off; off >>= 1) p += __shfl_xor_sync(0xffffffffu, p, off);
        mx = fmaxf(mx, p);
        sm += p;
    }
    if (lane == 0) Mout[gw] = mx - sm * (1.0f / (float)L_);
}

// ---------------- top-40 per (b,h) ------------------------------------------------
__global__ void topk_kernel(const float* __restrict__ Mv, int* __restrict__ top)
{
    int bh  = blockIdx.x;
    int tid = threadIdx.x;
    __shared__ float sv[L_];
    __shared__ float rv[256];
    __shared__ int   ri[256];
    for (int i = tid; i < L_; i += 256) sv[i] = Mv[(size_t)bh * L_ + i];
    __syncthreads();
    for (int r = 0; r < U_; r++) {
        float bv = -1e30f; int bi = 0x7fffffff;
        for (int i = tid; i < L_; i += 256) {
            float v = sv[i];
            if (v > bv || (v == bv && i < bi)) { bv = v; bi = i; }
        }
        rv[tid] = bv; ri[tid] = bi;
        __syncthreads();
        for (int s = 128; s; s >>= 1) {
            if (tid < s) {
                float ov = rv[tid + s]; int oi = ri[tid + s];
                if (ov > rv[tid] || (ov == rv[tid] && oi < ri[tid])) { rv[tid] = ov; ri[tid] = oi; }
            }
            __syncthreads();
        }
        if (tid == 0) { top[bh * U_ + r] = ri[0]; sv[ri[0]] = -1e30f; }
        __syncthreads();
    }
}

// ---------------- v mean over L per (b,h) -----------------------------------------
__global__ void vmean_kernel(const float* __restrict__ v, float* __restrict__ vm)
{
    int bh = blockIdx.x; int b = bh >> 3, h = bh & 7;
    int tid = threadIdx.x;
    int d = tid & 31, seg = tid >> 5;
    const float* vb = v + (size_t)b * L_ * D + h * DH + d;
    float acc = 0.0f;
    for (int l = seg; l < L_; l += 8) acc += vb[(size_t)l * D];
    __shared__ float sp[8][32];
    sp[seg][d] = acc;
    __syncthreads();
    if (tid < 32) {
        float s = 0.0f;
        #pragma unroll
        for (int i = 0; i < 8; i++) s += sp[i][tid];
        vm[bh * DH + tid] = s * (1.0f / (float)L_);
    }
}

__global__ void ctxfill_kernel(const float* __restrict__ vm, float* __restrict__ ctx)
{
    int i = blockIdx.x * blockDim.x + threadIdx.x;
    if (i >= B_ * L_ * D) return;
    int dfull = i & (D - 1);
    int b = i / (L_ * D);
    int h = dfull >> 5, d = dfull & 31;
    ctx[i] = vm[((b << 3) + h) * DH + d];
}

// ---------------- flash-style reduced attention: one block per (b,h) --------------
__global__ __launch_bounds__(256, 1)
void attn_topq_flash(const float* __restrict__ q, const float* __restrict__ k,
                     const float* __restrict__ v, const int* __restrict__ top,
                     float* __restrict__ ctx)
{
    __shared__ float Ks[128][33];
    __shared__ float Vs[128][33];
    __shared__ float qs[40][32];
    __shared__ float ps[8][128];
    __shared__ int   stop[40];

    int bh = blockIdx.x; int b = bh >> 3, h = bh & 7;
    int tid = threadIdx.x, w = tid >> 5, lane = tid & 31;

    if (tid < 40) stop[tid] = top[bh * U_ + tid];
    __syncthreads();
    for (int i = tid; i < 40 * 32; i += 256) {
        int u = i >> 5, d = i & 31;
        qs[u][d] = q[((size_t)b * L_ + stop[u]) * D + h * DH + d];
    }

    float m[5], l[5], acc[5];
    #pragma unroll
    for (int j = 0; j < 5; j++) { m[j] = -1e30f; l[j] = 0.f; acc[j] = 0.f; }
    const float scale = 0.1767766952966369f;  // 1/sqrt(32)
    const float* kb = k + (size_t)b * L_ * D + h * DH;
    const float* vb = v + (size_t)b * L_ * D + h * DH;
    __syncthreads();

    for (int t0 = 0; t0 < L_; t0 += 128) {
        for (int i = tid; i < 128 * 32; i += 256) {
            int r = i >> 5, d = i & 31;
            Ks[r][d] = kb[(size_t)(t0 + r) * D + d];
            Vs[r][d] = vb[(size_t)(t0 + r) * D + d];
        }
        __syncthreads();

        float sj[5][4];
        #pragma unroll
        for (int j = 0; j < 5; j++)
            #pragma unroll
            for (int i = 0; i < 4; i++) sj[j][i] = 0.f;
        #pragma unroll
        for (int d = 0; d < 32; d++) {
            float k0v = Ks[lane][d], k1v = Ks[lane + 32][d];
            float k2v = Ks[lane + 64][d], k3v = Ks[lane + 96][d];
            #pragma unroll
            for (int j = 0; j < 5; j++) {
                float qd = qs[w * 5 + j][d];
                sj[j][0] = fmaf(qd, k0v, sj[j][0]);
                sj[j][1] = fmaf(qd, k1v, sj[j][1]);
                sj[j][2] = fmaf(qd, k2v, sj[j][2]);
                sj[j][3] = fmaf(qd, k3v, sj[j][3]);
            }
        }
        #pragma unroll
        for (int j = 0; j < 5; j++) {
            float s0 = sj[j][0] * scale, s1 = sj[j][1] * scale;
            float s2 = sj[j][2] * scale, s3 = sj[j][3] * scale;
            float tm = fmaxf(fmaxf(s0, s1), fmaxf(s2, s3));
            #pragma unroll
            for (int o = 16; o; o >>= 1) tm = fmaxf(tm, __shfl_xor_sync(0xffffffffu, tm, o));
            float mn   = fmaxf(m[j], tm);
            float corr = __expf(m[j] - mn);
            float p0 = __expf(s0 - mn), p1 = __expf(s1 - mn);
            float p2 = __expf(s2 - mn), p3 = __expf(s3 - mn);
            float psum = p0 + p1 + p2 + p3;
            #pragma unroll
            for (int o = 16; o; o >>= 1) psum += __shfl_xor_sync(0xffffffffu, psum, o);
            l[j] = l[j] * corr + psum;
            m[j] = mn;
            ps[w][lane] = p0; ps[w][lane + 32] = p1; ps[w][lane + 64] = p2; ps[w][lane + 96] = p3;
            __syncwarp();
            float aa = acc[j] * corr;
            const float4* pv4 = (const float4*)ps[w];
            #pragma unroll 8
            for (int kk4 = 0; kk4 < 32; kk4++) {
                float4 p4 = pv4[kk4];
                int kk = kk4 * 4;
                aa = fmaf(p4.x, Vs[kk][lane],     aa);
                aa = fmaf(p4.y, Vs[kk + 1][lane], aa);
                aa = fmaf(p4.z, Vs[kk + 2][lane], aa);
                aa = fmaf(p4.w, Vs[kk + 3][lane], aa);
            }
            acc[j] = aa;
            __syncwarp();
        }
        __syncthreads();
    }
    #pragma unroll
    for (int j = 0; j < 5; j++) {
        int u = w * 5 + j;
        ctx[((size_t)b * L_ + stop[u]) * D + h * DH + lane] = acc[j] / l[j];
    }
}

// ---------------- residual add + LayerNorm ----------------------------------------
__global__ void add_ln_kernel(float* __restrict__ h, const float* __restrict__ r,
                              const float* __restrict__ g, const float* __restrict__ bb)
{
    int row = blockIdx.x;
    int tid = threadIdx.x;
    float val = h[(size_t)row * D + tid] + r[(size_t)row * D + tid];
    __shared__ float s_red[256];
    s_red[tid] = val; __syncthreads();
    for (int s = 128; s; s >>= 1) { if (tid < s) s_red[tid] += s_red[tid + s]; __syncthreads(); }
    float mu = s_red[0] * (1.0f / (float)D);
    __syncthreads();
    float dv = val - mu;
    s_red[tid] = dv * dv; __syncthreads();
    for (int s = 128; s; s >>= 1) { if (tid < s) s_red[tid] += s_red[tid + s]; __syncthreads(); }
    float var = s_red[0] * (1.0f / (float)D);
    h[(size_t)row * D + tid] = dv * rsqrtf(var + 1e-5f) * g[tid] + bb[tid];
}

// ---------------- final MLP head ---------------------------------------------------
__global__ void head_kernel(const float* __restrict__ h, const float* __restrict__ w1,
                            const float* __restrict__ b1, const float* __restrict__ w2,
                            const float* __restrict__ b2, float* __restrict__ out)
{
    int b = blockIdx.x;
    int j = threadIdx.x;
    const float* last = h + ((size_t)b * L_ + (L_ - 1)) * D;
    float acc = b1[j];
    for (int d = 0; d < D; d++) acc = fmaf(last[d], w1[d * 64 + j], acc);
    acc = fmaxf(acc, 0.0f) * w2[j];
    __shared__ float s[64];
    s[j] = acc; __syncthreads();
    for (int st = 32; st; st >>= 1) { if (j < st) s[j] += s[j + st]; __syncthreads(); }
    if (j == 0) out[b] = s[0] + b2[0];
}

// ===================================================================================
extern "C" void kernel_launch(void* const* d_in, const int* in_sizes, int n_in,
                              void* d_out, int out_size)
{
    const float* x     = (const float*)d_in[0];
    const int*   idx   = (const int*)  d_in[1];
    const float* w_in  = (const float*)d_in[2];
    const float* b_in  = (const float*)d_in[3];
    const float* wq    = (const float*)d_in[4];
    const float* bq    = (const float*)d_in[5];
    const float* wk    = (const float*)d_in[6];
    const float* bk    = (const float*)d_in[7];
    const float* wv    = (const float*)d_in[8];
    const float* bv    = (const float*)d_in[9];
    const float* wo    = (const float*)d_in[10];
    const float* bo    = (const float*)d_in[11];
    const float* w_ff1 = (const float*)d_in[12];
    const float* b_ff1 = (const float*)d_in[13];
    const float* w_ff2 = (const float*)d_in[14];
    const float* b_ff2 = (const float*)d_in[15];
    const float* ln1_g = (const float*)d_in[16];
    const float* ln1_b = (const float*)d_in[17];
    const float* ln2_g = (const float*)d_in[18];
    const float* ln2_b = (const float*)d_in[19];
    const float* w_fc1 = (const float*)d_in[20];
    const float* b_fc1 = (const float*)d_in[21];
    const float* w_fc2 = (const float*)d_in[22];
    const float* b_fc2 = (const float*)d_in[23];
    float* out = (float*)d_out;

    float *h, *q, *k, *v, *ctx, *nx, *ff, *Mv, *vm, *wt; int* top;
    cudaGetSymbolAddress((void**)&h,   g_h);
    cudaGetSymbolAddress((void**)&q,   g_q);
    cudaGetSymbolAddress((void**)&k,   g_k);
    cudaGetSymbolAddress((void**)&v,   g_v);
    cudaGetSymbolAddress((void**)&ctx, g_ctx);
    cudaGetSymbolAddress((void**)&nx,  g_nx);
    cudaGetSymbolAddress((void**)&ff,  g_ff);
    cudaGetSymbolAddress((void**)&Mv,  g_M);
    cudaGetSymbolAddress((void**)&top, g_top);
    cudaGetSymbolAddress((void**)&vm,  g_vm);
    cudaGetSymbolAddress((void**)&wt,  g_wt);

    const int Mrows = B_ * L_;                     // 16384
    dim3 gD (D / 128,   Mrows / 128);              // (2,128)
    dim3 gFF(DFF / 128, Mrows / 128);              // (8,128)
    dim3 tb(32, 8);

    // wt layout (floats)
    float* wtin = wt;                              // [D, FIN]
    float* wtq  = wt + FIN * D;
    float* wtk  = wtq + D * D;
    float* wtv  = wtk + D * D;
    float* wto  = wtv + D * D;
    float* wt1  = wto + D * D;                     // [DFF, D]
    float* wt2  = wt1 + D * DFF;                   // [D, DFF]

    // input projection: transpose w_in [FIN,D] -> [D,FIN], then mma GEMM (K=32)
    transpose_kernel<<<dim3(D / 32, FIN / 32), tb>>>(w_in, wtin, FIN, D);
    mma_gemm_kernel<<<gD, 256>>>(x, wtin, b_in, h, Mrows, D, FIN, 0);

    for (int layer = 0; layer < NL; layer++) {
        const float* wqL = wq + (size_t)layer * D * D;
        const float* wkL = wk + (size_t)layer * D * D;
        const float* wvL = wv + (size_t)layer * D * D;
        const float* woL = wo + (size_t)layer * D * D;
        const float* f1L = w_ff1 + (size_t)layer * D * DFF;
        const float* f2L = w_ff2 + (size_t)layer * DFF * D;
        const int*   ixL = idx + (size_t)layer * L_ * S_;

        transpose_kernel<<<dim3(D / 32,   D / 32),   tb>>>(wqL, wtq, D, D);
        transpose_kernel<<<dim3(D / 32,   D / 32),   tb>>>(wkL, wtk, D, D);
        transpose_kernel<<<dim3(D / 32,   D / 32),   tb>>>(wvL, wtv, D, D);
        transpose_kernel<<<dim3(D / 32,   D / 32),   tb>>>(woL, wto, D, D);
        transpose_kernel<<<dim3(DFF / 32, D / 32),   tb>>>(f1L, wt1, D, DFF);
        transpose_kernel<<<dim3(D / 32,   DFF / 32), tb>>>(f2L, wt2, DFF, D);

        mma_gemm_kernel<<<gD, 256>>>(h, wtq, bq + layer * D, q, Mrows, D, D, 0);
        mma_gemm_kernel<<<gD, 256>>>(h, wtk, bk + layer * D, k, Mrows, D, D, 0);
        mma_gemm_kernel<<<gD, 256>>>(h, wtv, bv + layer * D, v, Mrows, D, D, 0);

        qk_sample_kernel<<<(B_ * H_ * L_ * 32) / 256, 256>>>(q, k, ixL, Mv);
        topk_kernel<<<B_ * H_, 256>>>(Mv, top);
        vmean_kernel<<<B_ * H_, 256>>>(v, vm);
        ctxfill_kernel<<<(B_ * L_ * D) / 256, 256>>>(vm, ctx);
        attn_topq_flash<<<B_ * H_, 256>>>(q, k, v, top, ctx);

        mma_gemm_kernel<<<gD, 256>>>(ctx, wto, bo + layer * D, nx, Mrows, D, D, 0);
        add_ln_kernel<<<Mrows, 256>>>(h, nx, ln1_g + layer * D, ln1_b + layer * D);

        mma_gemm_kernel<<<gFF, 256>>>(h, wt1, b_ff1 + layer * DFF, ff, Mrows, DFF, D, 1);
        mma_gemm_kernel<<<gD, 256>>>(ff, wt2, b_ff2 + layer * D, nx, Mrows, D, DFF, 0);
        add_ln_kernel<<<Mrows, 256>>>(h, nx, ln2_g + layer * D, ln2_b + layer * D);
    }

    head_kernel<<<B_, 64>>>(h, w_fc1, b_fc1, w_fc2, b_fc2, out);
}

// round 4
// speedup vs baseline: 1.9532x; 1.0920x over previous
#include <cuda_runtime.h>
#include <cuda_bf16.h>
#include <cstdint>
#include <math.h>

// Problem constants
#define B_   8
#define L_   2048
#define FIN  32
#define D    256
#define H_   8
#define DH   32
#define DFF  1024
#define S_   40
#define U_   40
#define NL   2

// ---------------- scratch (device globals; no allocation allowed) ----------------
__device__ float g_h  [B_*L_*D];
__device__ float g_q  [B_*L_*D];
__device__ float g_k  [B_*L_*D];
__device__ float g_v  [B_*L_*D];
__device__ float g_nx [B_*L_*D];
__device__ float g_M  [B_*H_*L_];
__device__ int   g_top[B_*H_*U_];
__device__ float g_vm [B_*H_*DH];

// bf16 hi/lo planes
__device__ __nv_bfloat16 g_x_hi [B_*L_*FIN], g_x_lo [B_*L_*FIN];
__device__ __nv_bfloat16 g_h_hi [B_*L_*D],   g_h_lo [B_*L_*D];
__device__ __nv_bfloat16 g_ctx_hi[B_*L_*D],  g_ctx_lo[B_*L_*D];
__device__ __nv_bfloat16 g_ff_hi[B_*L_*DFF], g_ff_lo[B_*L_*DFF];
#define WT_TOTAL (FIN*D + 4*D*D + D*DFF + DFF*D)
__device__ __nv_bfloat16 g_wt_hi[WT_TOTAL], g_wt_lo[WT_TOTAL];

// =========================== helpers ===============================================
__device__ __forceinline__ uint32_t smem_u32(const void* p) {
    uint32_t a;
    asm("{ .reg .u64 t; cvta.to.shared.u64 t, %1; cvt.u32.u64 %0, t; }" : "=r"(a) : "l"(p));
    return a;
}
__device__ __forceinline__ void split2(float x, float y, uint32_t& hi, uint32_t& lo) {
    __nv_bfloat162 h = __float22bfloat162_rn(make_float2(x, y));
    float2 hf = __bfloat1622float2(h);
    __nv_bfloat162 l = __float22bfloat162_rn(make_float2(x - hf.x, y - hf.y));
    hi = *(uint32_t*)&h; lo = *(uint32_t*)&l;
}
__device__ __forceinline__ void split_scalar(float v, __nv_bfloat16* hp, __nv_bfloat16* lp) {
    __nv_bfloat16 hb = __float2bfloat16(v);
    *hp = hb;
    *lp = __float2bfloat16(v - __bfloat162float(hb));
}

#define MMA_BF16(c, a, b)                                                        \
    asm volatile("mma.sync.aligned.m16n8k16.row.col.f32.bf16.bf16.f32 "          \
        "{%0,%1,%2,%3}, {%4,%5,%6,%7}, {%8,%9}, {%0,%1,%2,%3};"                  \
        : "+f"((c)[0]), "+f"((c)[1]), "+f"((c)[2]), "+f"((c)[3])                  \
        : "r"((a)[0]), "r"((a)[1]), "r"((a)[2]), "r"((a)[3]),                     \
          "r"((b)[0]), "r"((b)[1]))

// =================== pipelined bf16x3 GEMM: C = A @ Bt^T + bias ====================
// A planes: [M,K] bf16 hi/lo. Bt planes: [N,K] bf16 hi/lo.
// Block tile 128x128, K chunk 32, double-buffered cp.async.
// mode bit0: write fp32 C; bit1: write split planes Chi/Clo (post-relu).
#define RSU   20                  // uint32 per smem row (16 data + 4 pad; 80B, 16B-aligned)
#define PLANE (128*RSU)
#define BUFU  (4*PLANE)
#define GEMM_SMEM_V2 (2*BUFU*4)   // 81920 bytes

__global__ __launch_bounds__(256, 1)
void mma_gemm_bf16(const __nv_bfloat16* __restrict__ Ahi, const __nv_bfloat16* __restrict__ Alo,
                   const __nv_bfloat16* __restrict__ Bhi, const __nv_bfloat16* __restrict__ Blo,
                   const float* __restrict__ bias, float* __restrict__ C,
                   __nv_bfloat16* __restrict__ Chi, __nv_bfloat16* __restrict__ Clo,
                   int M, int N, int K, int relu, int mode)
{
    extern __shared__ uint32_t sm[];
    int tid  = threadIdx.x;
    int brow = blockIdx.y * 128;
    int bcol = blockIdx.x * 128;
    int w = tid >> 5, lane = tid & 31;
    int gid = lane >> 2, tig = lane & 3;
    int moff = (w >> 1) * 32, noff = (w & 1) * 64;
    uint32_t smb = smem_u32(sm);

    auto load_chunk = [&](int c, int buf) {
        int k0 = c * 32;
        uint32_t sb = smb + (uint32_t)buf * (BUFU * 4);
        #pragma unroll
        for (int i = 0; i < 8; i++) {
            int e  = tid + i * 256;
            int pl = e >> 9;               // 0..3
            int r  = (e >> 2) & 127;
            int s  = e & 3;
            const __nv_bfloat16* src;
            if      (pl == 0) src = Ahi + (size_t)(brow + r) * K + k0 + s * 8;
            else if (pl == 1) src = Alo + (size_t)(brow + r) * K + k0 + s * 8;
            else if (pl == 2) src = Bhi + (size_t)(bcol + r) * K + k0 + s * 8;
            else              src = Blo + (size_t)(bcol + r) * K + k0 + s * 8;
            uint32_t dst = sb + (uint32_t)(pl * PLANE + r * RSU + s * 4) * 4;
            asm volatile("cp.async.cg.shared.global [%0], [%1], 16;" :: "r"(dst), "l"(src));
        }
        asm volatile("cp.async.commit_group;" ::: "memory");
    };

    float acc[2][8][4] = {};
    const int NC = K >> 5;
    load_chunk(0, 0);

    for (int c = 0; c < NC; c++) {
        if (c + 1 < NC) {
            load_chunk(c + 1, (c + 1) & 1);
            asm volatile("cp.async.wait_group 1;" ::: "memory");
        } else {
            asm volatile("cp.async.wait_group 0;" ::: "memory");
        }
        __syncthreads();
        const uint32_t* Ah = sm + (c & 1) * BUFU;
        const uint32_t* Al = Ah + PLANE;
        const uint32_t* Bh = Al + PLANE;
        const uint32_t* Bl = Bh + PLANE;

        #pragma unroll
        for (int ks = 0; ks < 2; ks++) {
            int kb = ks * 8;
            uint32_t afh[2][4], afl[2][4], bfh[8][2], bfl[8][2];
            #pragma unroll
            for (int mt = 0; mt < 2; mt++) {
                int r = moff + mt * 16 + gid;
                afh[mt][0] = Ah[r * RSU + kb + tig];
                afh[mt][1] = Ah[(r + 8) * RSU + kb + tig];
                afh[mt][2] = Ah[r * RSU + kb + tig + 4];
                afh[mt][3] = Ah[(r + 8) * RSU + kb + tig + 4];
                afl[mt][0] = Al[r * RSU + kb + tig];
                afl[mt][1] = Al[(r + 8) * RSU + kb + tig];
                afl[mt][2] = Al[r * RSU + kb + tig + 4];
                afl[mt][3] = Al[(r + 8) * RSU + kb + tig + 4];
            }
            #pragma unroll
            for (int nt = 0; nt < 8; nt++) {
                int n = noff + nt * 8 + gid;
                bfh[nt][0] = Bh[n * RSU + kb + tig]; bfh[nt][1] = Bh[n * RSU + kb + tig + 4];
                bfl[nt][0] = Bl[n * RSU + kb + tig]; bfl[nt][1] = Bl[n * RSU + kb + tig + 4];
            }
            #pragma unroll
            for (int mt = 0; mt < 2; mt++)
                #pragma unroll
                for (int nt = 0; nt < 8; nt++) {
                    MMA_BF16(acc[mt][nt], afh[mt], bfh[nt]);
                    MMA_BF16(acc[mt][nt], afh[mt], bfl[nt]);
                    MMA_BF16(acc[mt][nt], afl[mt], bfh[nt]);
                }
        }
        __syncthreads();
    }

    // epilogue
    #pragma unroll
    for (int mt = 0; mt < 2; mt++) {
        int r0 = brow + moff + mt * 16 + gid;
        #pragma unroll
        for (int nt = 0; nt < 8; nt++) {
            int c = bcol + noff + nt * 8 + tig * 2;
            float b0 = bias[c], b1 = bias[c + 1];
            float2 o0 = make_float2(acc[mt][nt][0] + b0, acc[mt][nt][1] + b1);
            float2 o1 = make_float2(acc[mt][nt][2] + b0, acc[mt][nt][3] + b1);
            if (relu) {
                o0.x = fmaxf(o0.x, 0.f); o0.y = fmaxf(o0.y, 0.f);
                o1.x = fmaxf(o1.x, 0.f); o1.y = fmaxf(o1.y, 0.f);
            }
            size_t i0 = (size_t)r0 * N + c;
            size_t i1 = (size_t)(r0 + 8) * N + c;
            if (mode & 1) {
                *(float2*)(C + i0) = o0;
                *(float2*)(C + i1) = o1;
            }
            if (mode & 2) {
                uint32_t h0, l0, h1, l1;
                split2(o0.x, o0.y, h0, l0);
                split2(o1.x, o1.y, h1, l1);
                *(uint32_t*)(Chi + i0) = h0; *(uint32_t*)(Clo + i0) = l0;
                *(uint32_t*)(Chi + i1) = h1; *(uint32_t*)(Clo + i1) = l1;
            }
        }
    }
}

// ---------------- fused transpose + split: in[K,N] fp32 -> hi/lo [N,K] bf16 --------
__global__ void transpose_split_kernel(const float* __restrict__ in,
                                       __nv_bfloat16* __restrict__ hi,
                                       __nv_bfloat16* __restrict__ lo,
                                       int K, int N)
{
    __shared__ float t[32][33];
    int nb = blockIdx.x * 32, kb = blockIdx.y * 32;
    int tx = threadIdx.x, ty = threadIdx.y;
    #pragma unroll
    for (int i = ty; i < 32; i += 8)
        t[i][tx] = in[(size_t)(kb + i) * N + nb + tx];
    __syncthreads();
    #pragma unroll
    for (int i = ty; i < 32; i += 8) {
        float v = t[tx][i];
        size_t o = (size_t)(nb + i) * K + kb + tx;
        split_scalar(v, hi + o, lo + o);
    }
}

// ---------------- plain split: fp32 -> hi/lo bf16 ---------------------------------
__global__ void split_kernel(const float* __restrict__ in,
                             __nv_bfloat16* __restrict__ hi,
                             __nv_bfloat16* __restrict__ lo, int n)
{
    int i = (blockIdx.x * blockDim.x + threadIdx.x) * 2;
    if (i >= n) return;
    float2 v = *(const float2*)(in + i);
    uint32_t h, l;
    split2(v.x, v.y, h, l);
    *(uint32_t*)(hi + i) = h;
    *(uint32_t*)(lo + i) = l;
}

// ---------------- sampled QK -> M score ------------------------------------------
__global__ void qk_sample_kernel(const float* __restrict__ q, const float* __restrict__ k,
                                 const int* __restrict__ idx, float* __restrict__ Mout)
{
    int gw   = (blockIdx.x * blockDim.x + threadIdx.x) >> 5;
    int lane = threadIdx.x & 31;
    if (gw >= B_ * H_ * L_) return;
    int l  = gw & (L_ - 1);
    int bh = gw >> 11;
    int b  = bh >> 3, h = bh & 7;

    float qd = q[((size_t)b * L_ + l) * D + h * DH + lane];
    const float* kbase = k + (size_t)b * L_ * D + h * DH;
    const int*   irow  = idx + l * S_;

    float mx = -1e30f, sm = 0.0f;
    for (int s = 0; s < S_; s++) {
        int   ki = __ldg(&irow[s]);
        float p  = qd * __ldg(&kbase[(size_t)ki * D + lane]);
        #pragma unroll
        for (int off = 16; off; off >>= 1) p += __shfl_xor_sync(0xffffffffu, p, off);
        mx = fmaxf(mx, p);
        sm += p;
    }
    if (lane == 0) Mout[gw] = mx - sm * (1.0f / (float)L_);
}

// ---------------- top-40 per (b,h) ------------------------------------------------
__global__ void topk_kernel(const float* __restrict__ Mv, int* __restrict__ top)
{
    int bh  = blockIdx.x;
    int tid = threadIdx.x;
    __shared__ float sv[L_];
    __shared__ float rv[256];
    __shared__ int   ri[256];
    for (int i = tid; i < L_; i += 256) sv[i] = Mv[(size_t)bh * L_ + i];
    __syncthreads();
    for (int r = 0; r < U_; r++) {
        float bv = -1e30f; int bi = 0x7fffffff;
        for (int i = tid; i < L_; i += 256) {
            float v = sv[i];
            if (v > bv || (v == bv && i < bi)) { bv = v; bi = i; }
        }
        rv[tid] = bv; ri[tid] = bi;
        __syncthreads();
        for (int s = 128; s; s >>= 1) {
            if (tid < s) {
                float ov = rv[tid + s]; int oi = ri[tid + s];
                if (ov > rv[tid] || (ov == rv[tid] && oi < ri[tid])) { rv[tid] = ov; ri[tid] = oi; }
            }
            __syncthreads();
        }
        if (tid == 0) { top[bh * U_ + r] = ri[0]; sv[ri[0]] = -1e30f; }
        __syncthreads();
    }
}

// ---------------- v mean over L per (b,h) -----------------------------------------
__global__ void vmean_kernel(const float* __restrict__ v, float* __restrict__ vm)
{
    int bh = blockIdx.x; int b = bh >> 3, h = bh & 7;
    int tid = threadIdx.x;
    int d = tid & 31, seg = tid >> 5;
    const float* vb = v + (size_t)b * L_ * D + h * DH + d;
    float acc = 0.0f;
    for (int l = seg; l < L_; l += 8) acc += vb[(size_t)l * D];
    __shared__ float sp[8][32];
    sp[seg][d] = acc;
    __syncthreads();
    if (tid < 32) {
        float s = 0.0f;
        #pragma unroll
        for (int i = 0; i < 8; i++) s += sp[i][tid];
        vm[bh * DH + tid] = s * (1.0f / (float)L_);
    }
}

// ---------------- fill ctx planes with broadcast v-mean ---------------------------
__global__ void ctxfill_kernel(const float* __restrict__ vm,
                               __nv_bfloat16* __restrict__ chi,
                               __nv_bfloat16* __restrict__ clo)
{
    int i = blockIdx.x * blockDim.x + threadIdx.x;
    if (i >= B_ * L_ * D) return;
    int dfull = i & (D - 1);
    int b = i / (L_ * D);
    int h = dfull >> 5, d = dfull & 31;
    float v = vm[((b << 3) + h) * DH + d];
    split_scalar(v, chi + i, clo + i);
}

// ---------------- flash-style reduced attention: one block per (b,h) --------------
__global__ __launch_bounds__(256, 1)
void attn_topq_flash(const float* __restrict__ q, const float* __restrict__ k,
                     const float* __restrict__ v, const int* __restrict__ top,
                     __nv_bfloat16* __restrict__ chi, __nv_bfloat16* __restrict__ clo)
{
    __shared__ float Ks[128][33];
    __shared__ float Vs[128][33];
    __shared__ float qs[40][32];
    __shared__ float ps[8][128];
    __shared__ int   stop[40];

    int bh = blockIdx.x; int b = bh >> 3, h = bh & 7;
    int tid = threadIdx.x, w = tid >> 5, lane = tid & 31;

    if (tid < 40) stop[tid] = top[bh * U_ + tid];
    __syncthreads();
    for (int i = tid; i < 40 * 32; i += 256) {
        int u = i >> 5, d = i & 31;
        qs[u][d] = q[((size_t)b * L_ + stop[u]) * D + h * DH + d];
    }

    float m[5], l[5], acc[5];
    #pragma unroll
    for (int j = 0; j < 5; j++) { m[j] = -1e30f; l[j] = 0.f; acc[j] = 0.f; }
    const float scale = 0.1767766952966369f;
    const float* kb = k + (size_t)b * L_ * D + h * DH;
    const float* vb = v + (size_t)b * L_ * D + h * DH;
    __syncthreads();

    for (int t0 = 0; t0 < L_; t0 += 128) {
        for (int i = tid; i < 128 * 32; i += 256) {
            int r = i >> 5, d = i & 31;
            Ks[r][d] = kb[(size_t)(t0 + r) * D + d];
            Vs[r][d] = vb[(size_t)(t0 + r) * D + d];
        }
        __syncthreads();

        float sj[5][4];
        #pragma unroll
        for (int j = 0; j < 5; j++)
            #pragma unroll
            for (int i = 0; i < 4; i++) sj[j][i] = 0.f;
        #pragma unroll
        for (int d = 0; d < 32; d++) {
            float k0v = Ks[lane][d], k1v = Ks[lane + 32][d];
            float k2v = Ks[lane + 64][d], k3v = Ks[lane + 96][d];
            #pragma unroll
            for (int j = 0; j < 5; j++) {
                float qd = qs[w * 5 + j][d];
                sj[j][0] = fmaf(qd, k0v, sj[j][0]);
                sj[j][1] = fmaf(qd, k1v, sj[j][1]);
                sj[j][2] = fmaf(qd, k2v, sj[j][2]);
                sj[j][3] = fmaf(qd, k3v, sj[j][3]);
            }
        }
        #pragma unroll
        for (int j = 0; j < 5; j++) {
            float s0 = sj[j][0] * scale, s1 = sj[j][1] * scale;
            float s2 = sj[j][2] * scale, s3 = sj[j][3] * scale;
            float tm = fmaxf(fmaxf(s0, s1), fmaxf(s2, s3));
            #pragma unroll
            for (int o = 16; o; o >>= 1) tm = fmaxf(tm, __shfl_xor_sync(0xffffffffu, tm, o));
            float mn   = fmaxf(m[j], tm);
            float corr = __expf(m[j] - mn);
            float p0 = __expf(s0 - mn), p1 = __expf(s1 - mn);
            float p2 = __expf(s2 - mn), p3 = __expf(s3 - mn);
            float psum = p0 + p1 + p2 + p3;
            #pragma unroll
            for (int o = 16; o; o >>= 1) psum += __shfl_xor_sync(0xffffffffu, psum, o);
            l[j] = l[j] * corr + psum;
            m[j] = mn;
            ps[w][lane] = p0; ps[w][lane + 32] = p1; ps[w][lane + 64] = p2; ps[w][lane + 96] = p3;
            __syncwarp();
            float aa = acc[j] * corr;
            const float4* pv4 = (const float4*)ps[w];
            #pragma unroll 8
            for (int kk4 = 0; kk4 < 32; kk4++) {
                float4 p4 = pv4[kk4];
                int kk = kk4 * 4;
                aa = fmaf(p4.x, Vs[kk][lane],     aa);
                aa = fmaf(p4.y, Vs[kk + 1][lane], aa);
                aa = fmaf(p4.z, Vs[kk + 2][lane], aa);
                aa = fmaf(p4.w, Vs[kk + 3][lane], aa);
            }
            acc[j] = aa;
            __syncwarp();
        }
        __syncthreads();
    }
    #pragma unroll
    for (int j = 0; j < 5; j++) {
        int u = w * 5 + j;
        float o = acc[j] / l[j];
        size_t off = ((size_t)b * L_ + stop[u]) * D + h * DH + lane;
        split_scalar(o, chi + off, clo + off);
    }
}

// ---------------- residual add + LayerNorm + split --------------------------------
__global__ void add_ln_kernel(float* __restrict__ h, const float* __restrict__ r,
                              const float* __restrict__ g, const float* __restrict__ bb,
                              __nv_bfloat16* __restrict__ hhi, __nv_bfloat16* __restrict__ hlo)
{
    int row = blockIdx.x;
    int tid = threadIdx.x;
    float val = h[(size_t)row * D + tid] + r[(size_t)row * D + tid];
    __shared__ float s_red[256];
    s_red[tid] = val; __syncthreads();
    for (int s = 128; s; s >>= 1) { if (tid < s) s_red[tid] += s_red[tid + s]; __syncthreads(); }
    float mu = s_red[0] * (1.0f / (float)D);
    __syncthreads();
    float dv = val - mu;
    s_red[tid] = dv * dv; __syncthreads();
    for (int s = 128; s; s >>= 1) { if (tid < s) s_red[tid] += s_red[tid + s]; __syncthreads(); }
    float var = s_red[0] * (1.0f / (float)D);
    float o = dv * rsqrtf(var + 1e-5f) * g[tid] + bb[tid];
    size_t off = (size_t)row * D + tid;
    h[off] = o;
    split_scalar(o, hhi + off, hlo + off);
}

// ---------------- final MLP head ---------------------------------------------------
__global__ void head_kernel(const float* __restrict__ h, const float* __restrict__ w1,
                            const float* __restrict__ b1, const float* __restrict__ w2,
                            const float* __restrict__ b2, float* __restrict__ out)
{
    int b = blockIdx.x;
    int j = threadIdx.x;
    const float* last = h + ((size_t)b * L_ + (L_ - 1)) * D;
    float acc = b1[j];
    for (int d = 0; d < D; d++) acc = fmaf(last[d], w1[d * 64 + j], acc);
    acc = fmaxf(acc, 0.0f) * w2[j];
    __shared__ float s[64];
    s[j] = acc; __syncthreads();
    for (int st = 32; st; st >>= 1) { if (j < st) s[j] += s[j + st]; __syncthreads(); }
    if (j == 0) out[b] = s[0] + b2[0];
}

// ===================================================================================
extern "C" void kernel_launch(void* const* d_in, const int* in_sizes, int n_in,
                              void* d_out, int out_size)
{
    const float* x     = (const float*)d_in[0];
    const int*   idx   = (const int*)  d_in[1];
    const float* w_in  = (const float*)d_in[2];
    const float* b_in  = (const float*)d_in[3];
    const float* wq    = (const float*)d_in[4];
    const float* bq    = (const float*)d_in[5];
    const float* wk    = (const float*)d_in[6];
    const float* bk    = (const float*)d_in[7];
    const float* wv    = (const float*)d_in[8];
    const float* bv    = (const float*)d_in[9];
    const float* wo    = (const float*)d_in[10];
    const float* bo    = (const float*)d_in[11];
    const float* w_ff1 = (const float*)d_in[12];
    const float* b_ff1 = (const float*)d_in[13];
    const float* w_ff2 = (const float*)d_in[14];
    const float* b_ff2 = (const float*)d_in[15];
    const float* ln1_g = (const float*)d_in[16];
    const float* ln1_b = (const float*)d_in[17];
    const float* ln2_g = (const float*)d_in[18];
    const float* ln2_b = (const float*)d_in[19];
    const float* w_fc1 = (const float*)d_in[20];
    const float* b_fc1 = (const float*)d_in[21];
    const float* w_fc2 = (const float*)d_in[22];
    const float* b_fc2 = (const float*)d_in[23];
    float* out = (float*)d_out;

    float *h, *q, *k, *v, *nx, *Mv, *vm; int* top;
    __nv_bfloat16 *xhi, *xlo, *hhi, *hlo, *chi, *clo, *fhi, *flo, *whi, *wlo;
    cudaGetSymbolAddress((void**)&h,   g_h);
    cudaGetSymbolAddress((void**)&q,   g_q);
    cudaGetSymbolAddress((void**)&k,   g_k);
    cudaGetSymbolAddress((void**)&v,   g_v);
    cudaGetSymbolAddress((void**)&nx,  g_nx);
    cudaGetSymbolAddress((void**)&Mv,  g_M);
    cudaGetSymbolAddress((void**)&top, g_top);
    cudaGetSymbolAddress((void**)&vm,  g_vm);
    cudaGetSymbolAddress((void**)&xhi, g_x_hi);  cudaGetSymbolAddress((void**)&xlo, g_x_lo);
    cudaGetSymbolAddress((void**)&hhi, g_h_hi);  cudaGetSymbolAddress((void**)&hlo, g_h_lo);
    cudaGetSymbolAddress((void**)&chi, g_ctx_hi); cudaGetSymbolAddress((void**)&clo, g_ctx_lo);
    cudaGetSymbolAddress((void**)&fhi, g_ff_hi); cudaGetSymbolAddress((void**)&flo, g_ff_lo);
    cudaGetSymbolAddress((void**)&whi, g_wt_hi); cudaGetSymbolAddress((void**)&wlo, g_wt_lo);

    static int attr_set = 0;
    cudaFuncSetAttribute(mma_gemm_bf16, cudaFuncAttributeMaxDynamicSharedMemorySize, GEMM_SMEM_V2);
    (void)attr_set;

    const int Mrows = B_ * L_;                     // 16384
    dim3 gD (D / 128,   Mrows / 128);
    dim3 gFF(DFF / 128, Mrows / 128);
    dim3 tb(32, 8);

    // weight plane offsets (bf16 elems)
    const size_t o_in = 0;
    const size_t o_q  = o_in + (size_t)FIN * D;
    const size_t o_k  = o_q  + (size_t)D * D;
    const size_t o_v  = o_k  + (size_t)D * D;
    const size_t o_o  = o_v  + (size_t)D * D;
    const size_t o_f1 = o_o  + (size_t)D * D;       // [DFF, D]
    const size_t o_f2 = o_f1 + (size_t)D * DFF;     // [D, DFF]

    // split x, transpose+split input weight, input projection (K=32)
    split_kernel<<<(B_ * L_ * FIN) / 512, 256>>>(x, xhi, xlo, B_ * L_ * FIN);
    transpose_split_kernel<<<dim3(D / 32, FIN / 32), tb>>>(w_in, whi + o_in, wlo + o_in, FIN, D);
    mma_gemm_bf16<<<gD, 256, GEMM_SMEM_V2>>>(xhi, xlo, whi + o_in, wlo + o_in,
                                             b_in, h, hhi, hlo, Mrows, D, FIN, 0, 3);

    for (int layer = 0; layer < NL; layer++) {
        const float* wqL = wq + (size_t)layer * D * D;
        const float* wkL = wk + (size_t)layer * D * D;
        const float* wvL = wv + (size_t)layer * D * D;
        const float* woL = wo + (size_t)layer * D * D;
        const float* f1L = w_ff1 + (size_t)layer * D * DFF;
        const float* f2L = w_ff2 + (size_t)layer * DFF * D;
        const int*   ixL = idx + (size_t)layer * L_ * S_;

        transpose_split_kernel<<<dim3(D / 32,   D / 32),   tb>>>(wqL, whi + o_q,  wlo + o_q,  D, D);
        transpose_split_kernel<<<dim3(D / 32,   D / 32),   tb>>>(wkL, whi + o_k,  wlo + o_k,  D, D);
        transpose_split_kernel<<<dim3(D / 32,   D / 32),   tb>>>(wvL, whi + o_v,  wlo + o_v,  D, D);
        transpose_split_kernel<<<dim3(D / 32,   D / 32),   tb>>>(woL, whi + o_o,  wlo + o_o,  D, D);
        transpose_split_kernel<<<dim3(DFF / 32, D / 32),   tb>>>(f1L, whi + o_f1, wlo + o_f1, D, DFF);
        transpose_split_kernel<<<dim3(D / 32,   DFF / 32), tb>>>(f2L, whi + o_f2, wlo + o_f2, DFF, D);

        mma_gemm_bf16<<<gD, 256, GEMM_SMEM_V2>>>(hhi, hlo, whi + o_q, wlo + o_q,
                                                 bq + layer * D, q, nullptr, nullptr, Mrows, D, D, 0, 1);
        mma_gemm_bf16<<<gD, 256, GEMM_SMEM_V2>>>(hhi, hlo, whi + o_k, wlo + o_k,
                                                 bk + layer * D, k, nullptr, nullptr, Mrows, D, D, 0, 1);
        mma_gemm_bf16<<<gD, 256, GEMM_SMEM_V2>>>(hhi, hlo, whi + o_v, wlo + o_v,
                                                 bv + layer * D, v, nullptr, nullptr, Mrows, D, D, 0, 1);

        qk_sample_kernel<<<(B_ * H_ * L_ * 32) / 256, 256>>>(q, k, ixL, Mv);
        topk_kernel<<<B_ * H_, 256>>>(Mv, top);
        vmean_kernel<<<B_ * H_, 256>>>(v, vm);
        ctxfill_kernel<<<(B_ * L_ * D) / 256, 256>>>(vm, chi, clo);
        attn_topq_flash<<<B_ * H_, 256>>>(q, k, v, top, chi, clo);

        mma_gemm_bf16<<<gD, 256, GEMM_SMEM_V2>>>(chi, clo, whi + o_o, wlo + o_o,
                                                 bo + layer * D, nx, nullptr, nullptr, Mrows, D, D, 0, 1);
        add_ln_kernel<<<Mrows, 256>>>(h, nx, ln1_g + layer * D, ln1_b + layer * D, hhi, hlo);

        mma_gemm_bf16<<<gFF, 256, GEMM_SMEM_V2>>>(hhi, hlo, whi + o_f1, wlo + o_f1,
                                                  b_ff1 + layer * DFF, nullptr, fhi, flo, Mrows, DFF, D, 1, 2);
        mma_gemm_bf16<<<gD, 256, GEMM_SMEM_V2>>>(fhi, flo, whi + o_f2, wlo + o_f2,
                                                 b_ff2 + layer * D, nx, nullptr, nullptr, Mrows, D, DFF, 0, 1);
        add_ln_kernel<<<Mrows, 256>>>(h, nx, ln2_g + layer * D, ln2_b + layer * D, hhi, hlo);
    }

    head_kernel<<<B_, 64>>>(h, w_fc1, b_fc1, w_fc2, b_fc2, out);
}

// round 5
// speedup vs baseline: 2.0876x; 1.0688x over previous
#include <cuda_runtime.h>
#include <cuda_bf16.h>
#include <cstdint>
#include <math.h>

// Problem constants
#define B_   8
#define L_   2048
#define FIN  32
#define D    256
#define H_   8
#define DH   32
#define DFF  1024
#define S_   40
#define U_   40
#define NL   2

// ---------------- scratch (device globals; no allocation allowed) ----------------
__device__ float g_h  [B_*L_*D];
__device__ float g_q  [B_*L_*D];
__device__ float g_k  [B_*L_*D];
__device__ float g_v  [B_*L_*D];
__device__ float g_nx [B_*L_*D];
__device__ float g_M  [B_*H_*L_];
__device__ int   g_top[B_*H_*U_];
__device__ float g_vm [B_*H_*DH];

// bf16 hi/lo planes
__device__ __nv_bfloat16 g_x_hi [B_*L_*FIN], g_x_lo [B_*L_*FIN];
__device__ __nv_bfloat16 g_h_hi [B_*L_*D],   g_h_lo [B_*L_*D];
__device__ __nv_bfloat16 g_ctx_hi[B_*L_*D],  g_ctx_lo[B_*L_*D];
__device__ __nv_bfloat16 g_ff_hi[B_*L_*DFF], g_ff_lo[B_*L_*DFF];
// all-layer weight planes: in (8192) + 2 layers x (4*65536 + 262144 + 262144)
#define LYR_SZ   786432
#define WT_TOTAL (FIN*D + NL*LYR_SZ)
__device__ __nv_bfloat16 g_wt_hi[WT_TOTAL], g_wt_lo[WT_TOTAL];

// =========================== helpers ===============================================
__device__ __forceinline__ uint32_t smem_u32(const void* p) {
    uint32_t a;
    asm("{ .reg .u64 t; cvta.to.shared.u64 t, %1; cvt.u32.u64 %0, t; }" : "=r"(a) : "l"(p));
    return a;
}
__device__ __forceinline__ void split2(float x, float y, uint32_t& hi, uint32_t& lo) {
    __nv_bfloat162 h = __float22bfloat162_rn(make_float2(x, y));
    float2 hf = __bfloat1622float2(h);
    __nv_bfloat162 l = __float22bfloat162_rn(make_float2(x - hf.x, y - hf.y));
    hi = *(uint32_t*)&h; lo = *(uint32_t*)&l;
}
__device__ __forceinline__ void split_scalar(float v, __nv_bfloat16* hp, __nv_bfloat16* lp) {
    __nv_bfloat16 hb = __float2bfloat16(v);
    *hp = hb;
    *lp = __float2bfloat16(v - __bfloat162float(hb));
}

#define MMA_BF16(c, a, b)                                                        \
    asm volatile("mma.sync.aligned.m16n8k16.row.col.f32.bf16.bf16.f32 "          \
        "{%0,%1,%2,%3}, {%4,%5,%6,%7}, {%8,%9}, {%0,%1,%2,%3};"                  \
        : "+f"((c)[0]), "+f"((c)[1]), "+f"((c)[2]), "+f"((c)[3])                  \
        : "r"((a)[0]), "r"((a)[1]), "r"((a)[2]), "r"((a)[3]),                     \
          "r"((b)[0]), "r"((b)[1]))

#define LDM4(r, addr)                                                            \
    asm volatile("ldmatrix.sync.aligned.m8n8.x4.shared.b16 {%0,%1,%2,%3}, [%4];" \
        : "=r"((r)[0]), "=r"((r)[1]), "=r"((r)[2]), "=r"((r)[3]) : "r"(addr))

// =================== pipelined bf16x3 GEMM with ldmatrix ===========================
// A planes: [M,K] bf16 hi/lo. Bt planes: [Ntot,K] bf16 hi/lo (pre-transposed).
// Block tile 128x128, K chunk 32, double-buffered cp.async, ldmatrix fragments.
// mode bit0: fp32 C out; bit1: split-plane out. split3: route output by bcol>>8.
#define RSU   20                  // uint32 per smem row (16 data + 4 pad)
#define PLANE (128*RSU)
#define BUFU  (4*PLANE)
#define GEMM_SMEM_V2 (2*BUFU*4)   // 81920 bytes

__global__ __launch_bounds__(256, 1)
void mma_gemm_bf16(const __nv_bfloat16* __restrict__ Ahi, const __nv_bfloat16* __restrict__ Alo,
                   const __nv_bfloat16* __restrict__ Bhi, const __nv_bfloat16* __restrict__ Blo,
                   const float* __restrict__ b0, const float* __restrict__ b1,
                   const float* __restrict__ b2,
                   float* __restrict__ C0, float* __restrict__ C1, float* __restrict__ C2,
                   __nv_bfloat16* __restrict__ Chi, __nv_bfloat16* __restrict__ Clo,
                   int M, int N, int K, int relu, int mode, int split3)
{
    extern __shared__ uint32_t sm[];
    int tid  = threadIdx.x;
    int brow = blockIdx.y * 128;
    int bcol = blockIdx.x * 128;
    int w = tid >> 5, lane = tid & 31;
    int gid = lane >> 2, tig = lane & 3;
    int moff = (w >> 1) * 32, noff = (w & 1) * 64;
    uint32_t smb = smem_u32(sm);

    // per-lane ldmatrix byte offsets within a plane
    int mat = lane >> 3, r8 = lane & 7;
    uint32_t aoff[2], boff[4];
    #pragma unroll
    for (int mt = 0; mt < 2; mt++) {
        int row = moff + mt * 16 + (mat & 1) * 8 + r8;
        aoff[mt] = (uint32_t)(row * RSU + (mat >> 1) * 4) * 4;
    }
    #pragma unroll
    for (int p = 0; p < 4; p++) {
        int row = noff + p * 16 + (mat >> 1) * 8 + r8;
        boff[p] = (uint32_t)(row * RSU + (mat & 1) * 4) * 4;
    }

    auto load_chunk = [&](int c, int buf) {
        int k0 = c * 32;
        uint32_t sb = smb + (uint32_t)buf * (BUFU * 4);
        #pragma unroll
        for (int i = 0; i < 8; i++) {
            int e  = tid + i * 256;
            int pl = e >> 9;
            int r  = (e >> 2) & 127;
            int s  = e & 3;
            const __nv_bfloat16* src;
            if      (pl == 0) src = Ahi + (size_t)(brow + r) * K + k0 + s * 8;
            else if (pl == 1) src = Alo + (size_t)(brow + r) * K + k0 + s * 8;
            else if (pl == 2) src = Bhi + (size_t)(bcol + r) * K + k0 + s * 8;
            else              src = Blo + (size_t)(bcol + r) * K + k0 + s * 8;
            uint32_t dst = sb + (uint32_t)(pl * PLANE + r * RSU + s * 4) * 4;
            asm volatile("cp.async.cg.shared.global [%0], [%1], 16;" :: "r"(dst), "l"(src));
        }
        asm volatile("cp.async.commit_group;" ::: "memory");
    };

    float acc[2][8][4] = {};
    const int NC = K >> 5;
    load_chunk(0, 0);

    for (int c = 0; c < NC; c++) {
        if (c + 1 < NC) {
            load_chunk(c + 1, (c + 1) & 1);
            asm volatile("cp.async.wait_group 1;" ::: "memory");
        } else {
            asm volatile("cp.async.wait_group 0;" ::: "memory");
        }
        __syncthreads();
        uint32_t bb = smb + (uint32_t)(c & 1) * (BUFU * 4);
        uint32_t Ahb = bb, Alb = bb + PLANE * 4, Bhb = bb + 2 * PLANE * 4, Blb = bb + 3 * PLANE * 4;

        #pragma unroll
        for (int ks = 0; ks < 2; ks++) {
            uint32_t ka = ks * 32;
            uint32_t afh[2][4], afl[2][4], bfh[4][4], bfl[4][4];
            #pragma unroll
            for (int mt = 0; mt < 2; mt++) {
                LDM4(afh[mt], Ahb + aoff[mt] + ka);
                LDM4(afl[mt], Alb + aoff[mt] + ka);
            }
            #pragma unroll
            for (int p = 0; p < 4; p++) {
                LDM4(bfh[p], Bhb + boff[p] + ka);
                LDM4(bfl[p], Blb + boff[p] + ka);
            }
            #pragma unroll
            for (int mt = 0; mt < 2; mt++)
                #pragma unroll
                for (int p = 0; p < 4; p++)
                    #pragma unroll
                    for (int hf = 0; hf < 2; hf++) {
                        int nt = p * 2 + hf;
                        MMA_BF16(acc[mt][nt], afh[mt], &bfh[p][hf * 2]);
                        MMA_BF16(acc[mt][nt], afh[mt], &bfl[p][hf * 2]);
                        MMA_BF16(acc[mt][nt], afl[mt], &bfh[p][hf * 2]);
                    }
        }
        __syncthreads();
    }

    // epilogue: pick output target
    float* Cf; const float* bp_; int cb, Nst;
    if (split3) {
        int mi = bcol >> 8;
        Cf  = (mi == 0) ? C0 : (mi == 1 ? C1 : C2);
        bp_ = (mi == 0) ? b0 : (mi == 1 ? b1 : b2);
        cb = bcol & 255; Nst = 256;
    } else {
        Cf = C0; bp_ = b0; cb = bcol; Nst = N;
    }

    #pragma unroll
    for (int mt = 0; mt < 2; mt++) {
        int r0 = brow + moff + mt * 16 + gid;
        #pragma unroll
        for (int nt = 0; nt < 8; nt++) {
            int c = cb + noff + nt * 8 + tig * 2;
            float bb0 = bp_[c], bb1 = bp_[c + 1];
            float2 o0 = make_float2(acc[mt][nt][0] + bb0, acc[mt][nt][1] + bb1);
            float2 o1 = make_float2(acc[mt][nt][2] + bb0, acc[mt][nt][3] + bb1);
            if (relu) {
                o0.x = fmaxf(o0.x, 0.f); o0.y = fmaxf(o0.y, 0.f);
                o1.x = fmaxf(o1.x, 0.f); o1.y = fmaxf(o1.y, 0.f);
            }
            size_t i0 = (size_t)r0 * Nst + c;
            size_t i1 = (size_t)(r0 + 8) * Nst + c;
            if (mode & 1) {
                *(float2*)(Cf + i0) = o0;
                *(float2*)(Cf + i1) = o1;
            }
            if (mode & 2) {
                uint32_t h0, l0, h1, l1;
                split2(o0.x, o0.y, h0, l0);
                split2(o1.x, o1.y, h1, l1);
                *(uint32_t*)(Chi + i0) = h0; *(uint32_t*)(Clo + i0) = l0;
                *(uint32_t*)(Chi + i1) = h1; *(uint32_t*)(Clo + i1) = l1;
            }
        }
    }
}

// ---------------- batched transpose+split of ALL weights (one launch) -------------
// 13 matrices -> hi/lo [N,K] planes. Tile table hardcoded.
__global__ void transpose_all_kernel(const float* __restrict__ w_in,
                                     const float* __restrict__ wq, const float* __restrict__ wk,
                                     const float* __restrict__ wv, const float* __restrict__ wo,
                                     const float* __restrict__ f1, const float* __restrict__ f2,
                                     __nv_bfloat16* __restrict__ hi, __nv_bfloat16* __restrict__ lo)
{
    const int start[14] = {0, 8, 72, 136, 200, 264, 520, 776, 840, 904, 968, 1032, 1288, 1544};
    int t = blockIdx.x;
    int m = 0;
    #pragma unroll
    for (int i = 1; i < 14; i++) if (t >= start[i]) m = i;
    // m in [0,12]
    int layer = (m >= 7) ? 1 : 0;
    int mi = (m == 0) ? 0 : ((m - 1) % 6) + 1;   // 0=in, 1..4=q,k,v,o, 5=f1, 6=f2
    const float* src; int K, N; size_t dst;
    size_t base = (size_t)FIN * D + (size_t)layer * LYR_SZ;
    switch (mi) {
        case 0: src = w_in;                          K = FIN; N = D;   dst = 0;             break;
        case 1: src = wq + (size_t)layer * D * D;    K = D;   N = D;   dst = base;          break;
        case 2: src = wk + (size_t)layer * D * D;    K = D;   N = D;   dst = base + 65536;  break;
        case 3: src = wv + (size_t)layer * D * D;    K = D;   N = D;   dst = base + 131072; break;
        case 4: src = wo + (size_t)layer * D * D;    K = D;   N = D;   dst = base + 196608; break;
        case 5: src = f1 + (size_t)layer * D * DFF;  K = D;   N = DFF; dst = base + 262144; break;
        default:src = f2 + (size_t)layer * DFF * D;  K = DFF; N = D;   dst = base + 524288; break;
    }
    int lt = t - start[m];
    int ntn = N >> 5;
    int nb = (lt % ntn) << 5, kb = (lt / ntn) << 5;

    __shared__ float tbuf[32][33];
    int tx = threadIdx.x, ty = threadIdx.y;
    #pragma unroll
    for (int i = ty; i < 32; i += 8)
        tbuf[i][tx] = src[(size_t)(kb + i) * N + nb + tx];
    __syncthreads();
    #pragma unroll
    for (int i = ty; i < 32; i += 8) {
        float v = tbuf[tx][i];
        size_t o = dst + (size_t)(nb + i) * K + kb + tx;
        split_scalar(v, hi + o, lo + o);
    }
}

// ---------------- plain split: fp32 -> hi/lo bf16 ---------------------------------
__global__ void split_kernel(const float* __restrict__ in,
                             __nv_bfloat16* __restrict__ hi,
                             __nv_bfloat16* __restrict__ lo, int n)
{
    int i = (blockIdx.x * blockDim.x + threadIdx.x) * 2;
    if (i >= n) return;
    float2 v = *(const float2*)(in + i);
    uint32_t h, l;
    split2(v.x, v.y, h, l);
    *(uint32_t*)(hi + i) = h;
    *(uint32_t*)(lo + i) = l;
}

// ---------------- sampled QK -> M score ------------------------------------------
__global__ void qk_sample_kernel(const float* __restrict__ q, const float* __restrict__ k,
                                 const int* __restrict__ idx, float* __restrict__ Mout)
{
    int gw   = (blockIdx.x * blockDim.x + threadIdx.x) >> 5;
    int lane = threadIdx.x & 31;
    if (gw >= B_ * H_ * L_) return;
    int l  = gw & (L_ - 1);
    int bh = gw >> 11;
    int b  = bh >> 3, h = bh & 7;

    float qd = q[((size_t)b * L_ + l) * D + h * DH + lane];
    const float* kbase = k + (size_t)b * L_ * D + h * DH;
    const int*   irow  = idx + l * S_;

    float mx = -1e30f, sm = 0.0f;
    for (int s = 0; s < S_; s++) {
        int   ki = __ldg(&irow[s]);
        float p  = qd * __ldg(&kbase[(size_t)ki * D + lane]);
        #pragma unroll
        for (int off = 16; off; off >>= 1) p += __shfl_xor_sync(0xffffffffu, p, off);
        mx = fmaxf(mx, p);
        sm += p;
    }
    if (lane == 0) Mout[gw] = mx - sm * (1.0f / (float)L_);
}

// ---------------- top-40 per (b,h) ------------------------------------------------
__global__ void topk_kernel(const float* __restrict__ Mv, int* __restrict__ top)
{
    int bh  = blockIdx.x;
    int tid = threadIdx.x;
    __shared__ float sv[L_];
    __shared__ float rv[256];
    __shared__ int   ri[256];
    for (int i = tid; i < L_; i += 256) sv[i] = Mv[(size_t)bh * L_ + i];
    __syncthreads();
    for (int r = 0; r < U_; r++) {
        float bv = -1e30f; int bi = 0x7fffffff;
        for (int i = tid; i < L_; i += 256) {
            float v = sv[i];
            if (v > bv || (v == bv && i < bi)) { bv = v; bi = i; }
        }
        rv[tid] = bv; ri[tid] = bi;
        __syncthreads();
        for (int s = 128; s; s >>= 1) {
            if (tid < s) {
                float ov = rv[tid + s]; int oi = ri[tid + s];
                if (ov > rv[tid] || (ov == rv[tid] && oi < ri[tid])) { rv[tid] = ov; ri[tid] = oi; }
            }
            __syncthreads();
        }
        if (tid == 0) { top[bh * U_ + r] = ri[0]; sv[ri[0]] = -1e30f; }
        __syncthreads();
    }
}

// ---------------- v mean over L per (b,h) -----------------------------------------
__global__ void vmean_kernel(const float* __restrict__ v, float* __restrict__ vm)
{
    int bh = blockIdx.x; int b = bh >> 3, h = bh & 7;
    int tid = threadIdx.x;
    int d = tid & 31, seg = tid >> 5;
    const float* vb = v + (size_t)b * L_ * D + h * DH + d;
    float acc = 0.0f;
    for (int l = seg; l < L_; l += 8) acc += vb[(size_t)l * D];
    __shared__ float sp[8][32];
    sp[seg][d] = acc;
    __syncthreads();
    if (tid < 32) {
        float s = 0.0f;
        #pragma unroll
        for (int i = 0; i < 8; i++) s += sp[i][tid];
        vm[bh * DH + tid] = s * (1.0f / (float)L_);
    }
}

// ---------------- fill ctx planes with broadcast v-mean ---------------------------
__global__ void ctxfill_kernel(const float* __restrict__ vm,
                               __nv_bfloat16* __restrict__ chi,
                               __nv_bfloat16* __restrict__ clo)
{
    int i = blockIdx.x * blockDim.x + threadIdx.x;
    if (i >= B_ * L_ * D) return;
    int dfull = i & (D - 1);
    int b = i / (L_ * D);
    int h = dfull >> 5, d = dfull & 31;
    float v = vm[((b << 3) + h) * DH + d];
    split_scalar(v, chi + i, clo + i);
}

// ---------------- flash-style reduced attention: one block per (b,h) --------------
__global__ __launch_bounds__(256, 1)
void attn_topq_flash(const float* __restrict__ q, const float* __restrict__ k,
                     const float* __restrict__ v, const int* __restrict__ top,
                     __nv_bfloat16* __restrict__ chi, __nv_bfloat16* __restrict__ clo)
{
    __shared__ float Ks[128][33];
    __shared__ float Vs[128][33];
    __shared__ float qs[40][32];
    __shared__ float ps[8][128];
    __shared__ int   stop[40];

    int bh = blockIdx.x; int b = bh >> 3, h = bh & 7;
    int tid = threadIdx.x, w = tid >> 5, lane = tid & 31;

    if (tid < 40) stop[tid] = top[bh * U_ + tid];
    __syncthreads();
    for (int i = tid; i < 40 * 32; i += 256) {
        int u = i >> 5, d = i & 31;
        qs[u][d] = q[((size_t)b * L_ + stop[u]) * D + h * DH + d];
    }

    float m[5], l[5], acc[5];
    #pragma unroll
    for (int j = 0; j < 5; j++) { m[j] = -1e30f; l[j] = 0.f; acc[j] = 0.f; }
    const float scale = 0.1767766952966369f;
    const float* kb = k + (size_t)b * L_ * D + h * DH;
    const float* vb = v + (size_t)b * L_ * D + h * DH;
    __syncthreads();

    for (int t0 = 0; t0 < L_; t0 += 128) {
        for (int i = tid; i < 128 * 32; i += 256) {
            int r = i >> 5, d = i & 31;
            Ks[r][d] = kb[(size_t)(t0 + r) * D + d];
            Vs[r][d] = vb[(size_t)(t0 + r) * D + d];
        }
        __syncthreads();

        float sj[5][4];
        #pragma unroll
        for (int j = 0; j < 5; j++)
            #pragma unroll
            for (int i = 0; i < 4; i++) sj[j][i] = 0.f;
        #pragma unroll
        for (int d = 0; d < 32; d++) {
            float k0v = Ks[lane][d], k1v = Ks[lane + 32][d];
            float k2v = Ks[lane + 64][d], k3v = Ks[lane + 96][d];
            #pragma unroll
            for (int j = 0; j < 5; j++) {
                float qd = qs[w * 5 + j][d];
                sj[j][0] = fmaf(qd, k0v, sj[j][0]);
                sj[j][1] = fmaf(qd, k1v, sj[j][1]);
                sj[j][2] = fmaf(qd, k2v, sj[j][2]);
                sj[j][3] = fmaf(qd, k3v, sj[j][3]);
            }
        }
        #pragma unroll
        for (int j = 0; j < 5; j++) {
            float s0 = sj[j][0] * scale, s1 = sj[j][1] * scale;
            float s2 = sj[j][2] * scale, s3 = sj[j][3] * scale;
            float tm = fmaxf(fmaxf(s0, s1), fmaxf(s2, s3));
            #pragma unroll
            for (int o = 16; o; o >>= 1) tm = fmaxf(tm, __shfl_xor_sync(0xffffffffu, tm, o));
            float mn   = fmaxf(m[j], tm);
            float corr = __expf(m[j] - mn);
            float p0 = __expf(s0 - mn), p1 = __expf(s1 - mn);
            float p2 = __expf(s2 - mn), p3 = __expf(s3 - mn);
            float psum = p0 + p1 + p2 + p3;
            #pragma unroll
            for (int o = 16; o; o >>= 1) psum += __shfl_xor_sync(0xffffffffu, psum, o);
            l[j] = l[j] * corr + psum;
            m[j] = mn;
            ps[w][lane] = p0; ps[w][lane + 32] = p1; ps[w][lane + 64] = p2; ps[w][lane + 96] = p3;
            __syncwarp();
            float aa = acc[j] * corr;
            const float4* pv4 = (const float4*)ps[w];
            #pragma unroll 8
            for (int kk4 = 0; kk4 < 32; kk4++) {
                float4 p4 = pv4[kk4];
                int kk = kk4 * 4;
                aa = fmaf(p4.x, Vs[kk][lane],     aa);
                aa = fmaf(p4.y, Vs[kk + 1][lane], aa);
                aa = fmaf(p4.z, Vs[kk + 2][lane], aa);
                aa = fmaf(p4.w, Vs[kk + 3][lane], aa);
            }
            acc[j] = aa;
            __syncwarp();
        }
        __syncthreads();
    }
    #pragma unroll
    for (int j = 0; j < 5; j++) {
        int u = w * 5 + j;
        float o = acc[j] / l[j];
        size_t off = ((size_t)b * L_ + stop[u]) * D + h * DH + lane;
        split_scalar(o, chi + off, clo + off);
    }
}

// ---------------- residual add + LayerNorm + split (shuffle reductions) -----------
__global__ void add_ln_kernel(float* __restrict__ h, const float* __restrict__ r,
                              const float* __restrict__ g, const float* __restrict__ bb,
                              __nv_bfloat16* __restrict__ hhi, __nv_bfloat16* __restrict__ hlo)
{
    int row = blockIdx.x;
    int tid = threadIdx.x;
    int w = tid >> 5, lane = tid & 31;
    size_t off = (size_t)row * D + tid;
    float val = h[off] + r[off];
    float s1 = val, s2 = val * val;
    #pragma unroll
    for (int o = 16; o; o >>= 1) {
        s1 += __shfl_xor_sync(0xffffffffu, s1, o);
        s2 += __shfl_xor_sync(0xffffffffu, s2, o);
    }
    __shared__ float a1[8], a2[8];
    __shared__ float mu_s, rv_s;
    if (lane == 0) { a1[w] = s1; a2[w] = s2; }
    __syncthreads();
    if (w == 0) {
        float t1 = (lane < 8) ? a1[lane] : 0.f;
        float t2 = (lane < 8) ? a2[lane] : 0.f;
        #pragma unroll
        for (int o = 4; o; o >>= 1) {
            t1 += __shfl_xor_sync(0xffffffffu, t1, o);
            t2 += __shfl_xor_sync(0xffffffffu, t2, o);
        }
        if (lane == 0) {
            float mu = t1 * (1.0f / (float)D);
            float var = t2 * (1.0f / (float)D) - mu * mu;
            mu_s = mu;
            rv_s = rsqrtf(var + 1e-5f);
        }
    }
    __syncthreads();
    float o = (val - mu_s) * rv_s * g[tid] + bb[tid];
    h[off] = o;
    split_scalar(o, hhi + off, hlo + off);
}

// ---------------- final MLP head ---------------------------------------------------
__global__ void head_kernel(const float* __restrict__ h, const float* __restrict__ w1,
                            const float* __restrict__ b1, const float* __restrict__ w2,
                            const float* __restrict__ b2, float* __restrict__ out)
{
    int b = blockIdx.x;
    int j = threadIdx.x;
    const float* last = h + ((size_t)b * L_ + (L_ - 1)) * D;
    float acc = b1[j];
    for (int d = 0; d < D; d++) acc = fmaf(last[d], w1[d * 64 + j], acc);
    acc = fmaxf(acc, 0.0f) * w2[j];
    __shared__ float s[64];
    s[j] = acc; __syncthreads();
    for (int st = 32; st; st >>= 1) { if (j < st) s[j] += s[j + st]; __syncthreads(); }
    if (j == 0) out[b] = s[0] + b2[0];
}

// ===================================================================================
extern "C" void kernel_launch(void* const* d_in, const int* in_sizes, int n_in,
                              void* d_out, int out_size)
{
    const float* x     = (const float*)d_in[0];
    const int*   idx   = (const int*)  d_in[1];
    const float* w_in  = (const float*)d_in[2];
    const float* b_in  = (const float*)d_in[3];
    const float* wq    = (const float*)d_in[4];
    const float* bq    = (const float*)d_in[5];
    const float* wk    = (const float*)d_in[6];
    const float* bk    = (const float*)d_in[7];
    const float* wv    = (const float*)d_in[8];
    const float* bv    = (const float*)d_in[9];
    const float* wo    = (const float*)d_in[10];
    const float* bo    = (const float*)d_in[11];
    const float* w_ff1 = (const float*)d_in[12];
    const float* b_ff1 = (const float*)d_in[13];
    const float* w_ff2 = (const float*)d_in[14];
    const float* b_ff2 = (const float*)d_in[15];
    const float* ln1_g = (const float*)d_in[16];
    const float* ln1_b = (const float*)d_in[17];
    const float* ln2_g = (const float*)d_in[18];
    const float* ln2_b = (const float*)d_in[19];
    const float* w_fc1 = (const float*)d_in[20];
    const float* b_fc1 = (const float*)d_in[21];
    const float* w_fc2 = (const float*)d_in[22];
    const float* b_fc2 = (const float*)d_in[23];
    float* out = (float*)d_out;

    float *h, *q, *k, *v, *nx, *Mv, *vm; int* top;
    __nv_bfloat16 *xhi, *xlo, *hhi, *hlo, *chi, *clo, *fhi, *flo, *whi, *wlo;
    cudaGetSymbolAddress((void**)&h,   g_h);
    cudaGetSymbolAddress((void**)&q,   g_q);
    cudaGetSymbolAddress((void**)&k,   g_k);
    cudaGetSymbolAddress((void**)&v,   g_v);
    cudaGetSymbolAddress((void**)&nx,  g_nx);
    cudaGetSymbolAddress((void**)&Mv,  g_M);
    cudaGetSymbolAddress((void**)&top, g_top);
    cudaGetSymbolAddress((void**)&vm,  g_vm);
    cudaGetSymbolAddress((void**)&xhi, g_x_hi);  cudaGetSymbolAddress((void**)&xlo, g_x_lo);
    cudaGetSymbolAddress((void**)&hhi, g_h_hi);  cudaGetSymbolAddress((void**)&hlo, g_h_lo);
    cudaGetSymbolAddress((void**)&chi, g_ctx_hi); cudaGetSymbolAddress((void**)&clo, g_ctx_lo);
    cudaGetSymbolAddress((void**)&fhi, g_ff_hi); cudaGetSymbolAddress((void**)&flo, g_ff_lo);
    cudaGetSymbolAddress((void**)&whi, g_wt_hi); cudaGetSymbolAddress((void**)&wlo, g_wt_lo);

    cudaFuncSetAttribute(mma_gemm_bf16, cudaFuncAttributeMaxDynamicSharedMemorySize, GEMM_SMEM_V2);

    const int Mrows = B_ * L_;                     // 16384
    dim3 gD  (D / 128,   Mrows / 128);             // (2,128)
    dim3 gQKV(3 * D / 128, Mrows / 128);           // (6,128)
    dim3 gFF (DFF / 128, Mrows / 128);             // (8,128)
    dim3 tb(32, 8);

    // weight plane offsets (bf16 elems)
    const size_t o_in = 0;
    auto o_q  = [&](int l){ return (size_t)FIN * D + (size_t)l * LYR_SZ; };
    auto o_o  = [&](int l){ return o_q(l) + 196608; };
    auto o_f1 = [&](int l){ return o_q(l) + 262144; };
    auto o_f2 = [&](int l){ return o_q(l) + 524288; };

    // 0: split x; 1: all weight transposes; 2: input projection
    split_kernel<<<(B_ * L_ * FIN) / 512, 256>>>(x, xhi, xlo, B_ * L_ * FIN);
    transpose_all_kernel<<<1544, tb>>>(w_in, wq, wk, wv, wo, w_ff1, w_ff2, whi, wlo);
    mma_gemm_bf16<<<gD, 256, GEMM_SMEM_V2>>>(xhi, xlo, whi + o_in, wlo + o_in,
        b_in, nullptr, nullptr, h, nullptr, nullptr, hhi, hlo, Mrows, D, FIN, 0, 3, 0);

    for (int layer = 0; layer < NL; layer++) {
        const int* ixL = idx + (size_t)layer * L_ * S_;

        // fused QKV (split3 routing)
        mma_gemm_bf16<<<gQKV, 256, GEMM_SMEM_V2>>>(hhi, hlo, whi + o_q(layer), wlo + o_q(layer),
            bq + layer * D, bk + layer * D, bv + layer * D,
            q, k, v, nullptr, nullptr, Mrows, 768, D, 0, 1, 1);

        qk_sample_kernel<<<(B_ * H_ * L_ * 32) / 256, 256>>>(q, k, ixL, Mv);
        topk_kernel<<<B_ * H_, 256>>>(Mv, top);          // launch #5 on first layer
        vmean_kernel<<<B_ * H_, 256>>>(v, vm);
        ctxfill_kernel<<<(B_ * L_ * D) / 256, 256>>>(vm, chi, clo);
        attn_topq_flash<<<B_ * H_, 256>>>(q, k, v, top, chi, clo);

        mma_gemm_bf16<<<gD, 256, GEMM_SMEM_V2>>>(chi, clo, whi + o_o(layer), wlo + o_o(layer),
            bo + layer * D, nullptr, nullptr, nx, nullptr, nullptr, nullptr, nullptr,
            Mrows, D, D, 0, 1, 0);
        add_ln_kernel<<<Mrows, 256>>>(h, nx, ln1_g + layer * D, ln1_b + layer * D, hhi, hlo);

        mma_gemm_bf16<<<gFF, 256, GEMM_SMEM_V2>>>(hhi, hlo, whi + o_f1(layer), wlo + o_f1(layer),
            b_ff1 + layer * DFF, nullptr, nullptr, nullptr, nullptr, nullptr, fhi, flo,
            Mrows, DFF, D, 1, 2, 0);
        mma_gemm_bf16<<<gD, 256, GEMM_SMEM_V2>>>(fhi, flo, whi + o_f2(layer), wlo + o_f2(layer),
            b_ff2 + layer * D, nullptr, nullptr, nx, nullptr, nullptr, nullptr, nullptr,
            Mrows, D, DFF, 0, 1, 0);
        add_ln_kernel<<<Mrows, 256>>>(h, nx, ln2_g + layer * D, ln2_b + layer * D, hhi, hlo);
    }

    head_kernel<<<B_, 64>>>(h, w_fc1, b_fc1, w_fc2, b_fc2, out);
}

// round 6
// speedup vs baseline: 2.3567x; 1.1289x over previous
#include <cuda_runtime.h>
#include <cuda_bf16.h>
#include <cstdint>
#include <math.h>

// Problem constants
#define B_   8
#define L_   2048
#define FIN  32
#define D    256
#define H_   8
#define DH   32
#define DFF  1024
#define S_   40
#define U_   40
#define NL   2

// ---------------- scratch (device globals; no allocation allowed) ----------------
__device__ float g_h  [B_*L_*D];
__device__ float g_q  [B_*L_*D];
__device__ float g_k  [B_*L_*D];
__device__ float g_v  [B_*L_*D];
__device__ float g_nx [B_*L_*D];
__device__ float g_M  [B_*H_*L_];
__device__ int   g_top[B_*H_*U_];
__device__ float g_vm [B_*H_*DH];

// bf16 hi/lo planes
__device__ __nv_bfloat16 g_x_hi [B_*L_*FIN], g_x_lo [B_*L_*FIN];
__device__ __nv_bfloat16 g_h_hi [B_*L_*D],   g_h_lo [B_*L_*D];
__device__ __nv_bfloat16 g_ctx_hi[B_*L_*D],  g_ctx_lo[B_*L_*D];
__device__ __nv_bfloat16 g_ff_hi[B_*L_*DFF], g_ff_lo[B_*L_*DFF];
#define LYR_SZ   786432
#define WT_TOTAL (FIN*D + NL*LYR_SZ)
__device__ __nv_bfloat16 g_wt_hi[WT_TOTAL], g_wt_lo[WT_TOTAL];

// =========================== helpers ===============================================
__device__ __forceinline__ uint32_t smem_u32(const void* p) {
    uint32_t a;
    asm("{ .reg .u64 t; cvta.to.shared.u64 t, %1; cvt.u32.u64 %0, t; }" : "=r"(a) : "l"(p));
    return a;
}
__device__ __forceinline__ void split2(float x, float y, uint32_t& hi, uint32_t& lo) {
    __nv_bfloat162 h = __float22bfloat162_rn(make_float2(x, y));
    float2 hf = __bfloat1622float2(h);
    __nv_bfloat162 l = __float22bfloat162_rn(make_float2(x - hf.x, y - hf.y));
    hi = *(uint32_t*)&h; lo = *(uint32_t*)&l;
}
__device__ __forceinline__ void split_scalar(float v, __nv_bfloat16* hp, __nv_bfloat16* lp) {
    __nv_bfloat16 hb = __float2bfloat16(v);
    *hp = hb;
    *lp = __float2bfloat16(v - __bfloat162float(hb));
}

#define MMA_BF16(c, a, b)                                                        \
    asm volatile("mma.sync.aligned.m16n8k16.row.col.f32.bf16.bf16.f32 "          \
        "{%0,%1,%2,%3}, {%4,%5,%6,%7}, {%8,%9}, {%0,%1,%2,%3};"                  \
        : "+f"((c)[0]), "+f"((c)[1]), "+f"((c)[2]), "+f"((c)[3])                  \
        : "r"((a)[0]), "r"((a)[1]), "r"((a)[2]), "r"((a)[3]),                     \
          "r"((b)[0]), "r"((b)[1]))

#define LDM4(r, addr)                                                            \
    asm volatile("ldmatrix.sync.aligned.m8n8.x4.shared.b16 {%0,%1,%2,%3}, [%4];" \
        : "=r"((r)[0]), "=r"((r)[1]), "=r"((r)[2]), "=r"((r)[3]) : "r"(addr))

// =================== pipelined bf16x3 GEMM with ldmatrix ===========================
#define RSU   20                  // uint32 per smem row (16 data + 4 pad)
#define PLANE (128*RSU)
#define BUFU  (4*PLANE)
#define GEMM_SMEM_V2 (2*BUFU*4)   // 81920 bytes

__global__ __launch_bounds__(256, 2)
void mma_gemm_bf16(const __nv_bfloat16* __restrict__ Ahi, const __nv_bfloat16* __restrict__ Alo,
                   const __nv_bfloat16* __restrict__ Bhi, const __nv_bfloat16* __restrict__ Blo,
                   const float* __restrict__ b0, const float* __restrict__ b1,
                   const float* __restrict__ b2,
                   float* __restrict__ C0, float* __restrict__ C1, float* __restrict__ C2,
                   __nv_bfloat16* __restrict__ Chi, __nv_bfloat16* __restrict__ Clo,
                   int M, int N, int K, int relu, int mode, int split3)
{
    extern __shared__ uint32_t sm[];
    int tid  = threadIdx.x;
    int brow = blockIdx.y * 128;
    int bcol = blockIdx.x * 128;
    int w = tid >> 5, lane = tid & 31;
    int gid = lane >> 2, tig = lane & 3;
    int moff = (w >> 1) * 32, noff = (w & 1) * 64;
    uint32_t smb = smem_u32(sm);

    // per-lane ldmatrix byte offsets within a plane
    int mat = lane >> 3, r8 = lane & 7;
    uint32_t aoff[2], boff[4];
    #pragma unroll
    for (int mt = 0; mt < 2; mt++) {
        int row = moff + mt * 16 + (mat & 1) * 8 + r8;
        aoff[mt] = (uint32_t)(row * RSU + (mat >> 1) * 4) * 4;
    }
    #pragma unroll
    for (int p = 0; p < 4; p++) {
        int row = noff + p * 16 + (mat >> 1) * 8 + r8;
        boff[p] = (uint32_t)(row * RSU + (mat & 1) * 4) * 4;
    }

    auto load_chunk = [&](int c, int buf) {
        int k0 = c * 32;
        uint32_t sb = smb + (uint32_t)buf * (BUFU * 4);
        #pragma unroll
        for (int i = 0; i < 8; i++) {
            int e  = tid + i * 256;
            int pl = e >> 9;
            int r  = (e >> 2) & 127;
            int s  = e & 3;
            const __nv_bfloat16* src;
            if      (pl == 0) src = Ahi + (size_t)(brow + r) * K + k0 + s * 8;
            else if (pl == 1) src = Alo + (size_t)(brow + r) * K + k0 + s * 8;
            else if (pl == 2) src = Bhi + (size_t)(bcol + r) * K + k0 + s * 8;
            else              src = Blo + (size_t)(bcol + r) * K + k0 + s * 8;
            uint32_t dst = sb + (uint32_t)(pl * PLANE + r * RSU + s * 4) * 4;
            asm volatile("cp.async.cg.shared.global [%0], [%1], 16;" :: "r"(dst), "l"(src));
        }
        asm volatile("cp.async.commit_group;" ::: "memory");
    };

    float acc[2][8][4] = {};
    const int NC = K >> 5;
    load_chunk(0, 0);

    for (int c = 0; c < NC; c++) {
        if (c + 1 < NC) {
            load_chunk(c + 1, (c + 1) & 1);
            asm volatile("cp.async.wait_group 1;" ::: "memory");
        } else {
            asm volatile("cp.async.wait_group 0;" ::: "memory");
        }
        __syncthreads();
        uint32_t bb = smb + (uint32_t)(c & 1) * (BUFU * 4);
        uint32_t Ahb = bb, Alb = bb + PLANE * 4, Bhb = bb + 2 * PLANE * 4, Blb = bb + 3 * PLANE * 4;

        #pragma unroll
        for (int ks = 0; ks < 2; ks++) {
            uint32_t ka = ks * 32;
            uint32_t afh[2][4], afl[2][4];
            #pragma unroll
            for (int mt = 0; mt < 2; mt++) {
                LDM4(afh[mt], Ahb + aoff[mt] + ka);
                LDM4(afl[mt], Alb + aoff[mt] + ka);
            }
            // B fragments loaded per-p to cut register pressure
            #pragma unroll
            for (int p = 0; p < 4; p++) {
                uint32_t bfh[4], bfl[4];
                LDM4(bfh, Bhb + boff[p] + ka);
                LDM4(bfl, Blb + boff[p] + ka);
                #pragma unroll
                for (int mt = 0; mt < 2; mt++)
                    #pragma unroll
                    for (int hf = 0; hf < 2; hf++) {
                        int nt = p * 2 + hf;
                        MMA_BF16(acc[mt][nt], afh[mt], &bfh[hf * 2]);
                        MMA_BF16(acc[mt][nt], afh[mt], &bfl[hf * 2]);
                        MMA_BF16(acc[mt][nt], afl[mt], &bfh[hf * 2]);
                    }
            }
        }
        __syncthreads();
    }

    // epilogue: pick output target
    float* Cf; const float* bp_; int cb, Nst;
    if (split3) {
        int mi = bcol >> 8;
        Cf  = (mi == 0) ? C0 : (mi == 1 ? C1 : C2);
        bp_ = (mi == 0) ? b0 : (mi == 1 ? b1 : b2);
        cb = bcol & 255; Nst = 256;
    } else {
        Cf = C0; bp_ = b0; cb = bcol; Nst = N;
    }

    #pragma unroll
    for (int mt = 0; mt < 2; mt++) {
        int r0 = brow + moff + mt * 16 + gid;
        #pragma unroll
        for (int nt = 0; nt < 8; nt++) {
            int c = cb + noff + nt * 8 + tig * 2;
            float bb0 = bp_[c], bb1 = bp_[c + 1];
            float2 o0 = make_float2(acc[mt][nt][0] + bb0, acc[mt][nt][1] + bb1);
            float2 o1 = make_float2(acc[mt][nt][2] + bb0, acc[mt][nt][3] + bb1);
            if (relu) {
                o0.x = fmaxf(o0.x, 0.f); o0.y = fmaxf(o0.y, 0.f);
                o1.x = fmaxf(o1.x, 0.f); o1.y = fmaxf(o1.y, 0.f);
            }
            size_t i0 = (size_t)r0 * Nst + c;
            size_t i1 = (size_t)(r0 + 8) * Nst + c;
            if (mode & 1) {
                *(float2*)(Cf + i0) = o0;
                *(float2*)(Cf + i1) = o1;
            }
            if (mode & 2) {
                uint32_t h0, l0, h1, l1;
                split2(o0.x, o0.y, h0, l0);
                split2(o1.x, o1.y, h1, l1);
                *(uint32_t*)(Chi + i0) = h0; *(uint32_t*)(Clo + i0) = l0;
                *(uint32_t*)(Chi + i1) = h1; *(uint32_t*)(Clo + i1) = l1;
            }
        }
    }
}

// ---------------- batched transpose+split of ALL weights (one launch) -------------
__global__ void transpose_all_kernel(const float* __restrict__ w_in,
                                     const float* __restrict__ wq, const float* __restrict__ wk,
                                     const float* __restrict__ wv, const float* __restrict__ wo,
                                     const float* __restrict__ f1, const float* __restrict__ f2,
                                     __nv_bfloat16* __restrict__ hi, __nv_bfloat16* __restrict__ lo)
{
    const int start[14] = {0, 8, 72, 136, 200, 264, 520, 776, 840, 904, 968, 1032, 1288, 1544};
    int t = blockIdx.x;
    int m = 0;
    #pragma unroll
    for (int i = 1; i < 14; i++) if (t >= start[i]) m = i;
    int layer = (m >= 7) ? 1 : 0;
    int mi = (m == 0) ? 0 : ((m - 1) % 6) + 1;
    const float* src; int K, N; size_t dst;
    size_t base = (size_t)FIN * D + (size_t)layer * LYR_SZ;
    switch (mi) {
        case 0: src = w_in;                          K = FIN; N = D;   dst = 0;             break;
        case 1: src = wq + (size_t)layer * D * D;    K = D;   N = D;   dst = base;          break;
        case 2: src = wk + (size_t)layer * D * D;    K = D;   N = D;   dst = base + 65536;  break;
        case 3: src = wv + (size_t)layer * D * D;    K = D;   N = D;   dst = base + 131072; break;
        case 4: src = wo + (size_t)layer * D * D;    K = D;   N = D;   dst = base + 196608; break;
        case 5: src = f1 + (size_t)layer * D * DFF;  K = D;   N = DFF; dst = base + 262144; break;
        default:src = f2 + (size_t)layer * DFF * D;  K = DFF; N = D;   dst = base + 524288; break;
    }
    int lt = t - start[m];
    int ntn = N >> 5;
    int nb = (lt % ntn) << 5, kb = (lt / ntn) << 5;

    __shared__ float tbuf[32][33];
    int tx = threadIdx.x, ty = threadIdx.y;
    #pragma unroll
    for (int i = ty; i < 32; i += 8)
        tbuf[i][tx] = src[(size_t)(kb + i) * N + nb + tx];
    __syncthreads();
    #pragma unroll
    for (int i = ty; i < 32; i += 8) {
        float v = tbuf[tx][i];
        size_t o = dst + (size_t)(nb + i) * K + kb + tx;
        split_scalar(v, hi + o, lo + o);
    }
}

// ---------------- plain split: fp32 -> hi/lo bf16 ---------------------------------
__global__ void split_kernel(const float* __restrict__ in,
                             __nv_bfloat16* __restrict__ hi,
                             __nv_bfloat16* __restrict__ lo, int n)
{
    int i = (blockIdx.x * blockDim.x + threadIdx.x) * 2;
    if (i >= n) return;
    float2 v = *(const float2*)(in + i);
    uint32_t h, l;
    split2(v.x, v.y, h, l);
    *(uint32_t*)(hi + i) = h;
    *(uint32_t*)(lo + i) = l;
}

// ---------------- sampled QK -> M score ------------------------------------------
__global__ void qk_sample_kernel(const float* __restrict__ q, const float* __restrict__ k,
                                 const int* __restrict__ idx, float* __restrict__ Mout)
{
    int gw   = (blockIdx.x * blockDim.x + threadIdx.x) >> 5;
    int lane = threadIdx.x & 31;
    if (gw >= B_ * H_ * L_) return;
    int l  = gw & (L_ - 1);
    int bh = gw >> 11;
    int b  = bh >> 3, h = bh & 7;

    float qd = q[((size_t)b * L_ + l) * D + h * DH + lane];
    const float* kbase = k + (size_t)b * L_ * D + h * DH;
    const int*   irow  = idx + l * S_;

    float mx = -1e30f, sm = 0.0f;
    for (int s = 0; s < S_; s++) {
        int   ki = __ldg(&irow[s]);
        float p  = qd * __ldg(&kbase[(size_t)ki * D + lane]);
        #pragma unroll
        for (int off = 16; off; off >>= 1) p += __shfl_xor_sync(0xffffffffu, p, off);
        mx = fmaxf(mx, p);
        sm += p;
    }
    if (lane == 0) Mout[gw] = mx - sm * (1.0f / (float)L_);
}

// ---------------- top-40 per (b,h): shuffle argmax, 2 barriers/round ---------------
__global__ void topk_kernel(const float* __restrict__ Mv, int* __restrict__ top)
{
    int bh  = blockIdx.x;
    int tid = threadIdx.x;
    int w = tid >> 5, lane = tid & 31;
    __shared__ float sv[L_];
    __shared__ float wv_[8];
    __shared__ int   wi_[8];
    for (int i = tid; i < L_; i += 256) sv[i] = Mv[(size_t)bh * L_ + i];
    __syncthreads();

    for (int r = 0; r < U_; r++) {
        float bv = -1e30f; int bi = 0x7fffffff;
        #pragma unroll
        for (int j = 0; j < 8; j++) {
            int i = tid + j * 256;
            float v = sv[i];
            if (v > bv || (v == bv && i < bi)) { bv = v; bi = i; }
        }
        #pragma unroll
        for (int o = 16; o; o >>= 1) {
            float ov = __shfl_xor_sync(0xffffffffu, bv, o);
            int   oi = __shfl_xor_sync(0xffffffffu, bi, o);
            if (ov > bv || (ov == bv && oi < bi)) { bv = ov; bi = oi; }
        }
        if (lane == 0) { wv_[w] = bv; wi_[w] = bi; }
        __syncthreads();
        if (tid == 0) {
            float fv = wv_[0]; int fi = wi_[0];
            #pragma unroll
            for (int j = 1; j < 8; j++) {
                float ov = wv_[j]; int oi = wi_[j];
                if (ov > fv || (ov == fv && oi < fi)) { fv = ov; fi = oi; }
            }
            top[bh * U_ + r] = fi;
            sv[fi] = -1e30f;
        }
        __syncthreads();
    }
}

// ---------------- v mean over L per (b,h) -----------------------------------------
__global__ void vmean_kernel(const float* __restrict__ v, float* __restrict__ vm)
{
    int bh = blockIdx.x; int b = bh >> 3, h = bh & 7;
    int tid = threadIdx.x;
    int d = tid & 31, seg = tid >> 5;
    const float* vb = v + (size_t)b * L_ * D + h * DH + d;
    float acc = 0.0f;
    for (int l = seg; l < L_; l += 8) acc += vb[(size_t)l * D];
    __shared__ float sp[8][32];
    sp[seg][d] = acc;
    __syncthreads();
    if (tid < 32) {
        float s = 0.0f;
        #pragma unroll
        for (int i = 0; i < 8; i++) s += sp[i][tid];
        vm[bh * DH + tid] = s * (1.0f / (float)L_);
    }
}

// ---------------- fill ctx planes with broadcast v-mean ---------------------------
__global__ void ctxfill_kernel(const float* __restrict__ vm,
                               __nv_bfloat16* __restrict__ chi,
                               __nv_bfloat16* __restrict__ clo)
{
    int i = blockIdx.x * blockDim.x + threadIdx.x;
    if (i >= B_ * L_ * D) return;
    int dfull = i & (D - 1);
    int b = i / (L_ * D);
    int h = dfull >> 5, d = dfull & 31;
    float v = vm[((b << 3) + h) * DH + d];
    split_scalar(v, chi + i, clo + i);
}

// ---------------- flash-style reduced attention: one block per (b,h) --------------
__global__ __launch_bounds__(256, 1)
void attn_topq_flash(const float* __restrict__ q, const float* __restrict__ k,
                     const float* __restrict__ v, const int* __restrict__ top,
                     __nv_bfloat16* __restrict__ chi, __nv_bfloat16* __restrict__ clo)
{
    __shared__ float Ks[128][33];
    __shared__ float Vs[128][33];
    __shared__ float qs[40][32];
    __shared__ float ps[8][128];
    __shared__ int   stop[40];

    int bh = blockIdx.x; int b = bh >> 3, h = bh & 7;
    int tid = threadIdx.x, w = tid >> 5, lane = tid & 31;

    if (tid < 40) stop[tid] = top[bh * U_ + tid];
    __syncthreads();
    for (int i = tid; i < 40 * 32; i += 256) {
        int u = i >> 5, d = i & 31;
        qs[u][d] = q[((size_t)b * L_ + stop[u]) * D + h * DH + d];
    }

    float m[5], l[5], acc[5];
    #pragma unroll
    for (int j = 0; j < 5; j++) { m[j] = -1e30f; l[j] = 0.f; acc[j] = 0.f; }
    const float scale = 0.1767766952966369f;
    const float* kb = k + (size_t)b * L_ * D + h * DH;
    const float* vb = v + (size_t)b * L_ * D + h * DH;
    __syncthreads();

    for (int t0 = 0; t0 < L_; t0 += 128) {
        for (int i = tid; i < 128 * 32; i += 256) {
            int r = i >> 5, d = i & 31;
            Ks[r][d] = kb[(size_t)(t0 + r) * D + d];
            Vs[r][d] = vb[(size_t)(t0 + r) * D + d];
        }
        __syncthreads();

        float sj[5][4];
        #pragma unroll
        for (int j = 0; j < 5; j++)
            #pragma unroll
            for (int i = 0; i < 4; i++) sj[j][i] = 0.f;
        #pragma unroll
        for (int d = 0; d < 32; d++) {
            float k0v = Ks[lane][d], k1v = Ks[lane + 32][d];
            float k2v = Ks[lane + 64][d], k3v = Ks[lane + 96][d];
            #pragma unroll
            for (int j = 0; j < 5; j++) {
                float qd = qs[w * 5 + j][d];
                sj[j][0] = fmaf(qd, k0v, sj[j][0]);
                sj[j][1] = fmaf(qd, k1v, sj[j][1]);
                sj[j][2] = fmaf(qd, k2v, sj[j][2]);
                sj[j][3] = fmaf(qd, k3v, sj[j][3]);
            }
        }
        #pragma unroll
        for (int j = 0; j < 5; j++) {
            float s0 = sj[j][0] * scale, s1 = sj[j][1] * scale;
            float s2 = sj[j][2] * scale, s3 = sj[j][3] * scale;
            float tm = fmaxf(fmaxf(s0, s1), fmaxf(s2, s3));
            #pragma unroll
            for (int o = 16; o; o >>= 1) tm = fmaxf(tm, __shfl_xor_sync(0xffffffffu, tm, o));
            float mn   = fmaxf(m[j], tm);
            float corr = __expf(m[j] - mn);
            float p0 = __expf(s0 - mn), p1 = __expf(s1 - mn);
            float p2 = __expf(s2 - mn), p3 = __expf(s3 - mn);
            float psum = p0 + p1 + p2 + p3;
            #pragma unroll
            for (int o = 16; o; o >>= 1) psum += __shfl_xor_sync(0xffffffffu, psum, o);
            l[j] = l[j] * corr + psum;
            m[j] = mn;
            ps[w][lane] = p0; ps[w][lane + 32] = p1; ps[w][lane + 64] = p2; ps[w][lane + 96] = p3;
            __syncwarp();
            float aa = acc[j] * corr;
            const float4* pv4 = (const float4*)ps[w];
            #pragma unroll 8
            for (int kk4 = 0; kk4 < 32; kk4++) {
                float4 p4 = pv4[kk4];
                int kk = kk4 * 4;
                aa = fmaf(p4.x, Vs[kk][lane],     aa);
                aa = fmaf(p4.y, Vs[kk + 1][lane], aa);
                aa = fmaf(p4.z, Vs[kk + 2][lane], aa);
                aa = fmaf(p4.w, Vs[kk + 3][lane], aa);
            }
            acc[j] = aa;
            __syncwarp();
        }
        __syncthreads();
    }
    #pragma unroll
    for (int j = 0; j < 5; j++) {
        int u = w * 5 + j;
        float o = acc[j] / l[j];
        size_t off = ((size_t)b * L_ + stop[u]) * D + h * DH + lane;
        split_scalar(o, chi + off, clo + off);
    }
}

// ---------------- residual add + LayerNorm + split (shuffle reductions) -----------
__global__ void add_ln_kernel(float* __restrict__ h, const float* __restrict__ r,
                              const float* __restrict__ g, const float* __restrict__ bb,
                              __nv_bfloat16* __restrict__ hhi, __nv_bfloat16* __restrict__ hlo)
{
    int row = blockIdx.x;
    int tid = threadIdx.x;
    int w = tid >> 5, lane = tid & 31;
    size_t off = (size_t)row * D + tid;
    float val = h[off] + r[off];
    float s1 = val, s2 = val * val;
    #pragma unroll
    for (int o = 16; o; o >>= 1) {
        s1 += __shfl_xor_sync(0xffffffffu, s1, o);
        s2 += __shfl_xor_sync(0xffffffffu, s2, o);
    }
    __shared__ float a1[8], a2[8];
    __shared__ float mu_s, rv_s;
    if (lane == 0) { a1[w] = s1; a2[w] = s2; }
    __syncthreads();
    if (w == 0) {
        float t1 = (lane < 8) ? a1[lane] : 0.f;
        float t2 = (lane < 8) ? a2[lane] : 0.f;
        #pragma unroll
        for (int o = 4; o; o >>= 1) {
            t1 += __shfl_xor_sync(0xffffffffu, t1, o);
            t2 += __shfl_xor_sync(0xffffffffu, t2, o);
        }
        if (lane == 0) {
            float mu = t1 * (1.0f / (float)D);
            float var = t2 * (1.0f / (float)D) - mu * mu;
            mu_s = mu;
            rv_s = rsqrtf(var + 1e-5f);
        }
    }
    __syncthreads();
    float o = (val - mu_s) * rv_s * g[tid] + bb[tid];
    h[off] = o;
    split_scalar(o, hhi + off, hlo + off);
}

// ---------------- final MLP head ---------------------------------------------------
__global__ void head_kernel(const float* __restrict__ h, const float* __restrict__ w1,
                            const float* __restrict__ b1, const float* __restrict__ w2,
                            const float* __restrict__ b2, float* __restrict__ out)
{
    int b = blockIdx.x;
    int j = threadIdx.x;
    const float* last = h + ((size_t)b * L_ + (L_ - 1)) * D;
    float acc = b1[j];
    for (int d = 0; d < D; d++) acc = fmaf(last[d], w1[d * 64 + j], acc);
    acc = fmaxf(acc, 0.0f) * w2[j];
    __shared__ float s[64];
    s[j] = acc; __syncthreads();
    for (int st = 32; st; st >>= 1) { if (j < st) s[j] += s[j + st]; __syncthreads(); }
    if (j == 0) out[b] = s[0] + b2[0];
}

// ===================================================================================
extern "C" void kernel_launch(void* const* d_in, const int* in_sizes, int n_in,
                              void* d_out, int out_size)
{
    const float* x     = (const float*)d_in[0];
    const int*   idx   = (const int*)  d_in[1];
    const float* w_in  = (const float*)d_in[2];
    const float* b_in  = (const float*)d_in[3];
    const float* wq    = (const float*)d_in[4];
    const float* bq    = (const float*)d_in[5];
    const float* wk    = (const float*)d_in[6];
    const float* bk    = (const float*)d_in[7];
    const float* wv    = (const float*)d_in[8];
    const float* bv    = (const float*)d_in[9];
    const float* wo    = (const float*)d_in[10];
    const float* bo    = (const float*)d_in[11];
    const float* w_ff1 = (const float*)d_in[12];
    const float* b_ff1 = (const float*)d_in[13];
    const float* w_ff2 = (const float*)d_in[14];
    const float* b_ff2 = (const float*)d_in[15];
    const float* ln1_g = (const float*)d_in[16];
    const float* ln1_b = (const float*)d_in[17];
    const float* ln2_g = (const float*)d_in[18];
    const float* ln2_b = (const float*)d_in[19];
    const float* w_fc1 = (const float*)d_in[20];
    const float* b_fc1 = (const float*)d_in[21];
    const float* w_fc2 = (const float*)d_in[22];
    const float* b_fc2 = (const float*)d_in[23];
    float* out = (float*)d_out;

    float *h, *q, *k, *v, *nx, *Mv, *vm; int* top;
    __nv_bfloat16 *xhi, *xlo, *hhi, *hlo, *chi, *clo, *fhi, *flo, *whi, *wlo;
    cudaGetSymbolAddress((void**)&h,   g_h);
    cudaGetSymbolAddress((void**)&q,   g_q);
    cudaGetSymbolAddress((void**)&k,   g_k);
    cudaGetSymbolAddress((void**)&v,   g_v);
    cudaGetSymbolAddress((void**)&nx,  g_nx);
    cudaGetSymbolAddress((void**)&Mv,  g_M);
    cudaGetSymbolAddress((void**)&top, g_top);
    cudaGetSymbolAddress((void**)&vm,  g_vm);
    cudaGetSymbolAddress((void**)&xhi, g_x_hi);  cudaGetSymbolAddress((void**)&xlo, g_x_lo);
    cudaGetSymbolAddress((void**)&hhi, g_h_hi);  cudaGetSymbolAddress((void**)&hlo, g_h_lo);
    cudaGetSymbolAddress((void**)&chi, g_ctx_hi); cudaGetSymbolAddress((void**)&clo, g_ctx_lo);
    cudaGetSymbolAddress((void**)&fhi, g_ff_hi); cudaGetSymbolAddress((void**)&flo, g_ff_lo);
    cudaGetSymbolAddress((void**)&whi, g_wt_hi); cudaGetSymbolAddress((void**)&wlo, g_wt_lo);

    cudaFuncSetAttribute(mma_gemm_bf16, cudaFuncAttributeMaxDynamicSharedMemorySize, GEMM_SMEM_V2);

    const int Mrows = B_ * L_;                     // 16384
    dim3 gD  (D / 128,   Mrows / 128);
    dim3 gQKV(3 * D / 128, Mrows / 128);
    dim3 gFF (DFF / 128, Mrows / 128);
    dim3 tb(32, 8);

    const size_t o_in = 0;
    auto o_q  = [&](int l){ return (size_t)FIN * D + (size_t)l * LYR_SZ; };
    auto o_o  = [&](int l){ return o_q(l) + 196608; };
    auto o_f1 = [&](int l){ return o_q(l) + 262144; };
    auto o_f2 = [&](int l){ return o_q(l) + 524288; };

    split_kernel<<<(B_ * L_ * FIN) / 512, 256>>>(x, xhi, xlo, B_ * L_ * FIN);
    transpose_all_kernel<<<1544, tb>>>(w_in, wq, wk, wv, wo, w_ff1, w_ff2, whi, wlo);
    mma_gemm_bf16<<<gD, 256, GEMM_SMEM_V2>>>(xhi, xlo, whi + o_in, wlo + o_in,
        b_in, nullptr, nullptr, h, nullptr, nullptr, hhi, hlo, Mrows, D, FIN, 0, 3, 0);

    for (int layer = 0; layer < NL; layer++) {
        const int* ixL = idx + (size_t)layer * L_ * S_;

        mma_gemm_bf16<<<gQKV, 256, GEMM_SMEM_V2>>>(hhi, hlo, whi + o_q(layer), wlo + o_q(layer),
            bq + layer * D, bk + layer * D, bv + layer * D,
            q, k, v, nullptr, nullptr, Mrows, 768, D, 0, 1, 1);

        qk_sample_kernel<<<(B_ * H_ * L_ * 32) / 256, 256>>>(q, k, ixL, Mv);
        topk_kernel<<<B_ * H_, 256>>>(Mv, top);
        vmean_kernel<<<B_ * H_, 256>>>(v, vm);
        ctxfill_kernel<<<(B_ * L_ * D) / 256, 256>>>(vm, chi, clo);
        attn_topq_flash<<<B_ * H_, 256>>>(q, k, v, top, chi, clo);

        mma_gemm_bf16<<<gD, 256, GEMM_SMEM_V2>>>(chi, clo, whi + o_o(layer), wlo + o_o(layer),
            bo + layer * D, nullptr, nullptr, nx, nullptr, nullptr, nullptr, nullptr,
            Mrows, D, D, 0, 1, 0);
        add_ln_kernel<<<Mrows, 256>>>(h, nx, ln1_g + layer * D, ln1_b + layer * D, hhi, hlo);

        mma_gemm_bf16<<<gFF, 256, GEMM_SMEM_V2>>>(hhi, hlo, whi + o_f1(layer), wlo + o_f1(layer),
            b_ff1 + layer * DFF, nullptr, nullptr, nullptr, nullptr, nullptr, fhi, flo,
            Mrows, DFF, D, 1, 2, 0);
        mma_gemm_bf16<<<gD, 256, GEMM_SMEM_V2>>>(fhi, flo, whi + o_f2(layer), wlo + o_f2(layer),
            b_ff2 + layer * D, nullptr, nullptr, nx, nullptr, nullptr, nullptr, nullptr,
            Mrows, D, DFF, 0, 1, 0);
        add_ln_kernel<<<Mrows, 256>>>(h, nx, ln2_g + layer * D, ln2_b + layer * D, hhi, hlo);
    }

    head_kernel<<<B_, 64>>>(h, w_fc1, b_fc1, w_fc2, b_fc2, out);
}

// round 7
// speedup vs baseline: 2.8601x; 1.2136x over previous
#include <cuda_runtime.h>
#include <cuda_bf16.h>
#include <cstdint>
#include <math.h>

// Problem constants
#define B_   8
#define L_   2048
#define FIN  32
#define D    256
#define H_   8
#define DH   32
#define DFF  1024
#define S_   40
#define U_   40
#define NL   2

// ---------------- scratch (device globals; no allocation allowed) ----------------
__device__ float g_h  [B_*L_*D];
__device__ float g_q  [B_*L_*D];
__device__ float g_k  [B_*L_*D];
__device__ float g_v  [B_*L_*D];
__device__ float g_nx [B_*L_*D];
__device__ float g_M  [B_*H_*L_];
__device__ int   g_top[B_*H_*U_];
__device__ float g_vm [B_*H_*DH];

// bf16 hi/lo planes
__device__ __nv_bfloat16 g_x_hi [B_*L_*FIN], g_x_lo [B_*L_*FIN];
__device__ __nv_bfloat16 g_h_hi [B_*L_*D],   g_h_lo [B_*L_*D];
__device__ __nv_bfloat16 g_ctx_hi[B_*L_*D],  g_ctx_lo[B_*L_*D];
__device__ __nv_bfloat16 g_ff_hi[B_*L_*DFF], g_ff_lo[B_*L_*DFF];
#define LYR_SZ   786432
#define WT_TOTAL (FIN*D + NL*LYR_SZ)
__device__ __nv_bfloat16 g_wt_hi[WT_TOTAL], g_wt_lo[WT_TOTAL];

// =========================== helpers ===============================================
__device__ __forceinline__ uint32_t smem_u32(const void* p) {
    uint32_t a;
    asm("{ .reg .u64 t; cvta.to.shared.u64 t, %1; cvt.u32.u64 %0, t; }" : "=r"(a) : "l"(p));
    return a;
}
__device__ __forceinline__ void split2(float x, float y, uint32_t& hi, uint32_t& lo) {
    __nv_bfloat162 h = __float22bfloat162_rn(make_float2(x, y));
    float2 hf = __bfloat1622float2(h);
    __nv_bfloat162 l = __float22bfloat162_rn(make_float2(x - hf.x, y - hf.y));
    hi = *(uint32_t*)&h; lo = *(uint32_t*)&l;
}
__device__ __forceinline__ void split_scalar(float v, __nv_bfloat16* hp, __nv_bfloat16* lp) {
    __nv_bfloat16 hb = __float2bfloat16(v);
    *hp = hb;
    *lp = __float2bfloat16(v - __bfloat162float(hb));
}

#define MMA_BF16(c, a, b)                                                        \
    asm volatile("mma.sync.aligned.m16n8k16.row.col.f32.bf16.bf16.f32 "          \
        "{%0,%1,%2,%3}, {%4,%5,%6,%7}, {%8,%9}, {%0,%1,%2,%3};"                  \
        : "+f"((c)[0]), "+f"((c)[1]), "+f"((c)[2]), "+f"((c)[3])                  \
        : "r"((a)[0]), "r"((a)[1]), "r"((a)[2]), "r"((a)[3]),                     \
          "r"((b)[0]), "r"((b)[1]))

#define LDM4(r, addr)                                                            \
    asm volatile("ldmatrix.sync.aligned.m8n8.x4.shared.b16 {%0,%1,%2,%3}, [%4];" \
        : "=r"((r)[0]), "=r"((r)[1]), "=r"((r)[2]), "=r"((r)[3]) : "r"(addr))

// =================== 3-stage pipelined bf16x3 GEMM, swizzled smem ==================
// plane layout: [128 rows][16 uint32] (64B rows), swizzle u' = u ^ ((r>>1)&3)
#define PLANE_U 2048              // uint32 per plane (128*16)
#define STAGE_U (4*PLANE_U)       // 4 planes per stage
#define STAGE_B (STAGE_U*4)       // 32768 bytes
#define GEMM_SMEM_V3 (3*STAGE_B)  // 98304 bytes

__global__ __launch_bounds__(256, 2)
void mma_gemm_bf16(const __nv_bfloat16* __restrict__ Ahi, const __nv_bfloat16* __restrict__ Alo,
                   const __nv_bfloat16* __restrict__ Bhi, const __nv_bfloat16* __restrict__ Blo,
                   const float* __restrict__ b0, const float* __restrict__ b1,
                   const float* __restrict__ b2,
                   float* __restrict__ C0, float* __restrict__ C1, float* __restrict__ C2,
                   __nv_bfloat16* __restrict__ Chi, __nv_bfloat16* __restrict__ Clo,
                   int M, int N, int K, int relu, int mode, int split3)
{
    extern __shared__ uint32_t sm[];
    int tid  = threadIdx.x;
    int brow = blockIdx.y * 128;
    int bcol = blockIdx.x * 128;
    int w = tid >> 5, lane = tid & 31;
    int gid = lane >> 2, tig = lane & 3;
    int moff = (w >> 1) * 32, noff = (w & 1) * 64;
    uint32_t smb = smem_u32(sm);

    // ldmatrix byte offsets within a plane: [mt or p][ks]
    int mat = lane >> 3, r8 = lane & 7;
    uint32_t aoffk[2][2], boffk[4][2];
    #pragma unroll
    for (int mt = 0; mt < 2; mt++) {
        int row = moff + mt * 16 + (mat & 1) * 8 + r8;
        int sw = (row >> 1) & 3;
        #pragma unroll
        for (int ks = 0; ks < 2; ks++) {
            int u = ks * 2 + (mat >> 1);
            aoffk[mt][ks] = (uint32_t)(row * 16 + ((u ^ sw) << 2)) * 4;
        }
    }
    #pragma unroll
    for (int p = 0; p < 4; p++) {
        int row = noff + p * 16 + (mat >> 1) * 8 + r8;
        int sw = (row >> 1) & 3;
        #pragma unroll
        for (int ks = 0; ks < 2; ks++) {
            int u = ks * 2 + (mat & 1);
            boffk[p][ks] = (uint32_t)(row * 16 + ((u ^ sw) << 2)) * 4;
        }
    }

    auto load_chunk = [&](int c, int stage) {
        int k0 = c * 32;
        uint32_t sb = smb + (uint32_t)stage * STAGE_B;
        #pragma unroll
        for (int i = 0; i < 8; i++) {
            int e  = tid + i * 256;
            int pl = e >> 9;
            int r  = (e >> 2) & 127;
            int s  = e & 3;
            const __nv_bfloat16* src;
            if      (pl == 0) src = Ahi + (size_t)(brow + r) * K + k0 + s * 8;
            else if (pl == 1) src = Alo + (size_t)(brow + r) * K + k0 + s * 8;
            else if (pl == 2) src = Bhi + (size_t)(bcol + r) * K + k0 + s * 8;
            else              src = Blo + (size_t)(bcol + r) * K + k0 + s * 8;
            uint32_t off_u = (uint32_t)(pl * PLANE_U + r * 16 + ((s ^ ((r >> 1) & 3)) << 2));
            asm volatile("cp.async.cg.shared.global [%0], [%1], 16;"
                         :: "r"(smb + (uint32_t)stage * STAGE_B - smb + sb - sb + (off_u * 4) + (uint32_t)stage * 0 + (sb - smb) * 0 + smb * 0 + sb + off_u * 4 - sb), "l"(src));
        }
        asm volatile("cp.async.commit_group;" ::: "memory");
    };
    // NOTE: the expression above must be just sb + off_u*4; rewritten below.

    float acc[2][8][4] = {};
    const int NC = K >> 5;

    // prologue: stages 0 and 1
    {
        int k0 = 0;
        #pragma unroll
        for (int st = 0; st < 2; st++) {
            if (st < NC) {
                uint32_t sb = smb + (uint32_t)st * STAGE_B;
                k0 = st * 32;
                #pragma unroll
                for (int i = 0; i < 8; i++) {
                    int e  = tid + i * 256;
                    int pl = e >> 9;
                    int r  = (e >> 2) & 127;
                    int s  = e & 3;
                    const __nv_bfloat16* src;
                    if      (pl == 0) src = Ahi + (size_t)(brow + r) * K + k0 + s * 8;
                    else if (pl == 1) src = Alo + (size_t)(brow + r) * K + k0 + s * 8;
                    else if (pl == 2) src = Bhi + (size_t)(bcol + r) * K + k0 + s * 8;
                    else              src = Blo + (size_t)(bcol + r) * K + k0 + s * 8;
                    uint32_t dst = sb + (uint32_t)(pl * PLANE_U + r * 16 + ((s ^ ((r >> 1) & 3)) << 2)) * 4;
                    asm volatile("cp.async.cg.shared.global [%0], [%1], 16;" :: "r"(dst), "l"(src));
                }
                asm volatile("cp.async.commit_group;" ::: "memory");
            }
        }
    }

    int stage_c = 0;   // stage of chunk c
    for (int c = 0; c < NC; c++) {
        if (c + 1 < NC) {
            asm volatile("cp.async.wait_group 1;" ::: "memory");
        } else {
            asm volatile("cp.async.wait_group 0;" ::: "memory");
        }
        __syncthreads();

        // issue load for chunk c+2 into stage (c+2)%3 (that stage was read at iter c-1)
        if (c + 2 < NC) {
            int stage_n = stage_c + 2; if (stage_n >= 3) stage_n -= 3;
            uint32_t sb = smb + (uint32_t)stage_n * STAGE_B;
            int k0 = (c + 2) * 32;
            #pragma unroll
            for (int i = 0; i < 8; i++) {
                int e  = tid + i * 256;
                int pl = e >> 9;
                int r  = (e >> 2) & 127;
                int s  = e & 3;
                const __nv_bfloat16* src;
                if      (pl == 0) src = Ahi + (size_t)(brow + r) * K + k0 + s * 8;
                else if (pl == 1) src = Alo + (size_t)(brow + r) * K + k0 + s * 8;
                else if (pl == 2) src = Bhi + (size_t)(bcol + r) * K + k0 + s * 8;
                else              src = Blo + (size_t)(bcol + r) * K + k0 + s * 8;
                uint32_t dst = sb + (uint32_t)(pl * PLANE_U + r * 16 + ((s ^ ((r >> 1) & 3)) << 2)) * 4;
                asm volatile("cp.async.cg.shared.global [%0], [%1], 16;" :: "r"(dst), "l"(src));
            }
            asm volatile("cp.async.commit_group;" ::: "memory");
        }

        uint32_t bb = smb + (uint32_t)stage_c * STAGE_B;
        uint32_t Ahb = bb, Alb = bb + PLANE_U * 4, Bhb = bb + 2 * PLANE_U * 4, Blb = bb + 3 * PLANE_U * 4;

        #pragma unroll
        for (int ks = 0; ks < 2; ks++) {
            uint32_t afh[2][4], afl[2][4];
            #pragma unroll
            for (int mt = 0; mt < 2; mt++) {
                LDM4(afh[mt], Ahb + aoffk[mt][ks]);
                LDM4(afl[mt], Alb + aoffk[mt][ks]);
            }
            #pragma unroll
            for (int p = 0; p < 4; p++) {
                uint32_t bfh[4], bfl[4];
                LDM4(bfh, Bhb + boffk[p][ks]);
                LDM4(bfl, Blb + boffk[p][ks]);
                #pragma unroll
                for (int mt = 0; mt < 2; mt++)
                    #pragma unroll
                    for (int hf = 0; hf < 2; hf++) {
                        int nt = p * 2 + hf;
                        MMA_BF16(acc[mt][nt], afh[mt], &bfh[hf * 2]);
                        MMA_BF16(acc[mt][nt], afh[mt], &bfl[hf * 2]);
                        MMA_BF16(acc[mt][nt], afl[mt], &bfh[hf * 2]);
                    }
            }
        }
        stage_c++; if (stage_c >= 3) stage_c = 0;
    }

    // epilogue: pick output target
    float* Cf; const float* bp_; int cb, Nst;
    if (split3) {
        int mi = bcol >> 8;
        Cf  = (mi == 0) ? C0 : (mi == 1 ? C1 : C2);
        bp_ = (mi == 0) ? b0 : (mi == 1 ? b1 : b2);
        cb = bcol & 255; Nst = 256;
    } else {
        Cf = C0; bp_ = b0; cb = bcol; Nst = N;
    }

    #pragma unroll
    for (int mt = 0; mt < 2; mt++) {
        int r0 = brow + moff + mt * 16 + gid;
        #pragma unroll
        for (int nt = 0; nt < 8; nt++) {
            int c = cb + noff + nt * 8 + tig * 2;
            float bb0 = bp_[c], bb1 = bp_[c + 1];
            float2 o0 = make_float2(acc[mt][nt][0] + bb0, acc[mt][nt][1] + bb1);
            float2 o1 = make_float2(acc[mt][nt][2] + bb0, acc[mt][nt][3] + bb1);
            if (relu) {
                o0.x = fmaxf(o0.x, 0.f); o0.y = fmaxf(o0.y, 0.f);
                o1.x = fmaxf(o1.x, 0.f); o1.y = fmaxf(o1.y, 0.f);
            }
            size_t i0 = (size_t)r0 * Nst + c;
            size_t i1 = (size_t)(r0 + 8) * Nst + c;
            if (mode & 1) {
                *(float2*)(Cf + i0) = o0;
                *(float2*)(Cf + i1) = o1;
            }
            if (mode & 2) {
                uint32_t h0, l0, h1, l1;
                split2(o0.x, o0.y, h0, l0);
                split2(o1.x, o1.y, h1, l1);
                *(uint32_t*)(Chi + i0) = h0; *(uint32_t*)(Clo + i0) = l0;
                *(uint32_t*)(Chi + i1) = h1; *(uint32_t*)(Clo + i1) = l1;
            }
        }
    }
}

// ---------------- batched transpose+split of ALL weights (one launch) -------------
__global__ void transpose_all_kernel(const float* __restrict__ w_in,
                                     const float* __restrict__ wq, const float* __restrict__ wk,
                                     const float* __restrict__ wv, const float* __restrict__ wo,
                                     const float* __restrict__ f1, const float* __restrict__ f2,
                                     __nv_bfloat16* __restrict__ hi, __nv_bfloat16* __restrict__ lo)
{
    const int start[14] = {0, 8, 72, 136, 200, 264, 520, 776, 840, 904, 968, 1032, 1288, 1544};
    int t = blockIdx.x;
    int m = 0;
    #pragma unroll
    for (int i = 1; i < 14; i++) if (t >= start[i]) m = i;
    int layer = (m >= 7) ? 1 : 0;
    int mi = (m == 0) ? 0 : ((m - 1) % 6) + 1;
    const float* src; int K, N; size_t dst;
    size_t base = (size_t)FIN * D + (size_t)layer * LYR_SZ;
    switch (mi) {
        case 0: src = w_in;                          K = FIN; N = D;   dst = 0;             break;
        case 1: src = wq + (size_t)layer * D * D;    K = D;   N = D;   dst = base;          break;
        case 2: src = wk + (size_t)layer * D * D;    K = D;   N = D;   dst = base + 65536;  break;
        case 3: src = wv + (size_t)layer * D * D;    K = D;   N = D;   dst = base + 131072; break;
        case 4: src = wo + (size_t)layer * D * D;    K = D;   N = D;   dst = base + 196608; break;
        case 5: src = f1 + (size_t)layer * D * DFF;  K = D;   N = DFF; dst = base + 262144; break;
        default:src = f2 + (size_t)layer * DFF * D;  K = DFF; N = D;   dst = base + 524288; break;
    }
    int lt = t - start[m];
    int ntn = N >> 5;
    int nb = (lt % ntn) << 5, kb = (lt / ntn) << 5;

    __shared__ float tbuf[32][33];
    int tx = threadIdx.x, ty = threadIdx.y;
    #pragma unroll
    for (int i = ty; i < 32; i += 8)
        tbuf[i][tx] = src[(size_t)(kb + i) * N + nb + tx];
    __syncthreads();
    #pragma unroll
    for (int i = ty; i < 32; i += 8) {
        float v = tbuf[tx][i];
        size_t o = dst + (size_t)(nb + i) * K + kb + tx;
        split_scalar(v, hi + o, lo + o);
    }
}

// ---------------- plain split: fp32 -> hi/lo bf16 ---------------------------------
__global__ void split_kernel(const float* __restrict__ in,
                             __nv_bfloat16* __restrict__ hi,
                             __nv_bfloat16* __restrict__ lo, int n)
{
    int i = (blockIdx.x * blockDim.x + threadIdx.x) * 2;
    if (i >= n) return;
    float2 v = *(const float2*)(in + i);
    uint32_t h, l;
    split2(v.x, v.y, h, l);
    *(uint32_t*)(hi + i) = h;
    *(uint32_t*)(lo + i) = l;
}

// ---------------- sampled QK -> M score (float2 half-warp form) -------------------
__global__ void qk_sample_kernel(const float* __restrict__ q, const float* __restrict__ k,
                                 const int* __restrict__ idx, float* __restrict__ Mout)
{
    int gw   = (blockIdx.x * blockDim.x + threadIdx.x) >> 5;
    int lane = threadIdx.x & 31;
    if (gw >= B_ * H_ * L_) return;
    int l  = gw & (L_ - 1);
    int bh = gw >> 11;
    int b  = bh >> 3, h = bh & 7;

    int d2 = lane & 15, sh = lane >> 4;
    float2 q2 = *(const float2*)(q + ((size_t)b * L_ + l) * D + h * DH + 2 * d2);
    const float* kbase = k + (size_t)b * L_ * D + h * DH;
    const int*   irow  = idx + l * S_;

    float mx = -1e30f, sm = 0.0f;
    #pragma unroll 4
    for (int s0 = 0; s0 < S_; s0 += 2) {
        int ki = __ldg(&irow[s0 + sh]);
        float2 kv = *(const float2*)(kbase + (size_t)ki * D + 2 * d2);
        float p = q2.x * kv.x + q2.y * kv.y;
        p += __shfl_xor_sync(0xffffffffu, p, 1);
        p += __shfl_xor_sync(0xffffffffu, p, 2);
        p += __shfl_xor_sync(0xffffffffu, p, 4);
        p += __shfl_xor_sync(0xffffffffu, p, 8);
        mx = fmaxf(mx, p);
        sm += p;
    }
    mx = fmaxf(mx, __shfl_xor_sync(0xffffffffu, mx, 16));
    sm += __shfl_xor_sync(0xffffffffu, sm, 16);
    if (lane == 0) Mout[gw] = mx - sm * (1.0f / (float)L_);
}

// ---------------- top-40 per (b,h): shuffle argmax, 2 barriers/round ---------------
__global__ void topk_kernel(const float* __restrict__ Mv, int* __restrict__ top)
{
    int bh  = blockIdx.x;
    int tid = threadIdx.x;
    int w = tid >> 5, lane = tid & 31;
    __shared__ float sv[L_];
    __shared__ float wv_[8];
    __shared__ int   wi_[8];
    for (int i = tid; i < L_; i += 256) sv[i] = Mv[(size_t)bh * L_ + i];
    __syncthreads();

    for (int r = 0; r < U_; r++) {
        float bv = -1e30f; int bi = 0x7fffffff;
        #pragma unroll
        for (int j = 0; j < 8; j++) {
            int i = tid + j * 256;
            float v = sv[i];
            if (v > bv || (v == bv && i < bi)) { bv = v; bi = i; }
        }
        #pragma unroll
        for (int o = 16; o; o >>= 1) {
            float ov = __shfl_xor_sync(0xffffffffu, bv, o);
            int   oi = __shfl_xor_sync(0xffffffffu, bi, o);
            if (ov > bv || (ov == bv && oi < bi)) { bv = ov; bi = oi; }
        }
        if (lane == 0) { wv_[w] = bv; wi_[w] = bi; }
        __syncthreads();
        if (tid == 0) {
            float fv = wv_[0]; int fi = wi_[0];
            #pragma unroll
            for (int j = 1; j < 8; j++) {
                float ov = wv_[j]; int oi = wi_[j];
                if (ov > fv || (ov == fv && oi < fi)) { fv = ov; fi = oi; }
            }
            top[bh * U_ + r] = fi;
            sv[fi] = -1e30f;
        }
        __syncthreads();
    }
}

// ---------------- v mean over L per (b,h) -----------------------------------------
__global__ void vmean_kernel(const float* __restrict__ v, float* __restrict__ vm)
{
    int bh = blockIdx.x; int b = bh >> 3, h = bh & 7;
    int tid = threadIdx.x;
    int d = tid & 31, seg = tid >> 5;
    const float* vb = v + (size_t)b * L_ * D + h * DH + d;
    float acc = 0.0f;
    for (int l = seg; l < L_; l += 8) acc += vb[(size_t)l * D];
    __shared__ float sp[8][32];
    sp[seg][d] = acc;
    __syncthreads();
    if (tid < 32) {
        float s = 0.0f;
        #pragma unroll
        for (int i = 0; i < 8; i++) s += sp[i][tid];
        vm[bh * DH + tid] = s * (1.0f / (float)L_);
    }
}

// ---------------- fill ctx planes with broadcast v-mean ---------------------------
__global__ void ctxfill_kernel(const float* __restrict__ vm,
                               __nv_bfloat16* __restrict__ chi,
                               __nv_bfloat16* __restrict__ clo)
{
    int i = blockIdx.x * blockDim.x + threadIdx.x;
    if (i >= B_ * L_ * D) return;
    int dfull = i & (D - 1);
    int b = i / (L_ * D);
    int h = dfull >> 5, d = dfull & 31;
    float v = vm[((b << 3) + h) * DH + d];
    split_scalar(v, chi + i, clo + i);
}

// ---------------- flash-style reduced attention: one block per (b,h) --------------
__global__ __launch_bounds__(256, 1)
void attn_topq_flash(const float* __restrict__ q, const float* __restrict__ k,
                     const float* __restrict__ v, const int* __restrict__ top,
                     __nv_bfloat16* __restrict__ chi, __nv_bfloat16* __restrict__ clo)
{
    __shared__ float Ks[128][33];
    __shared__ float Vs[128][33];
    __shared__ float qs[40][32];
    __shared__ float ps[8][128];
    __shared__ int   stop[40];

    int bh = blockIdx.x; int b = bh >> 3, h = bh & 7;
    int tid = threadIdx.x, w = tid >> 5, lane = tid & 31;

    if (tid < 40) stop[tid] = top[bh * U_ + tid];
    __syncthreads();
    for (int i = tid; i < 40 * 32; i += 256) {
        int u = i >> 5, d = i & 31;
        qs[u][d] = q[((size_t)b * L_ + stop[u]) * D + h * DH + d];
    }

    float m[5], l[5], acc[5];
    #pragma unroll
    for (int j = 0; j < 5; j++) { m[j] = -1e30f; l[j] = 0.f; acc[j] = 0.f; }
    const float scale = 0.1767766952966369f;
    const float* kb = k + (size_t)b * L_ * D + h * DH;
    const float* vb = v + (size_t)b * L_ * D + h * DH;
    __syncthreads();

    for (int t0 = 0; t0 < L_; t0 += 128) {
        for (int i = tid; i < 128 * 32; i += 256) {
            int r = i >> 5, d = i & 31;
            Ks[r][d] = kb[(size_t)(t0 + r) * D + d];
            Vs[r][d] = vb[(size_t)(t0 + r) * D + d];
        }
        __syncthreads();

        float sj[5][4];
        #pragma unroll
        for (int j = 0; j < 5; j++)
            #pragma unroll
            for (int i = 0; i < 4; i++) sj[j][i] = 0.f;
        #pragma unroll
        for (int d = 0; d < 32; d++) {
            float k0v = Ks[lane][d], k1v = Ks[lane + 32][d];
            float k2v = Ks[lane + 64][d], k3v = Ks[lane + 96][d];
            #pragma unroll
            for (int j = 0; j < 5; j++) {
                float qd = qs[w * 5 + j][d];
                sj[j][0] = fmaf(qd, k0v, sj[j][0]);
                sj[j][1] = fmaf(qd, k1v, sj[j][1]);
                sj[j][2] = fmaf(qd, k2v, sj[j][2]);
                sj[j][3] = fmaf(qd, k3v, sj[j][3]);
            }
        }
        #pragma unroll
        for (int j = 0; j < 5; j++) {
            float s0 = sj[j][0] * scale, s1 = sj[j][1] * scale;
            float s2 = sj[j][2] * scale, s3 = sj[j][3] * scale;
            float tm = fmaxf(fmaxf(s0, s1), fmaxf(s2, s3));
            #pragma unroll
            for (int o = 16; o; o >>= 1) tm = fmaxf(tm, __shfl_xor_sync(0xffffffffu, tm, o));
            float mn   = fmaxf(m[j], tm);
            float corr = __expf(m[j] - mn);
            float p0 = __expf(s0 - mn), p1 = __expf(s1 - mn);
            float p2 = __expf(s2 - mn), p3 = __expf(s3 - mn);
            float psum = p0 + p1 + p2 + p3;
            #pragma unroll
            for (int o = 16; o; o >>= 1) psum += __shfl_xor_sync(0xffffffffu, psum, o);
            l[j] = l[j] * corr + psum;
            m[j] = mn;
            ps[w][lane] = p0; ps[w][lane + 32] = p1; ps[w][lane + 64] = p2; ps[w][lane + 96] = p3;
            __syncwarp();
            float aa = acc[j] * corr;
            const float4* pv4 = (const float4*)ps[w];
            #pragma unroll 8
            for (int kk4 = 0; kk4 < 32; kk4++) {
                float4 p4 = pv4[kk4];
                int kk = kk4 * 4;
                aa = fmaf(p4.x, Vs[kk][lane],     aa);
                aa = fmaf(p4.y, Vs[kk + 1][lane], aa);
                aa = fmaf(p4.z, Vs[kk + 2][lane], aa);
                aa = fmaf(p4.w, Vs[kk + 3][lane], aa);
            }
            acc[j] = aa;
            __syncwarp();
        }
        __syncthreads();
    }
    #pragma unroll
    for (int j = 0; j < 5; j++) {
        int u = w * 5 + j;
        float o = acc[j] / l[j];
        size_t off = ((size_t)b * L_ + stop[u]) * D + h * DH + lane;
        split_scalar(o, chi + off, clo + off);
    }
}

// ---------------- residual add + LayerNorm + split (shuffle reductions) -----------
__global__ void add_ln_kernel(float* __restrict__ h, const float* __restrict__ r,
                              const float* __restrict__ g, const float* __restrict__ bb,
                              __nv_bfloat16* __restrict__ hhi, __nv_bfloat16* __restrict__ hlo)
{
    int row = blockIdx.x;
    int tid = threadIdx.x;
    int w = tid >> 5, lane = tid & 31;
    size_t off = (size_t)row * D + tid;
    float val = h[off] + r[off];
    float s1 = val, s2 = val * val;
    #pragma unroll
    for (int o = 16; o; o >>= 1) {
        s1 += __shfl_xor_sync(0xffffffffu, s1, o);
        s2 += __shfl_xor_sync(0xffffffffu, s2, o);
    }
    __shared__ float a1[8], a2[8];
    __shared__ float mu_s, rv_s;
    if (lane == 0) { a1[w] = s1; a2[w] = s2; }
    __syncthreads();
    if (w == 0) {
        float t1 = (lane < 8) ? a1[lane] : 0.f;
        float t2 = (lane < 8) ? a2[lane] : 0.f;
        #pragma unroll
        for (int o = 4; o; o >>= 1) {
            t1 += __shfl_xor_sync(0xffffffffu, t1, o);
            t2 += __shfl_xor_sync(0xffffffffu, t2, o);
        }
        if (lane == 0) {
            float mu = t1 * (1.0f / (float)D);
            float var = t2 * (1.0f / (float)D) - mu * mu;
            mu_s = mu;
            rv_s = rsqrtf(var + 1e-5f);
        }
    }
    __syncthreads();
    float o = (val - mu_s) * rv_s * g[tid] + bb[tid];
    h[off] = o;
    split_scalar(o, hhi + off, hlo + off);
}

// ---------------- final MLP head ---------------------------------------------------
__global__ void head_kernel(const float* __restrict__ h, const float* __restrict__ w1,
                            const float* __restrict__ b1, const float* __restrict__ w2,
                            const float* __restrict__ b2, float* __restrict__ out)
{
    int b = blockIdx.x;
    int j = threadIdx.x;
    const float* last = h + ((size_t)b * L_ + (L_ - 1)) * D;
    float acc = b1[j];
    for (int d = 0; d < D; d++) acc = fmaf(last[d], w1[d * 64 + j], acc);
    acc = fmaxf(acc, 0.0f) * w2[j];
    __shared__ float s[64];
    s[j] = acc; __syncthreads();
    for (int st = 32; st; st >>= 1) { if (j < st) s[j] += s[j + st]; __syncthreads(); }
    if (j == 0) out[b] = s[0] + b2[0];
}

// ===================================================================================
extern "C" void kernel_launch(void* const* d_in, const int* in_sizes, int n_in,
                              void* d_out, int out_size)
{
    const float* x     = (const float*)d_in[0];
    const int*   idx   = (const int*)  d_in[1];
    const float* w_in  = (const float*)d_in[2];
    const float* b_in  = (const float*)d_in[3];
    const float* wq    = (const float*)d_in[4];
    const float* bq    = (const float*)d_in[5];
    const float* wk    = (const float*)d_in[6];
    const float* bk    = (const float*)d_in[7];
    const float* wv    = (const float*)d_in[8];
    const float* bv    = (const float*)d_in[9];
    const float* wo    = (const float*)d_in[10];
    const float* bo    = (const float*)d_in[11];
    const float* w_ff1 = (const float*)d_in[12];
    const float* b_ff1 = (const float*)d_in[13];
    const float* w_ff2 = (const float*)d_in[14];
    const float* b_ff2 = (const float*)d_in[15];
    const float* ln1_g = (const float*)d_in[16];
    const float* ln1_b = (const float*)d_in[17];
    const float* ln2_g = (const float*)d_in[18];
    const float* ln2_b = (const float*)d_in[19];
    const float* w_fc1 = (const float*)d_in[20];
    const float* b_fc1 = (const float*)d_in[21];
    const float* w_fc2 = (const float*)d_in[22];
    const float* b_fc2 = (const float*)d_in[23];
    float* out = (float*)d_out;

    float *h, *q, *k, *v, *nx, *Mv, *vm; int* top;
    __nv_bfloat16 *xhi, *xlo, *hhi, *hlo, *chi, *clo, *fhi, *flo, *whi, *wlo;
    cudaGetSymbolAddress((void**)&h,   g_h);
    cudaGetSymbolAddress((void**)&q,   g_q);
    cudaGetSymbolAddress((void**)&k,   g_k);
    cudaGetSymbolAddress((void**)&v,   g_v);
    cudaGetSymbolAddress((void**)&nx,  g_nx);
    cudaGetSymbolAddress((void**)&Mv,  g_M);
    cudaGetSymbolAddress((void**)&top, g_top);
    cudaGetSymbolAddress((void**)&vm,  g_vm);
    cudaGetSymbolAddress((void**)&xhi, g_x_hi);  cudaGetSymbolAddress((void**)&xlo, g_x_lo);
    cudaGetSymbolAddress((void**)&hhi, g_h_hi);  cudaGetSymbolAddress((void**)&hlo, g_h_lo);
    cudaGetSymbolAddress((void**)&chi, g_ctx_hi); cudaGetSymbolAddress((void**)&clo, g_ctx_lo);
    cudaGetSymbolAddress((void**)&fhi, g_ff_hi); cudaGetSymbolAddress((void**)&flo, g_ff_lo);
    cudaGetSymbolAddress((void**)&whi, g_wt_hi); cudaGetSymbolAddress((void**)&wlo, g_wt_lo);

    cudaFuncSetAttribute(mma_gemm_bf16, cudaFuncAttributeMaxDynamicSharedMemorySize, GEMM_SMEM_V3);

    const int Mrows = B_ * L_;                     // 16384
    dim3 gD  (D / 128,   Mrows / 128);
    dim3 gQKV(3 * D / 128, Mrows / 128);
    dim3 gFF (DFF / 128, Mrows / 128);
    dim3 tb(32, 8);

    const size_t o_in = 0;
    auto o_q  = [&](int l){ return (size_t)FIN * D + (size_t)l * LYR_SZ; };
    auto o_o  = [&](int l){ return o_q(l) + 196608; };
    auto o_f1 = [&](int l){ return o_q(l) + 262144; };
    auto o_f2 = [&](int l){ return o_q(l) + 524288; };

    split_kernel<<<(B_ * L_ * FIN) / 512, 256>>>(x, xhi, xlo, B_ * L_ * FIN);
    transpose_all_kernel<<<1544, tb>>>(w_in, wq, wk, wv, wo, w_ff1, w_ff2, whi, wlo);
    mma_gemm_bf16<<<gD, 256, GEMM_SMEM_V3>>>(xhi, xlo, whi + o_in, wlo + o_in,
        b_in, nullptr, nullptr, h, nullptr, nullptr, hhi, hlo, Mrows, D, FIN, 0, 3, 0);

    for (int layer = 0; layer < NL; layer++) {
        const int* ixL = idx + (size_t)layer * L_ * S_;

        mma_gemm_bf16<<<gQKV, 256, GEMM_SMEM_V3>>>(hhi, hlo, whi + o_q(layer), wlo + o_q(layer),
            bq + layer * D, bk + layer * D, bv + layer * D,
            q, k, v, nullptr, nullptr, Mrows, 768, D, 0, 1, 1);

        qk_sample_kernel<<<(B_ * H_ * L_ * 32) / 256, 256>>>(q, k, ixL, Mv);
        topk_kernel<<<B_ * H_, 256>>>(Mv, top);
        vmean_kernel<<<B_ * H_, 256>>>(v, vm);
        ctxfill_kernel<<<(B_ * L_ * D) / 256, 256>>>(vm, chi, clo);
        attn_topq_flash<<<B_ * H_, 256>>>(q, k, v, top, chi, clo);

        mma_gemm_bf16<<<gD, 256, GEMM_SMEM_V3>>>(chi, clo, whi + o_o(layer), wlo + o_o(layer),
            bo + layer * D, nullptr, nullptr, nx, nullptr, nullptr, nullptr, nullptr,
            Mrows, D, D, 0, 1, 0);
        add_ln_kernel<<<Mrows, 256>>>(h, nx, ln1_g + layer * D, ln1_b + layer * D, hhi, hlo);

        mma_gemm_bf16<<<gFF, 256, GEMM_SMEM_V3>>>(hhi, hlo, whi + o_f1(layer), wlo + o_f1(layer),
            b_ff1 + layer * DFF, nullptr, nullptr, nullptr, nullptr, nullptr, fhi, flo,
            Mrows, DFF, D, 1, 2, 0);
        mma_gemm_bf16<<<gD, 256, GEMM_SMEM_V3>>>(fhi, flo, whi + o_f2(layer), wlo + o_f2(layer),
            b_ff2 + layer * D, nullptr, nullptr, nx, nullptr, nullptr, nullptr, nullptr,
            Mrows, D, DFF, 0, 1, 0);
        add_ln_kernel<<<Mrows, 256>>>(h, nx, ln2_g + layer * D, ln2_b + layer * D, hhi, hlo);
    }

    head_kernel<<<B_, 64>>>(h, w_fc1, b_fc1, w_fc2, b_fc2, out);
}

// round 8
// speedup vs baseline: 3.2680x; 1.1426x over previous
#include <cuda_runtime.h>
#include <cuda_bf16.h>
#include <cstdint>
#include <math.h>

// Problem constants
#define B_   8
#define L_   2048
#define FIN  32
#define D    256
#define H_   8
#define DH   32
#define DFF  1024
#define S_   40
#define U_   40
#define NL   2

// ---------------- scratch (device globals; no allocation allowed) ----------------
__device__ float g_h  [B_*L_*D];
__device__ float g_q  [B_*L_*D];
__device__ float g_k  [B_*L_*D];
__device__ float g_v  [B_*L_*D];
__device__ float g_nx [B_*L_*D];
__device__ float g_M  [B_*H_*L_];
__device__ int   g_top[B_*H_*U_];
__device__ float g_vm [B_*H_*DH];

// bf16 hi/lo planes
__device__ __nv_bfloat16 g_x_hi [B_*L_*FIN], g_x_lo [B_*L_*FIN];
__device__ __nv_bfloat16 g_h_hi [B_*L_*D],   g_h_lo [B_*L_*D];
__device__ __nv_bfloat16 g_ctx_hi[B_*L_*D],  g_ctx_lo[B_*L_*D];
__device__ __nv_bfloat16 g_ff_hi[B_*L_*DFF], g_ff_lo[B_*L_*DFF];
#define LYR_SZ   786432
#define WT_TOTAL (FIN*D + NL*LYR_SZ)
__device__ __nv_bfloat16 g_wt_hi[WT_TOTAL], g_wt_lo[WT_TOTAL];

// =========================== helpers ===============================================
__device__ __forceinline__ uint32_t smem_u32(const void* p) {
    uint32_t a;
    asm("{ .reg .u64 t; cvta.to.shared.u64 t, %1; cvt.u32.u64 %0, t; }" : "=r"(a) : "l"(p));
    return a;
}
__device__ __forceinline__ void split2(float x, float y, uint32_t& hi, uint32_t& lo) {
    __nv_bfloat162 h = __float22bfloat162_rn(make_float2(x, y));
    float2 hf = __bfloat1622float2(h);
    __nv_bfloat162 l = __float22bfloat162_rn(make_float2(x - hf.x, y - hf.y));
    hi = *(uint32_t*)&h; lo = *(uint32_t*)&l;
}
__device__ __forceinline__ void split_scalar(float v, __nv_bfloat16* hp, __nv_bfloat16* lp) {
    __nv_bfloat16 hb = __float2bfloat16(v);
    *hp = hb;
    *lp = __float2bfloat16(v - __bfloat162float(hb));
}

#define MMA_BF16(c, a, b)                                                        \
    asm volatile("mma.sync.aligned.m16n8k16.row.col.f32.bf16.bf16.f32 "          \
        "{%0,%1,%2,%3}, {%4,%5,%6,%7}, {%8,%9}, {%0,%1,%2,%3};"                  \
        : "+f"((c)[0]), "+f"((c)[1]), "+f"((c)[2]), "+f"((c)[3])                  \
        : "r"((a)[0]), "r"((a)[1]), "r"((a)[2]), "r"((a)[3]),                     \
          "r"((b)[0]), "r"((b)[1]))

#define LDM4(r, addr)                                                            \
    asm volatile("ldmatrix.sync.aligned.m8n8.x4.shared.b16 {%0,%1,%2,%3}, [%4];" \
        : "=r"((r)[0]), "=r"((r)[1]), "=r"((r)[2]), "=r"((r)[3]) : "r"(addr))

// =================== 3-stage pipelined bf16x3 GEMM, swizzled smem ==================
// plane layout: [128 rows][16 uint32] (64B rows), swizzle u' = u ^ ((r>>1)&3)
#define PLANE_U 2048
#define STAGE_U (4*PLANE_U)
#define STAGE_B (STAGE_U*4)       // 32768 bytes
#define GEMM_SMEM_V3 (3*STAGE_B)  // 98304 bytes

__global__ __launch_bounds__(256, 2)
void mma_gemm_bf16(const __nv_bfloat16* __restrict__ Ahi, const __nv_bfloat16* __restrict__ Alo,
                   const __nv_bfloat16* __restrict__ Bhi, const __nv_bfloat16* __restrict__ Blo,
                   const float* __restrict__ b0, const float* __restrict__ b1,
                   const float* __restrict__ b2,
                   float* __restrict__ C0, float* __restrict__ C1, float* __restrict__ C2,
                   __nv_bfloat16* __restrict__ Chi, __nv_bfloat16* __restrict__ Clo,
                   const float* __restrict__ Radd,
                   int M, int N, int K, int relu, int mode, int split3)
{
    extern __shared__ uint32_t sm[];
    int tid  = threadIdx.x;
    int brow = blockIdx.y * 128;
    int bcol = blockIdx.x * 128;
    int w = tid >> 5, lane = tid & 31;
    int gid = lane >> 2, tig = lane & 3;
    int moff = (w >> 1) * 32, noff = (w & 1) * 64;
    uint32_t smb = smem_u32(sm);

    int mat = lane >> 3, r8 = lane & 7;
    uint32_t aoffk[2][2], boffk[4][2];
    #pragma unroll
    for (int mt = 0; mt < 2; mt++) {
        int row = moff + mt * 16 + (mat & 1) * 8 + r8;
        int sw = (row >> 1) & 3;
        #pragma unroll
        for (int ks = 0; ks < 2; ks++) {
            int u = ks * 2 + (mat >> 1);
            aoffk[mt][ks] = (uint32_t)(row * 16 + ((u ^ sw) << 2)) * 4;
        }
    }
    #pragma unroll
    for (int p = 0; p < 4; p++) {
        int row = noff + p * 16 + (mat >> 1) * 8 + r8;
        int sw = (row >> 1) & 3;
        #pragma unroll
        for (int ks = 0; ks < 2; ks++) {
            int u = ks * 2 + (mat & 1);
            boffk[p][ks] = (uint32_t)(row * 16 + ((u ^ sw) << 2)) * 4;
        }
    }

    float acc[2][8][4] = {};
    const int NC = K >> 5;

    // prologue: stages 0 and 1
    #pragma unroll
    for (int st = 0; st < 2; st++) {
        if (st < NC) {
            uint32_t sb = smb + (uint32_t)st * STAGE_B;
            int k0 = st * 32;
            #pragma unroll
            for (int i = 0; i < 8; i++) {
                int e  = tid + i * 256;
                int pl = e >> 9;
                int r  = (e >> 2) & 127;
                int s  = e & 3;
                const __nv_bfloat16* src;
                if      (pl == 0) src = Ahi + (size_t)(brow + r) * K + k0 + s * 8;
                else if (pl == 1) src = Alo + (size_t)(brow + r) * K + k0 + s * 8;
                else if (pl == 2) src = Bhi + (size_t)(bcol + r) * K + k0 + s * 8;
                else              src = Blo + (size_t)(bcol + r) * K + k0 + s * 8;
                uint32_t dst = sb + (uint32_t)(pl * PLANE_U + r * 16 + ((s ^ ((r >> 1) & 3)) << 2)) * 4;
                asm volatile("cp.async.cg.shared.global [%0], [%1], 16;" :: "r"(dst), "l"(src));
            }
            asm volatile("cp.async.commit_group;" ::: "memory");
        }
    }

    int stage_c = 0;
    for (int c = 0; c < NC; c++) {
        if (c + 1 < NC) {
            asm volatile("cp.async.wait_group 1;" ::: "memory");
        } else {
            asm volatile("cp.async.wait_group 0;" ::: "memory");
        }
        __syncthreads();

        if (c + 2 < NC) {
            int stage_n = stage_c + 2; if (stage_n >= 3) stage_n -= 3;
            uint32_t sb = smb + (uint32_t)stage_n * STAGE_B;
            int k0 = (c + 2) * 32;
            #pragma unroll
            for (int i = 0; i < 8; i++) {
                int e  = tid + i * 256;
                int pl = e >> 9;
                int r  = (e >> 2) & 127;
                int s  = e & 3;
                const __nv_bfloat16* src;
                if      (pl == 0) src = Ahi + (size_t)(brow + r) * K + k0 + s * 8;
                else if (pl == 1) src = Alo + (size_t)(brow + r) * K + k0 + s * 8;
                else if (pl == 2) src = Bhi + (size_t)(bcol + r) * K + k0 + s * 8;
                else              src = Blo + (size_t)(bcol + r) * K + k0 + s * 8;
                uint32_t dst = sb + (uint32_t)(pl * PLANE_U + r * 16 + ((s ^ ((r >> 1) & 3)) << 2)) * 4;
                asm volatile("cp.async.cg.shared.global [%0], [%1], 16;" :: "r"(dst), "l"(src));
            }
            asm volatile("cp.async.commit_group;" ::: "memory");
        }

        uint32_t bb = smb + (uint32_t)stage_c * STAGE_B;
        uint32_t Ahb = bb, Alb = bb + PLANE_U * 4, Bhb = bb + 2 * PLANE_U * 4, Blb = bb + 3 * PLANE_U * 4;

        #pragma unroll
        for (int ks = 0; ks < 2; ks++) {
            uint32_t afh[2][4], afl[2][4];
            #pragma unroll
            for (int mt = 0; mt < 2; mt++) {
                LDM4(afh[mt], Ahb + aoffk[mt][ks]);
                LDM4(afl[mt], Alb + aoffk[mt][ks]);
            }
            #pragma unroll
            for (int p = 0; p < 4; p++) {
                uint32_t bfh[4], bfl[4];
                LDM4(bfh, Bhb + boffk[p][ks]);
                LDM4(bfl, Blb + boffk[p][ks]);
                #pragma unroll
                for (int mt = 0; mt < 2; mt++)
                    #pragma unroll
                    for (int hf = 0; hf < 2; hf++) {
                        int nt = p * 2 + hf;
                        MMA_BF16(acc[mt][nt], afh[mt], &bfh[hf * 2]);
                        MMA_BF16(acc[mt][nt], afh[mt], &bfl[hf * 2]);
                        MMA_BF16(acc[mt][nt], afl[mt], &bfh[hf * 2]);
                    }
            }
        }
        stage_c++; if (stage_c >= 3) stage_c = 0;
    }

    // epilogue
    float* Cf; const float* bp_; int cb, Nst;
    if (split3) {
        int mi = bcol >> 8;
        Cf  = (mi == 0) ? C0 : (mi == 1 ? C1 : C2);
        bp_ = (mi == 0) ? b0 : (mi == 1 ? b1 : b2);
        cb = bcol & 255; Nst = 256;
    } else {
        Cf = C0; bp_ = b0; cb = bcol; Nst = N;
    }

    #pragma unroll
    for (int mt = 0; mt < 2; mt++) {
        int r0 = brow + moff + mt * 16 + gid;
        #pragma unroll
        for (int nt = 0; nt < 8; nt++) {
            int c = cb + noff + nt * 8 + tig * 2;
            float bb0 = bp_[c], bb1 = bp_[c + 1];
            float2 o0 = make_float2(acc[mt][nt][0] + bb0, acc[mt][nt][1] + bb1);
            float2 o1 = make_float2(acc[mt][nt][2] + bb0, acc[mt][nt][3] + bb1);
            size_t i0 = (size_t)r0 * Nst + c;
            size_t i1 = (size_t)(r0 + 8) * Nst + c;
            if (Radd) {
                float2 ra0 = *(const float2*)(Radd + i0);
                float2 ra1 = *(const float2*)(Radd + i1);
                o0.x += ra0.x; o0.y += ra0.y;
                o1.x += ra1.x; o1.y += ra1.y;
            }
            if (relu) {
                o0.x = fmaxf(o0.x, 0.f); o0.y = fmaxf(o0.y, 0.f);
                o1.x = fmaxf(o1.x, 0.f); o1.y = fmaxf(o1.y, 0.f);
            }
            if (mode & 1) {
                *(float2*)(Cf + i0) = o0;
                *(float2*)(Cf + i1) = o1;
            }
            if (mode & 2) {
                uint32_t h0, l0, h1, l1;
                split2(o0.x, o0.y, h0, l0);
                split2(o1.x, o1.y, h1, l1);
                *(uint32_t*)(Chi + i0) = h0; *(uint32_t*)(Clo + i0) = l0;
                *(uint32_t*)(Chi + i1) = h1; *(uint32_t*)(Clo + i1) = l1;
            }
        }
    }
}

// ---------------- batched transpose+split of ALL weights (one launch) -------------
__global__ void transpose_all_kernel(const float* __restrict__ w_in,
                                     const float* __restrict__ wq, const float* __restrict__ wk,
                                     const float* __restrict__ wv, const float* __restrict__ wo,
                                     const float* __restrict__ f1, const float* __restrict__ f2,
                                     __nv_bfloat16* __restrict__ hi, __nv_bfloat16* __restrict__ lo)
{
    const int start[14] = {0, 8, 72, 136, 200, 264, 520, 776, 840, 904, 968, 1032, 1288, 1544};
    int t = blockIdx.x;
    int m = 0;
    #pragma unroll
    for (int i = 1; i < 14; i++) if (t >= start[i]) m = i;
    int layer = (m >= 7) ? 1 : 0;
    int mi = (m == 0) ? 0 : ((m - 1) % 6) + 1;
    const float* src; int K, N; size_t dst;
    size_t base = (size_t)FIN * D + (size_t)layer * LYR_SZ;
    switch (mi) {
        case 0: src = w_in;                          K = FIN; N = D;   dst = 0;             break;
        case 1: src = wq + (size_t)layer * D * D;    K = D;   N = D;   dst = base;          break;
        case 2: src = wk + (size_t)layer * D * D;    K = D;   N = D;   dst = base + 65536;  break;
        case 3: src = wv + (size_t)layer * D * D;    K = D;   N = D;   dst = base + 131072; break;
        case 4: src = wo + (size_t)layer * D * D;    K = D;   N = D;   dst = base + 196608; break;
        case 5: src = f1 + (size_t)layer * D * DFF;  K = D;   N = DFF; dst = base + 262144; break;
        default:src = f2 + (size_t)layer * DFF * D;  K = DFF; N = D;   dst = base + 524288; break;
    }
    int lt = t - start[m];
    int ntn = N >> 5;
    int nb = (lt % ntn) << 5, kb = (lt / ntn) << 5;

    __shared__ float tbuf[32][33];
    int tx = threadIdx.x, ty = threadIdx.y;
    #pragma unroll
    for (int i = ty; i < 32; i += 8)
        tbuf[i][tx] = src[(size_t)(kb + i) * N + nb + tx];
    __syncthreads();
    #pragma unroll
    for (int i = ty; i < 32; i += 8) {
        float v = tbuf[tx][i];
        size_t o = dst + (size_t)(nb + i) * K + kb + tx;
        split_scalar(v, hi + o, lo + o);
    }
}

// ---------------- plain split: fp32 -> hi/lo bf16 ---------------------------------
__global__ void split_kernel(const float* __restrict__ in,
                             __nv_bfloat16* __restrict__ hi,
                             __nv_bfloat16* __restrict__ lo, int n)
{
    int i = (blockIdx.x * blockDim.x + threadIdx.x) * 2;
    if (i >= n) return;
    float2 v = *(const float2*)(in + i);
    uint32_t h, l;
    split2(v.x, v.y, h, l);
    *(uint32_t*)(hi + i) = h;
    *(uint32_t*)(lo + i) = l;
}

// ---------------- fused sampled-QK M-score + v-mean (block-routed) ----------------
__global__ void qkvm_kernel(const float* __restrict__ q, const float* __restrict__ k,
                            const int* __restrict__ idx, float* __restrict__ Mout,
                            const float* __restrict__ v, float* __restrict__ vm)
{
    if (blockIdx.x < 2048) {
        // sampled QK -> M score (float2 half-warp form)
        int gw   = (blockIdx.x * blockDim.x + threadIdx.x) >> 5;
        int lane = threadIdx.x & 31;
        int l  = gw & (L_ - 1);
        int bh = gw >> 11;
        int b  = bh >> 3, h = bh & 7;

        int d2 = lane & 15, sh = lane >> 4;
        float2 q2 = *(const float2*)(q + ((size_t)b * L_ + l) * D + h * DH + 2 * d2);
        const float* kbase = k + (size_t)b * L_ * D + h * DH;
        const int*   irow  = idx + l * S_;

        float mx = -1e30f, sm = 0.0f;
        #pragma unroll 4
        for (int s0 = 0; s0 < S_; s0 += 2) {
            int ki = __ldg(&irow[s0 + sh]);
            float2 kv = *(const float2*)(kbase + (size_t)ki * D + 2 * d2);
            float p = q2.x * kv.x + q2.y * kv.y;
            p += __shfl_xor_sync(0xffffffffu, p, 1);
            p += __shfl_xor_sync(0xffffffffu, p, 2);
            p += __shfl_xor_sync(0xffffffffu, p, 4);
            p += __shfl_xor_sync(0xffffffffu, p, 8);
            mx = fmaxf(mx, p);
            sm += p;
        }
        mx = fmaxf(mx, __shfl_xor_sync(0xffffffffu, mx, 16));
        sm += __shfl_xor_sync(0xffffffffu, sm, 16);
        if (lane == 0) Mout[gw] = mx - sm * (1.0f / (float)L_);
    } else {
        // v mean
        int bh = blockIdx.x - 2048; int b = bh >> 3, h = bh & 7;
        int tid = threadIdx.x;
        int d = tid & 31, seg = tid >> 5;
        const float* vb = v + (size_t)b * L_ * D + h * DH + d;
        float acc = 0.0f;
        for (int l = seg; l < L_; l += 8) acc += vb[(size_t)l * D];
        __shared__ float sp[8][32];
        sp[seg][d] = acc;
        __syncthreads();
        if (tid < 32) {
            float s = 0.0f;
            #pragma unroll
            for (int i = 0; i < 8; i++) s += sp[i][tid];
            vm[bh * DH + tid] = s * (1.0f / (float)L_);
        }
    }
}

// ---------------- top-40 per (b,h): shuffle argmax, 2 barriers/round ---------------
__global__ void topk_kernel(const float* __restrict__ Mv, int* __restrict__ top)
{
    int bh  = blockIdx.x;
    int tid = threadIdx.x;
    int w = tid >> 5, lane = tid & 31;
    __shared__ float sv[L_];
    __shared__ float wv_[8];
    __shared__ int   wi_[8];
    for (int i = tid; i < L_; i += 256) sv[i] = Mv[(size_t)bh * L_ + i];
    __syncthreads();

    for (int r = 0; r < U_; r++) {
        float bv = -1e30f; int bi = 0x7fffffff;
        #pragma unroll
        for (int j = 0; j < 8; j++) {
            int i = tid + j * 256;
            float v = sv[i];
            if (v > bv || (v == bv && i < bi)) { bv = v; bi = i; }
        }
        #pragma unroll
        for (int o = 16; o; o >>= 1) {
            float ov = __shfl_xor_sync(0xffffffffu, bv, o);
            int   oi = __shfl_xor_sync(0xffffffffu, bi, o);
            if (ov > bv || (ov == bv && oi < bi)) { bv = ov; bi = oi; }
        }
        if (lane == 0) { wv_[w] = bv; wi_[w] = bi; }
        __syncthreads();
        if (tid == 0) {
            float fv = wv_[0]; int fi = wi_[0];
            #pragma unroll
            for (int j = 1; j < 8; j++) {
                float ov = wv_[j]; int oi = wi_[j];
                if (ov > fv || (ov == fv && oi < fi)) { fv = ov; fi = oi; }
            }
            top[bh * U_ + r] = fi;
            sv[fi] = -1e30f;
        }
        __syncthreads();
    }
}

// ---------------- fill ctx planes with broadcast v-mean (vectorized x4) ------------
__global__ void ctxfill_kernel(const float* __restrict__ vm,
                               __nv_bfloat16* __restrict__ chi,
                               __nv_bfloat16* __restrict__ clo)
{
    int i4 = (blockIdx.x * blockDim.x + threadIdx.x) * 4;
    if (i4 >= B_ * L_ * D) return;
    int dfull = i4 & (D - 1);
    int b = i4 / (L_ * D);
    int h = dfull >> 5, d = dfull & 31;
    float4 v = *(const float4*)(vm + ((b << 3) + h) * DH + d);
    uint32_t h01, h23, l01, l23;
    split2(v.x, v.y, h01, l01);
    split2(v.z, v.w, h23, l23);
    *(uint2*)(chi + i4) = make_uint2(h01, h23);
    *(uint2*)(clo + i4) = make_uint2(l01, l23);
}

// ---------------- flash-style reduced attention: one block per (b,h) --------------
__global__ __launch_bounds__(256, 1)
void attn_topq_flash(const float* __restrict__ q, const float* __restrict__ k,
                     const float* __restrict__ v, const int* __restrict__ top,
                     __nv_bfloat16* __restrict__ chi, __nv_bfloat16* __restrict__ clo)
{
    __shared__ float Ks[128][33];
    __shared__ float Vs[128][33];
    __shared__ float qs[40][32];
    __shared__ float ps[8][128];
    __shared__ int   stop[40];

    int bh = blockIdx.x; int b = bh >> 3, h = bh & 7;
    int tid = threadIdx.x, w = tid >> 5, lane = tid & 31;

    if (tid < 40) stop[tid] = top[bh * U_ + tid];
    __syncthreads();
    for (int i = tid; i < 40 * 32; i += 256) {
        int u = i >> 5, d = i & 31;
        qs[u][d] = q[((size_t)b * L_ + stop[u]) * D + h * DH + d];
    }

    float m[5], l[5], acc[5];
    #pragma unroll
    for (int j = 0; j < 5; j++) { m[j] = -1e30f; l[j] = 0.f; acc[j] = 0.f; }
    const float scale = 0.1767766952966369f;
    const float* kb = k + (size_t)b * L_ * D + h * DH;
    const float* vb = v + (size_t)b * L_ * D + h * DH;
    __syncthreads();

    for (int t0 = 0; t0 < L_; t0 += 128) {
        for (int i = tid; i < 128 * 32; i += 256) {
            int r = i >> 5, d = i & 31;
            Ks[r][d] = kb[(size_t)(t0 + r) * D + d];
            Vs[r][d] = vb[(size_t)(t0 + r) * D + d];
        }
        __syncthreads();

        float sj[5][4];
        #pragma unroll
        for (int j = 0; j < 5; j++)
            #pragma unroll
            for (int i = 0; i < 4; i++) sj[j][i] = 0.f;
        #pragma unroll
        for (int d = 0; d < 32; d++) {
            float k0v = Ks[lane][d], k1v = Ks[lane + 32][d];
            float k2v = Ks[lane + 64][d], k3v = Ks[lane + 96][d];
            #pragma unroll
            for (int j = 0; j < 5; j++) {
                float qd = qs[w * 5 + j][d];
                sj[j][0] = fmaf(qd, k0v, sj[j][0]);
                sj[j][1] = fmaf(qd, k1v, sj[j][1]);
                sj[j][2] = fmaf(qd, k2v, sj[j][2]);
                sj[j][3] = fmaf(qd, k3v, sj[j][3]);
            }
        }
        #pragma unroll
        for (int j = 0; j < 5; j++) {
            float s0 = sj[j][0] * scale, s1 = sj[j][1] * scale;
            float s2 = sj[j][2] * scale, s3 = sj[j][3] * scale;
            float tm = fmaxf(fmaxf(s0, s1), fmaxf(s2, s3));
            #pragma unroll
            for (int o = 16; o; o >>= 1) tm = fmaxf(tm, __shfl_xor_sync(0xffffffffu, tm, o));
            float mn   = fmaxf(m[j], tm);
            float corr = __expf(m[j] - mn);
            float p0 = __expf(s0 - mn), p1 = __expf(s1 - mn);
            float p2 = __expf(s2 - mn), p3 = __expf(s3 - mn);
            float psum = p0 + p1 + p2 + p3;
            #pragma unroll
            for (int o = 16; o; o >>= 1) psum += __shfl_xor_sync(0xffffffffu, psum, o);
            l[j] = l[j] * corr + psum;
            m[j] = mn;
            ps[w][lane] = p0; ps[w][lane + 32] = p1; ps[w][lane + 64] = p2; ps[w][lane + 96] = p3;
            __syncwarp();
            float aa = acc[j] * corr;
            const float4* pv4 = (const float4*)ps[w];
            #pragma unroll 8
            for (int kk4 = 0; kk4 < 32; kk4++) {
                float4 p4 = pv4[kk4];
                int kk = kk4 * 4;
                aa = fmaf(p4.x, Vs[kk][lane],     aa);
                aa = fmaf(p4.y, Vs[kk + 1][lane], aa);
                aa = fmaf(p4.z, Vs[kk + 2][lane], aa);
                aa = fmaf(p4.w, Vs[kk + 3][lane], aa);
            }
            acc[j] = aa;
            __syncwarp();
        }
        __syncthreads();
    }
    #pragma unroll
    for (int j = 0; j < 5; j++) {
        int u = w * 5 + j;
        float o = acc[j] / l[j];
        size_t off = ((size_t)b * L_ + stop[u]) * D + h * DH + lane;
        split_scalar(o, chi + off, clo + off);
    }
}

// ---------- LayerNorm of pre-summed input + split; 2 rows/block, vectorized --------
__global__ void add_ln_kernel(const float* __restrict__ sum,
                              const float* __restrict__ g, const float* __restrict__ bb,
                              float* __restrict__ hout,
                              __nv_bfloat16* __restrict__ hhi, __nv_bfloat16* __restrict__ hlo)
{
    int tid = threadIdx.x;
    int rl  = tid >> 7;                 // row within block (0/1)
    int ct  = tid & 127;                // column thread
    int row = blockIdx.x * 2 + rl;
    size_t off = (size_t)row * D + ct * 2;
    float2 v = *(const float2*)(sum + off);
    float s1 = v.x + v.y, s2 = v.x * v.x + v.y * v.y;
    #pragma unroll
    for (int o = 16; o; o >>= 1) {
        s1 += __shfl_xor_sync(0xffffffffu, s1, o);
        s2 += __shfl_xor_sync(0xffffffffu, s2, o);
    }
    __shared__ float a1[2][4], a2[2][4], mu[2], rv[2];
    int wr = (tid >> 5) & 3;            // warp within row
    int lane = tid & 31;
    if (lane == 0) { a1[rl][wr] = s1; a2[rl][wr] = s2; }
    __syncthreads();
    if (ct == 0) {
        float t1 = a1[rl][0] + a1[rl][1] + a1[rl][2] + a1[rl][3];
        float t2 = a2[rl][0] + a2[rl][1] + a2[rl][2] + a2[rl][3];
        float m = t1 * (1.0f / (float)D);
        float var = t2 * (1.0f / (float)D) - m * m;
        mu[rl] = m;
        rv[rl] = rsqrtf(var + 1e-5f);
    }
    __syncthreads();
    float m = mu[rl], r = rv[rl];
    float2 gg = *(const float2*)(g + ct * 2);
    float2 b2 = *(const float2*)(bb + ct * 2);
    float2 o;
    o.x = (v.x - m) * r * gg.x + b2.x;
    o.y = (v.y - m) * r * gg.y + b2.y;
    *(float2*)(hout + off) = o;
    uint32_t hi32, lo32;
    split2(o.x, o.y, hi32, lo32);
    *(uint32_t*)(hhi + off) = hi32;
    *(uint32_t*)(hlo + off) = lo32;
}

// ---------------- final MLP head ---------------------------------------------------
__global__ void head_kernel(const float* __restrict__ h, const float* __restrict__ w1,
                            const float* __restrict__ b1, const float* __restrict__ w2,
                            const float* __restrict__ b2, float* __restrict__ out)
{
    int b = blockIdx.x;
    int j = threadIdx.x;
    const float* last = h + ((size_t)b * L_ + (L_ - 1)) * D;
    float acc = b1[j];
    for (int d = 0; d < D; d++) acc = fmaf(last[d], w1[d * 64 + j], acc);
    acc = fmaxf(acc, 0.0f) * w2[j];
    __shared__ float s[64];
    s[j] = acc; __syncthreads();
    for (int st = 32; st; st >>= 1) { if (j < st) s[j] += s[j + st]; __syncthreads(); }
    if (j == 0) out[b] = s[0] + b2[0];
}

// ===================================================================================
extern "C" void kernel_launch(void* const* d_in, const int* in_sizes, int n_in,
                              void* d_out, int out_size)
{
    const float* x     = (const float*)d_in[0];
    const int*   idx   = (const int*)  d_in[1];
    const float* w_in  = (const float*)d_in[2];
    const float* b_in  = (const float*)d_in[3];
    const float* wq    = (const float*)d_in[4];
    const float* bq    = (const float*)d_in[5];
    const float* wk    = (const float*)d_in[6];
    const float* bk    = (const float*)d_in[7];
    const float* wv    = (const float*)d_in[8];
    const float* bv    = (const float*)d_in[9];
    const float* wo    = (const float*)d_in[10];
    const float* bo    = (const float*)d_in[11];
    const float* w_ff1 = (const float*)d_in[12];
    const float* b_ff1 = (const float*)d_in[13];
    const float* w_ff2 = (const float*)d_in[14];
    const float* b_ff2 = (const float*)d_in[15];
    const float* ln1_g = (const float*)d_in[16];
    const float* ln1_b = (const float*)d_in[17];
    const float* ln2_g = (const float*)d_in[18];
    const float* ln2_b = (const float*)d_in[19];
    const float* w_fc1 = (const float*)d_in[20];
    const float* b_fc1 = (const float*)d_in[21];
    const float* w_fc2 = (const float*)d_in[22];
    const float* b_fc2 = (const float*)d_in[23];
    float* out = (float*)d_out;

    float *h, *q, *k, *v, *nx, *Mv, *vm; int* top;
    __nv_bfloat16 *xhi, *xlo, *hhi, *hlo, *chi, *clo, *fhi, *flo, *whi, *wlo;
    cudaGetSymbolAddress((void**)&h,   g_h);
    cudaGetSymbolAddress((void**)&q,   g_q);
    cudaGetSymbolAddress((void**)&k,   g_k);
    cudaGetSymbolAddress((void**)&v,   g_v);
    cudaGetSymbolAddress((void**)&nx,  g_nx);
    cudaGetSymbolAddress((void**)&Mv,  g_M);
    cudaGetSymbolAddress((void**)&top, g_top);
    cudaGetSymbolAddress((void**)&vm,  g_vm);
    cudaGetSymbolAddress((void**)&xhi, g_x_hi);  cudaGetSymbolAddress((void**)&xlo, g_x_lo);
    cudaGetSymbolAddress((void**)&hhi, g_h_hi);  cudaGetSymbolAddress((void**)&hlo, g_h_lo);
    cudaGetSymbolAddress((void**)&chi, g_ctx_hi); cudaGetSymbolAddress((void**)&clo, g_ctx_lo);
    cudaGetSymbolAddress((void**)&fhi, g_ff_hi); cudaGetSymbolAddress((void**)&flo, g_ff_lo);
    cudaGetSymbolAddress((void**)&whi, g_wt_hi); cudaGetSymbolAddress((void**)&wlo, g_wt_lo);

    cudaFuncSetAttribute(mma_gemm_bf16, cudaFuncAttributeMaxDynamicSharedMemorySize, GEMM_SMEM_V3);

    const int Mrows = B_ * L_;                     // 16384
    dim3 gD  (D / 128,   Mrows / 128);
    dim3 gQKV(3 * D / 128, Mrows / 128);
    dim3 gFF (DFF / 128, Mrows / 128);
    dim3 tb(32, 8);

    const size_t o_in = 0;
    auto o_q  = [&](int l){ return (size_t)FIN * D + (size_t)l * LYR_SZ; };
    auto o_o  = [&](int l){ return o_q(l) + 196608; };
    auto o_f1 = [&](int l){ return o_q(l) + 262144; };
    auto o_f2 = [&](int l){ return o_q(l) + 524288; };

    split_kernel<<<(B_ * L_ * FIN) / 512, 256>>>(x, xhi, xlo, B_ * L_ * FIN);
    transpose_all_kernel<<<1544, tb>>>(w_in, wq, wk, wv, wo, w_ff1, w_ff2, whi, wlo);
    mma_gemm_bf16<<<gD, 256, GEMM_SMEM_V3>>>(xhi, xlo, whi + o_in, wlo + o_in,
        b_in, nullptr, nullptr, h, nullptr, nullptr, hhi, hlo, nullptr, Mrows, D, FIN, 0, 3, 0);

    for (int layer = 0; layer < NL; layer++) {
        const int* ixL = idx + (size_t)layer * L_ * S_;

        mma_gemm_bf16<<<gQKV, 256, GEMM_SMEM_V3>>>(hhi, hlo, whi + o_q(layer), wlo + o_q(layer),
            bq + layer * D, bk + layer * D, bv + layer * D,
            q, k, v, nullptr, nullptr, nullptr, Mrows, 768, D, 0, 1, 1);

        qkvm_kernel<<<2048 + B_ * H_, 256>>>(q, k, ixL, Mv, v, vm);
        topk_kernel<<<B_ * H_, 256>>>(Mv, top);
        ctxfill_kernel<<<(B_ * L_ * D) / 1024, 256>>>(vm, chi, clo);
        attn_topq_flash<<<B_ * H_, 256>>>(q, k, v, top, chi, clo);

        // wo GEMM with fused residual add: nx = ctx@wo + bo + h
        mma_gemm_bf16<<<gD, 256, GEMM_SMEM_V3>>>(chi, clo, whi + o_o(layer), wlo + o_o(layer),
            bo + layer * D, nullptr, nullptr, nx, nullptr, nullptr, nullptr, nullptr, h,
            Mrows, D, D, 0, 1, 0);
        add_ln_kernel<<<Mrows / 2, 256>>>(nx, ln1_g + layer * D, ln1_b + layer * D, h, hhi, hlo);

        mma_gemm_bf16<<<gFF, 256, GEMM_SMEM_V3>>>(hhi, hlo, whi + o_f1(layer), wlo + o_f1(layer),
            b_ff1 + layer * DFF, nullptr, nullptr, nullptr, nullptr, nullptr, fhi, flo, nullptr,
            Mrows, DFF, D, 1, 2, 0);
        // FF2 GEMM with fused residual add: nx = ff@w_ff2 + b_ff2 + h
        mma_gemm_bf16<<<gD, 256, GEMM_SMEM_V3>>>(fhi, flo, whi + o_f2(layer), wlo + o_f2(layer),
            b_ff2 + layer * D, nullptr, nullptr, nx, nullptr, nullptr, nullptr, nullptr, h,
            Mrows, D, DFF, 0, 1, 0);
        add_ln_kernel<<<Mrows / 2, 256>>>(nx, ln2_g + layer * D, ln2_b + layer * D, h, hhi, hlo);
    }

    head_kernel<<<B_, 64>>>(h, w_fc1, b_fc1, w_fc2, b_fc2, out);
}

// round 9
// speedup vs baseline: 3.7063x; 1.1341x over previous
#include <cuda_runtime.h>
#include <cuda_bf16.h>
#include <cstdint>
#include <math.h>

// Problem constants
#define B_   8
#define L_   2048
#define FIN  32
#define D    256
#define H_   8
#define DH   32
#define DFF  1024
#define S_   40
#define U_   40
#define NL   2

// ---------------- scratch (device globals; no allocation allowed) ----------------
__device__ float g_h  [B_*L_*D];
__device__ float g_q  [B_*L_*D];
__device__ float g_k  [B_*L_*D];
__device__ float g_v  [B_*L_*D];
__device__ float g_nx [B_*L_*D];
__device__ float g_M  [B_*H_*L_];
__device__ int   g_top[B_*H_*U_];
__device__ float g_vm [B_*H_*DH];
__device__ float g_ctxl[B_*H_*DH];     // last-row ctx for final layer

// bf16 hi/lo planes
__device__ __nv_bfloat16 g_x_hi [B_*L_*FIN], g_x_lo [B_*L_*FIN];
__device__ __nv_bfloat16 g_h_hi [B_*L_*D],   g_h_lo [B_*L_*D];
__device__ __nv_bfloat16 g_ctx_hi[B_*L_*D],  g_ctx_lo[B_*L_*D];
__device__ __nv_bfloat16 g_ff_hi[B_*L_*DFF], g_ff_lo[B_*L_*DFF];
#define LYR_SZ   786432
#define WT_TOTAL (FIN*D + NL*LYR_SZ)
__device__ __nv_bfloat16 g_wt_hi[WT_TOTAL], g_wt_lo[WT_TOTAL];

// =========================== helpers ===============================================
__device__ __forceinline__ uint32_t smem_u32(const void* p) {
    uint32_t a;
    asm("{ .reg .u64 t; cvta.to.shared.u64 t, %1; cvt.u32.u64 %0, t; }" : "=r"(a) : "l"(p));
    return a;
}
__device__ __forceinline__ void split2(float x, float y, uint32_t& hi, uint32_t& lo) {
    __nv_bfloat162 h = __float22bfloat162_rn(make_float2(x, y));
    float2 hf = __bfloat1622float2(h);
    __nv_bfloat162 l = __float22bfloat162_rn(make_float2(x - hf.x, y - hf.y));
    hi = *(uint32_t*)&h; lo = *(uint32_t*)&l;
}
__device__ __forceinline__ void split_scalar(float v, __nv_bfloat16* hp, __nv_bfloat16* lp) {
    __nv_bfloat16 hb = __float2bfloat16(v);
    *hp = hb;
    *lp = __float2bfloat16(v - __bfloat162float(hb));
}

#define MMA_BF16(c, a, b)                                                        \
    asm volatile("mma.sync.aligned.m16n8k16.row.col.f32.bf16.bf16.f32 "          \
        "{%0,%1,%2,%3}, {%4,%5,%6,%7}, {%8,%9}, {%0,%1,%2,%3};"                  \
        : "+f"((c)[0]), "+f"((c)[1]), "+f"((c)[2]), "+f"((c)[3])                  \
        : "r"((a)[0]), "r"((a)[1]), "r"((a)[2]), "r"((a)[3]),                     \
          "r"((b)[0]), "r"((b)[1]))

#define LDM4(r, addr)                                                            \
    asm volatile("ldmatrix.sync.aligned.m8n8.x4.shared.b16 {%0,%1,%2,%3}, [%4];" \
        : "=r"((r)[0]), "=r"((r)[1]), "=r"((r)[2]), "=r"((r)[3]) : "r"(addr))

// =================== 3-stage pipelined bf16x3 GEMM, swizzled smem ==================
#define PLANE_U 2048
#define STAGE_U (4*PLANE_U)
#define STAGE_B (STAGE_U*4)       // 32768 bytes
#define GEMM_SMEM_V3 (3*STAGE_B)  // 98304 bytes

__global__ __launch_bounds__(256, 2)
void mma_gemm_bf16(const __nv_bfloat16* __restrict__ Ahi, const __nv_bfloat16* __restrict__ Alo,
                   const __nv_bfloat16* __restrict__ Bhi, const __nv_bfloat16* __restrict__ Blo,
                   const float* __restrict__ b0, const float* __restrict__ b1,
                   const float* __restrict__ b2,
                   float* __restrict__ C0, float* __restrict__ C1, float* __restrict__ C2,
                   __nv_bfloat16* __restrict__ Chi, __nv_bfloat16* __restrict__ Clo,
                   const float* __restrict__ Radd,
                   int M, int N, int K, int relu, int mode, int split3)
{
    extern __shared__ uint32_t sm[];
    int tid  = threadIdx.x;
    int brow = blockIdx.y * 128;
    int bcol = blockIdx.x * 128;
    int w = tid >> 5, lane = tid & 31;
    int gid = lane >> 2, tig = lane & 3;
    int moff = (w >> 1) * 32, noff = (w & 1) * 64;
    uint32_t smb = smem_u32(sm);

    int mat = lane >> 3, r8 = lane & 7;
    uint32_t aoffk[2][2], boffk[4][2];
    #pragma unroll
    for (int mt = 0; mt < 2; mt++) {
        int row = moff + mt * 16 + (mat & 1) * 8 + r8;
        int sw = (row >> 1) & 3;
        #pragma unroll
        for (int ks = 0; ks < 2; ks++) {
            int u = ks * 2 + (mat >> 1);
            aoffk[mt][ks] = (uint32_t)(row * 16 + ((u ^ sw) << 2)) * 4;
        }
    }
    #pragma unroll
    for (int p = 0; p < 4; p++) {
        int row = noff + p * 16 + (mat >> 1) * 8 + r8;
        int sw = (row >> 1) & 3;
        #pragma unroll
        for (int ks = 0; ks < 2; ks++) {
            int u = ks * 2 + (mat & 1);
            boffk[p][ks] = (uint32_t)(row * 16 + ((u ^ sw) << 2)) * 4;
        }
    }

    float acc[2][8][4] = {};
    const int NC = K >> 5;

    #pragma unroll
    for (int st = 0; st < 2; st++) {
        if (st < NC) {
            uint32_t sb = smb + (uint32_t)st * STAGE_B;
            int k0 = st * 32;
            #pragma unroll
            for (int i = 0; i < 8; i++) {
                int e  = tid + i * 256;
                int pl = e >> 9;
                int r  = (e >> 2) & 127;
                int s  = e & 3;
                const __nv_bfloat16* src;
                if      (pl == 0) src = Ahi + (size_t)(brow + r) * K + k0 + s * 8;
                else if (pl == 1) src = Alo + (size_t)(brow + r) * K + k0 + s * 8;
                else if (pl == 2) src = Bhi + (size_t)(bcol + r) * K + k0 + s * 8;
                else              src = Blo + (size_t)(bcol + r) * K + k0 + s * 8;
                uint32_t dst = sb + (uint32_t)(pl * PLANE_U + r * 16 + ((s ^ ((r >> 1) & 3)) << 2)) * 4;
                asm volatile("cp.async.cg.shared.global [%0], [%1], 16;" :: "r"(dst), "l"(src));
            }
            asm volatile("cp.async.commit_group;" ::: "memory");
        }
    }

    int stage_c = 0;
    for (int c = 0; c < NC; c++) {
        if (c + 1 < NC) {
            asm volatile("cp.async.wait_group 1;" ::: "memory");
        } else {
            asm volatile("cp.async.wait_group 0;" ::: "memory");
        }
        __syncthreads();

        if (c + 2 < NC) {
            int stage_n = stage_c + 2; if (stage_n >= 3) stage_n -= 3;
            uint32_t sb = smb + (uint32_t)stage_n * STAGE_B;
            int k0 = (c + 2) * 32;
            #pragma unroll
            for (int i = 0; i < 8; i++) {
                int e  = tid + i * 256;
                int pl = e >> 9;
                int r  = (e >> 2) & 127;
                int s  = e & 3;
                const __nv_bfloat16* src;
                if      (pl == 0) src = Ahi + (size_t)(brow + r) * K + k0 + s * 8;
                else if (pl == 1) src = Alo + (size_t)(brow + r) * K + k0 + s * 8;
                else if (pl == 2) src = Bhi + (size_t)(bcol + r) * K + k0 + s * 8;
                else              src = Blo + (size_t)(bcol + r) * K + k0 + s * 8;
                uint32_t dst = sb + (uint32_t)(pl * PLANE_U + r * 16 + ((s ^ ((r >> 1) & 3)) << 2)) * 4;
                asm volatile("cp.async.cg.shared.global [%0], [%1], 16;" :: "r"(dst), "l"(src));
            }
            asm volatile("cp.async.commit_group;" ::: "memory");
        }

        uint32_t bb = smb + (uint32_t)stage_c * STAGE_B;
        uint32_t Ahb = bb, Alb = bb + PLANE_U * 4, Bhb = bb + 2 * PLANE_U * 4, Blb = bb + 3 * PLANE_U * 4;

        #pragma unroll
        for (int ks = 0; ks < 2; ks++) {
            uint32_t afh[2][4], afl[2][4];
            #pragma unroll
            for (int mt = 0; mt < 2; mt++) {
                LDM4(afh[mt], Ahb + aoffk[mt][ks]);
                LDM4(afl[mt], Alb + aoffk[mt][ks]);
            }
            #pragma unroll
            for (int p = 0; p < 4; p++) {
                uint32_t bfh[4], bfl[4];
                LDM4(bfh, Bhb + boffk[p][ks]);
                LDM4(bfl, Blb + boffk[p][ks]);
                #pragma unroll
                for (int mt = 0; mt < 2; mt++)
                    #pragma unroll
                    for (int hf = 0; hf < 2; hf++) {
                        int nt = p * 2 + hf;
                        MMA_BF16(acc[mt][nt], afh[mt], &bfh[hf * 2]);
                        MMA_BF16(acc[mt][nt], afh[mt], &bfl[hf * 2]);
                        MMA_BF16(acc[mt][nt], afl[mt], &bfh[hf * 2]);
                    }
            }
        }
        stage_c++; if (stage_c >= 3) stage_c = 0;
    }

    float* Cf; const float* bp_; int cb, Nst;
    if (split3) {
        int mi = bcol >> 8;
        Cf  = (mi == 0) ? C0 : (mi == 1 ? C1 : C2);
        bp_ = (mi == 0) ? b0 : (mi == 1 ? b1 : b2);
        cb = bcol & 255; Nst = 256;
    } else {
        Cf = C0; bp_ = b0; cb = bcol; Nst = N;
    }

    #pragma unroll
    for (int mt = 0; mt < 2; mt++) {
        int r0 = brow + moff + mt * 16 + gid;
        #pragma unroll
        for (int nt = 0; nt < 8; nt++) {
            int c = cb + noff + nt * 8 + tig * 2;
            float bb0 = bp_[c], bb1 = bp_[c + 1];
            float2 o0 = make_float2(acc[mt][nt][0] + bb0, acc[mt][nt][1] + bb1);
            float2 o1 = make_float2(acc[mt][nt][2] + bb0, acc[mt][nt][3] + bb1);
            size_t i0 = (size_t)r0 * Nst + c;
            size_t i1 = (size_t)(r0 + 8) * Nst + c;
            if (Radd) {
                float2 ra0 = *(const float2*)(Radd + i0);
                float2 ra1 = *(const float2*)(Radd + i1);
                o0.x += ra0.x; o0.y += ra0.y;
                o1.x += ra1.x; o1.y += ra1.y;
            }
            if (relu) {
                o0.x = fmaxf(o0.x, 0.f); o0.y = fmaxf(o0.y, 0.f);
                o1.x = fmaxf(o1.x, 0.f); o1.y = fmaxf(o1.y, 0.f);
            }
            if (mode & 1) {
                *(float2*)(Cf + i0) = o0;
                *(float2*)(Cf + i1) = o1;
            }
            if (mode & 2) {
                uint32_t h0, l0, h1, l1;
                split2(o0.x, o0.y, h0, l0);
                split2(o1.x, o1.y, h1, l1);
                *(uint32_t*)(Chi + i0) = h0; *(uint32_t*)(Clo + i0) = l0;
                *(uint32_t*)(Chi + i1) = h1; *(uint32_t*)(Clo + i1) = l1;
            }
        }
    }
}

// ---------------- batched transpose+split of ALL weights --------------------------
__global__ void transpose_all_kernel(const float* __restrict__ w_in,
                                     const float* __restrict__ wq, const float* __restrict__ wk,
                                     const float* __restrict__ wv, const float* __restrict__ wo,
                                     const float* __restrict__ f1, const float* __restrict__ f2,
                                     __nv_bfloat16* __restrict__ hi, __nv_bfloat16* __restrict__ lo)
{
    const int start[14] = {0, 8, 72, 136, 200, 264, 520, 776, 840, 904, 968, 1032, 1288, 1544};
    int t = blockIdx.x;
    int m = 0;
    #pragma unroll
    for (int i = 1; i < 14; i++) if (t >= start[i]) m = i;
    int layer = (m >= 7) ? 1 : 0;
    int mi = (m == 0) ? 0 : ((m - 1) % 6) + 1;
    const float* src; int K, N; size_t dst;
    size_t base = (size_t)FIN * D + (size_t)layer * LYR_SZ;
    switch (mi) {
        case 0: src = w_in;                          K = FIN; N = D;   dst = 0;             break;
        case 1: src = wq + (size_t)layer * D * D;    K = D;   N = D;   dst = base;          break;
        case 2: src = wk + (size_t)layer * D * D;    K = D;   N = D;   dst = base + 65536;  break;
        case 3: src = wv + (size_t)layer * D * D;    K = D;   N = D;   dst = base + 131072; break;
        case 4: src = wo + (size_t)layer * D * D;    K = D;   N = D;   dst = base + 196608; break;
        case 5: src = f1 + (size_t)layer * D * DFF;  K = D;   N = DFF; dst = base + 262144; break;
        default:src = f2 + (size_t)layer * DFF * D;  K = DFF; N = D;   dst = base + 524288; break;
    }
    int lt = t - start[m];
    int ntn = N >> 5;
    int nb = (lt % ntn) << 5, kb = (lt / ntn) << 5;

    __shared__ float tbuf[32][33];
    int tx = threadIdx.x, ty = threadIdx.y;
    #pragma unroll
    for (int i = ty; i < 32; i += 8)
        tbuf[i][tx] = src[(size_t)(kb + i) * N + nb + tx];
    __syncthreads();
    #pragma unroll
    for (int i = ty; i < 32; i += 8) {
        float v = tbuf[tx][i];
        size_t o = dst + (size_t)(nb + i) * K + kb + tx;
        split_scalar(v, hi + o, lo + o);
    }
}

// ---------------- plain split ------------------------------------------------------
__global__ void split_kernel(const float* __restrict__ in,
                             __nv_bfloat16* __restrict__ hi,
                             __nv_bfloat16* __restrict__ lo, int n)
{
    int i = (blockIdx.x * blockDim.x + threadIdx.x) * 2;
    if (i >= n) return;
    float2 v = *(const float2*)(in + i);
    uint32_t h, l;
    split2(v.x, v.y, h, l);
    *(uint32_t*)(hi + i) = h;
    *(uint32_t*)(lo + i) = l;
}

// ---------------- fused sampled-QK M-score + v-mean (FIXED grid) -------------------
#define QK_BLOCKS (B_*H_*L_/8)     // 16384 blocks of 8 warps, one warp per (b,h,l)
__global__ void qkvm_kernel(const float* __restrict__ q, const float* __restrict__ k,
                            const int* __restrict__ idx, float* __restrict__ Mout,
                            const float* __restrict__ v, float* __restrict__ vm)
{
    if (blockIdx.x < QK_BLOCKS) {
        int gw   = (blockIdx.x * blockDim.x + threadIdx.x) >> 5;
        int lane = threadIdx.x & 31;
        int l  = gw & (L_ - 1);
        int bh = gw >> 11;
        int b  = bh >> 3, h = bh & 7;

        int d2 = lane & 15, sh = lane >> 4;
        float2 q2 = *(const float2*)(q + ((size_t)b * L_ + l) * D + h * DH + 2 * d2);
        const float* kbase = k + (size_t)b * L_ * D + h * DH;
        const int*   irow  = idx + l * S_;

        float mx = -1e30f, sm = 0.0f;
        #pragma unroll 4
        for (int s0 = 0; s0 < S_; s0 += 2) {
            int ki = __ldg(&irow[s0 + sh]);
            float2 kv = *(const float2*)(kbase + (size_t)ki * D + 2 * d2);
            float p = q2.x * kv.x + q2.y * kv.y;
            p += __shfl_xor_sync(0xffffffffu, p, 1);
            p += __shfl_xor_sync(0xffffffffu, p, 2);
            p += __shfl_xor_sync(0xffffffffu, p, 4);
            p += __shfl_xor_sync(0xffffffffu, p, 8);
            mx = fmaxf(mx, p);
            sm += p;
        }
        mx = fmaxf(mx, __shfl_xor_sync(0xffffffffu, mx, 16));
        sm += __shfl_xor_sync(0xffffffffu, sm, 16);
        if (lane == 0) Mout[gw] = mx - sm * (1.0f / (float)L_);
    } else {
        int bh = blockIdx.x - QK_BLOCKS; int b = bh >> 3, h = bh & 7;
        int tid = threadIdx.x;
        int d = tid & 31, seg = tid >> 5;
        const float* vb = v + (size_t)b * L_ * D + h * DH + d;
        float acc = 0.0f;
        for (int l = seg; l < L_; l += 8) acc += vb[(size_t)l * D];
        __shared__ float sp[8][32];
        sp[seg][d] = acc;
        __syncthreads();
        if (tid < 32) {
            float s = 0.0f;
            #pragma unroll
            for (int i = 0; i < 8; i++) s += sp[i][tid];
            vm[bh * DH + tid] = s * (1.0f / (float)L_);
        }
    }
}

// ---------------- top-40 per (b,h) -------------------------------------------------
__global__ void topk_kernel(const float* __restrict__ Mv, int* __restrict__ top)
{
    int bh  = blockIdx.x;
    int tid = threadIdx.x;
    int w = tid >> 5, lane = tid & 31;
    __shared__ float sv[L_];
    __shared__ float wv_[8];
    __shared__ int   wi_[8];
    for (int i = tid; i < L_; i += 256) sv[i] = Mv[(size_t)bh * L_ + i];
    __syncthreads();

    for (int r = 0; r < U_; r++) {
        float bv = -1e30f; int bi = 0x7fffffff;
        #pragma unroll
        for (int j = 0; j < 8; j++) {
            int i = tid + j * 256;
            float v = sv[i];
            if (v > bv || (v == bv && i < bi)) { bv = v; bi = i; }
        }
        #pragma unroll
        for (int o = 16; o; o >>= 1) {
            float ov = __shfl_xor_sync(0xffffffffu, bv, o);
            int   oi = __shfl_xor_sync(0xffffffffu, bi, o);
            if (ov > bv || (ov == bv && oi < bi)) { bv = ov; bi = oi; }
        }
        if (lane == 0) { wv_[w] = bv; wi_[w] = bi; }
        __syncthreads();
        if (tid == 0) {
            float fv = wv_[0]; int fi = wi_[0];
            #pragma unroll
            for (int j = 1; j < 8; j++) {
                float ov = wv_[j]; int oi = wi_[j];
                if (ov > fv || (ov == fv && oi < fi)) { fv = ov; fi = oi; }
            }
            top[bh * U_ + r] = fi;
            sv[fi] = -1e30f;
        }
        __syncthreads();
    }
}

// ---------------- fill ctx planes with broadcast v-mean (layer 0 only) -------------
__global__ void ctxfill_kernel(const float* __restrict__ vm,
                               __nv_bfloat16* __restrict__ chi,
                               __nv_bfloat16* __restrict__ clo)
{
    int i4 = (blockIdx.x * blockDim.x + threadIdx.x) * 4;
    if (i4 >= B_ * L_ * D) return;
    int dfull = i4 & (D - 1);
    int b = i4 / (L_ * D);
    int h = dfull >> 5, d = dfull & 31;
    float4 v = *(const float4*)(vm + ((b << 3) + h) * DH + d);
    uint32_t h01, h23, l01, l23;
    split2(v.x, v.y, h01, l01);
    split2(v.z, v.w, h23, l23);
    *(uint2*)(chi + i4) = make_uint2(h01, h23);
    *(uint2*)(clo + i4) = make_uint2(l01, l23);
}

// ---------------- flash-style reduced attention (layer 0 only) ---------------------
__global__ __launch_bounds__(256, 1)
void attn_topq_flash(const float* __restrict__ q, const float* __restrict__ k,
                     const float* __restrict__ v, const int* __restrict__ top,
                     __nv_bfloat16* __restrict__ chi, __nv_bfloat16* __restrict__ clo)
{
    __shared__ float Ks[128][33];
    __shared__ float Vs[128][33];
    __shared__ float qs[40][32];
    __shared__ float ps[8][128];
    __shared__ int   stop[40];

    int bh = blockIdx.x; int b = bh >> 3, h = bh & 7;
    int tid = threadIdx.x, w = tid >> 5, lane = tid & 31;

    if (tid < 40) stop[tid] = top[bh * U_ + tid];
    __syncthreads();
    for (int i = tid; i < 40 * 32; i += 256) {
        int u = i >> 5, d = i & 31;
        qs[u][d] = q[((size_t)b * L_ + stop[u]) * D + h * DH + d];
    }

    float m[5], l[5], acc[5];
    #pragma unroll
    for (int j = 0; j < 5; j++) { m[j] = -1e30f; l[j] = 0.f; acc[j] = 0.f; }
    const float scale = 0.1767766952966369f;
    const float* kb = k + (size_t)b * L_ * D + h * DH;
    const float* vb = v + (size_t)b * L_ * D + h * DH;
    __syncthreads();

    for (int t0 = 0; t0 < L_; t0 += 128) {
        for (int i = tid; i < 128 * 32; i += 256) {
            int r = i >> 5, d = i & 31;
            Ks[r][d] = kb[(size_t)(t0 + r) * D + d];
            Vs[r][d] = vb[(size_t)(t0 + r) * D + d];
        }
        __syncthreads();

        float sj[5][4];
        #pragma unroll
        for (int j = 0; j < 5; j++)
            #pragma unroll
            for (int i = 0; i < 4; i++) sj[j][i] = 0.f;
        #pragma unroll
        for (int d = 0; d < 32; d++) {
            float k0v = Ks[lane][d], k1v = Ks[lane + 32][d];
            float k2v = Ks[lane + 64][d], k3v = Ks[lane + 96][d];
            #pragma unroll
            for (int j = 0; j < 5; j++) {
                float qd = qs[w * 5 + j][d];
                sj[j][0] = fmaf(qd, k0v, sj[j][0]);
                sj[j][1] = fmaf(qd, k1v, sj[j][1]);
                sj[j][2] = fmaf(qd, k2v, sj[j][2]);
                sj[j][3] = fmaf(qd, k3v, sj[j][3]);
            }
        }
        #pragma unroll
        for (int j = 0; j < 5; j++) {
            float s0 = sj[j][0] * scale, s1 = sj[j][1] * scale;
            float s2 = sj[j][2] * scale, s3 = sj[j][3] * scale;
            float tm = fmaxf(fmaxf(s0, s1), fmaxf(s2, s3));
            #pragma unroll
            for (int o = 16; o; o >>= 1) tm = fmaxf(tm, __shfl_xor_sync(0xffffffffu, tm, o));
            float mn   = fmaxf(m[j], tm);
            float corr = __expf(m[j] - mn);
            float p0 = __expf(s0 - mn), p1 = __expf(s1 - mn);
            float p2 = __expf(s2 - mn), p3 = __expf(s3 - mn);
            float psum = p0 + p1 + p2 + p3;
            #pragma unroll
            for (int o = 16; o; o >>= 1) psum += __shfl_xor_sync(0xffffffffu, psum, o);
            l[j] = l[j] * corr + psum;
            m[j] = mn;
            ps[w][lane] = p0; ps[w][lane + 32] = p1; ps[w][lane + 64] = p2; ps[w][lane + 96] = p3;
            __syncwarp();
            float aa = acc[j] * corr;
            const float4* pv4 = (const float4*)ps[w];
            #pragma unroll 8
            for (int kk4 = 0; kk4 < 32; kk4++) {
                float4 p4 = pv4[kk4];
                int kk = kk4 * 4;
                aa = fmaf(p4.x, Vs[kk][lane],     aa);
                aa = fmaf(p4.y, Vs[kk + 1][lane], aa);
                aa = fmaf(p4.z, Vs[kk + 2][lane], aa);
                aa = fmaf(p4.w, Vs[kk + 3][lane], aa);
            }
            acc[j] = aa;
            __syncwarp();
        }
        __syncthreads();
    }
    #pragma unroll
    for (int j = 0; j < 5; j++) {
        int u = w * 5 + j;
        float o = acc[j] / l[j];
        size_t off = ((size_t)b * L_ + stop[u]) * D + h * DH + lane;
        split_scalar(o, chi + off, clo + off);
    }
}

// ---------- LayerNorm of pre-summed input + split -----------------------------------
__global__ void add_ln_kernel(const float* __restrict__ sum,
                              const float* __restrict__ g, const float* __restrict__ bb,
                              float* __restrict__ hout,
                              __nv_bfloat16* __restrict__ hhi, __nv_bfloat16* __restrict__ hlo)
{
    int tid = threadIdx.x;
    int rl  = tid >> 7;
    int ct  = tid & 127;
    int row = blockIdx.x * 2 + rl;
    size_t off = (size_t)row * D + ct * 2;
    float2 v = *(const float2*)(sum + off);
    float s1 = v.x + v.y, s2 = v.x * v.x + v.y * v.y;
    #pragma unroll
    for (int o = 16; o; o >>= 1) {
        s1 += __shfl_xor_sync(0xffffffffu, s1, o);
        s2 += __shfl_xor_sync(0xffffffffu, s2, o);
    }
    __shared__ float a1[2][4], a2[2][4], mu[2], rv[2];
    int wr = (tid >> 5) & 3;
    int lane = tid & 31;
    if (lane == 0) { a1[rl][wr] = s1; a2[rl][wr] = s2; }
    __syncthreads();
    if (ct == 0) {
        float t1 = a1[rl][0] + a1[rl][1] + a1[rl][2] + a1[rl][3];
        float t2 = a2[rl][0] + a2[rl][1] + a2[rl][2] + a2[rl][3];
        float m = t1 * (1.0f / (float)D);
        float var = t2 * (1.0f / (float)D) - m * m;
        mu[rl] = m;
        rv[rl] = rsqrtf(var + 1e-5f);
    }
    __syncthreads();
    float m = mu[rl], r = rv[rl];
    float2 gg = *(const float2*)(g + ct * 2);
    float2 b2 = *(const float2*)(bb + ct * 2);
    float2 o;
    o.x = (v.x - m) * r * gg.x + b2.x;
    o.y = (v.y - m) * r * gg.y + b2.y;
    *(float2*)(hout + off) = o;
    uint32_t hi32, lo32;
    split2(o.x, o.y, hi32, lo32);
    *(uint32_t*)(hhi + off) = hi32;
    *(uint32_t*)(hlo + off) = lo32;
}

// --------- last-layer attention for row L-1 only: ctxl = attn or v-mean ------------
__global__ __launch_bounds__(256, 1)
void last_attn_kernel(const float* __restrict__ q, const float* __restrict__ k,
                      const float* __restrict__ v, const int* __restrict__ top,
                      const float* __restrict__ vm, float* __restrict__ ctxl)
{
    int bh = blockIdx.x; int b = bh >> 3, h = bh & 7;
    int tid = threadIdx.x;
    __shared__ int memb;
    __shared__ float qs[DH];
    __shared__ float sc[L_];
    __shared__ float red[256];
    __shared__ float part[8][DH];

    if (tid == 0) memb = 0;
    __syncthreads();
    if (tid < U_ && top[bh * U_ + tid] == (L_ - 1)) memb = 1;
    __syncthreads();
    if (!memb) {
        if (tid < DH) ctxl[bh * DH + tid] = vm[bh * DH + tid];
        return;
    }

    if (tid < DH) qs[tid] = q[((size_t)b * L_ + (L_ - 1)) * D + h * DH + tid];
    __syncthreads();

    const float* kb = k + (size_t)b * L_ * D + h * DH;
    const float scale = 0.1767766952966369f;
    float lmax = -1e30f;
    for (int l = tid; l < L_; l += 256) {
        const float4* kr = (const float4*)(kb + (size_t)l * D);
        float dot = 0.0f;
        #pragma unroll
        for (int j = 0; j < 8; j++) {
            float4 kv = __ldg(&kr[j]);
            dot += qs[4*j+0]*kv.x + qs[4*j+1]*kv.y + qs[4*j+2]*kv.z + qs[4*j+3]*kv.w;
        }
        dot *= scale;
        sc[l] = dot;
        lmax = fmaxf(lmax, dot);
    }
    red[tid] = lmax; __syncthreads();
    for (int s = 128; s; s >>= 1) { if (tid < s) red[tid] = fmaxf(red[tid], red[tid + s]); __syncthreads(); }
    float gmax = red[0];
    __syncthreads();
    float lsum = 0.0f;
    for (int l = tid; l < L_; l += 256) {
        float e = __expf(sc[l] - gmax);
        sc[l] = e;
        lsum += e;
    }
    red[tid] = lsum; __syncthreads();
    for (int s = 128; s; s >>= 1) { if (tid < s) red[tid] += red[tid + s]; __syncthreads(); }
    float inv = 1.0f / red[0];
    __syncthreads();

    int d = tid & 31, seg = tid >> 5;
    const float* vb = v + (size_t)b * L_ * D + h * DH + d;
    float acc = 0.0f;
    for (int l = seg; l < L_; l += 8) acc += sc[l] * vb[(size_t)l * D];
    part[seg][d] = acc;
    __syncthreads();
    if (tid < DH) {
        float s = 0.0f;
        #pragma unroll
        for (int i = 0; i < 8; i++) s += part[i][tid];
        ctxl[bh * DH + tid] = s * inv;
    }
}

// --------- final chain for row L-1: wo+LN+FFN+LN+head, all fp32, 1 block/b ---------
__global__ __launch_bounds__(256, 1)
void final_head_kernel(const float* __restrict__ h, const float* __restrict__ ctxl,
                       const float* __restrict__ wo2, const float* __restrict__ bo2,
                       const float* __restrict__ ln1g, const float* __restrict__ ln1b,
                       const float* __restrict__ ff1, const float* __restrict__ bf1,
                       const float* __restrict__ ff2, const float* __restrict__ bf2,
                       const float* __restrict__ ln2g, const float* __restrict__ ln2b,
                       const float* __restrict__ w1, const float* __restrict__ b1,
                       const float* __restrict__ w2, const float* __restrict__ b2,
                       float* __restrict__ out)
{
    int b = blockIdx.x;
    int tid = threadIdx.x;
    int w = tid >> 5, lane = tid & 31;
    __shared__ float row[D], ctxr[D], hb1[D], yb[DFF], hb2[D];
    __shared__ float a1[8], a2[8], stat[2];

    row[tid]  = h[((size_t)b * L_ + (L_ - 1)) * D + tid];
    ctxr[tid] = ctxl[b * D + tid];
    __syncthreads();

    // nx = ctx @ wo2 + bo2 ; val = row + nx
    float acc = bo2[tid];
    for (int dd = 0; dd < D; dd++) acc = fmaf(ctxr[dd], wo2[dd * D + tid], acc);
    float val = row[tid] + acc;

    // LN1
    {
        float s1 = val, s2 = val * val;
        #pragma unroll
        for (int o = 16; o; o >>= 1) {
            s1 += __shfl_xor_sync(0xffffffffu, s1, o);
            s2 += __shfl_xor_sync(0xffffffffu, s2, o);
        }
        if (lane == 0) { a1[w] = s1; a2[w] = s2; }
        __syncthreads();
        if (tid == 0) {
            float t1 = 0.f, t2 = 0.f;
            #pragma unroll
            for (int j = 0; j < 8; j++) { t1 += a1[j]; t2 += a2[j]; }
            float mu = t1 * (1.0f / (float)D);
            stat[0] = mu;
            stat[1] = rsqrtf(t2 * (1.0f / (float)D) - mu * mu + 1e-5f);
        }
        __syncthreads();
        hb1[tid] = (val - stat[0]) * stat[1] * ln1g[tid] + ln1b[tid];
        __syncthreads();
    }

    // y = relu(hb1 @ ff1 + bf1)   (DFF outputs, 4 per thread)
    #pragma unroll
    for (int jj = 0; jj < 4; jj++) {
        int j = tid + jj * 256;
        float a = bf1[j];
        for (int dd = 0; dd < D; dd++) a = fmaf(hb1[dd], ff1[(size_t)dd * DFF + j], a);
        yb[j] = fmaxf(a, 0.0f);
    }
    __syncthreads();

    // val2 = hb1 + y @ ff2 + bf2 ; LN2
    float acc2 = bf2[tid];
    for (int dd = 0; dd < DFF; dd++) acc2 = fmaf(yb[dd], ff2[(size_t)dd * D + tid], acc2);
    float val2 = hb1[tid] + acc2;
    {
        float s1 = val2, s2 = val2 * val2;
        #pragma unroll
        for (int o = 16; o; o >>= 1) {
            s1 += __shfl_xor_sync(0xffffffffu, s1, o);
            s2 += __shfl_xor_sync(0xffffffffu, s2, o);
        }
        __syncthreads();
        if (lane == 0) { a1[w] = s1; a2[w] = s2; }
        __syncthreads();
        if (tid == 0) {
            float t1 = 0.f, t2 = 0.f;
            #pragma unroll
            for (int j = 0; j < 8; j++) { t1 += a1[j]; t2 += a2[j]; }
            float mu = t1 * (1.0f / (float)D);
            stat[0] = mu;
            stat[1] = rsqrtf(t2 * (1.0f / (float)D) - mu * mu + 1e-5f);
        }
        __syncthreads();
        hb2[tid] = (val2 - stat[0]) * stat[1] * ln2g[tid] + ln2b[tid];
        __syncthreads();
    }

    // head
    __shared__ float th[64];
    if (tid < 64) {
        float a = b1[tid];
        for (int dd = 0; dd < D; dd++) a = fmaf(hb2[dd], w1[dd * 64 + tid], a);
        th[tid] = fmaxf(a, 0.0f) * w2[tid];
    }
    __syncthreads();
    if (tid < 32) {
        float s = th[tid] + th[tid + 32];
        #pragma unroll
        for (int o = 16; o; o >>= 1) s += __shfl_xor_sync(0xffffffffu, s, o);
        if (tid == 0) out[b] = s + b2[0];
    }
}

// ===================================================================================
extern "C" void kernel_launch(void* const* d_in, const int* in_sizes, int n_in,
                              void* d_out, int out_size)
{
    const float* x     = (const float*)d_in[0];
    const int*   idx   = (const int*)  d_in[1];
    const float* w_in  = (const float*)d_in[2];
    const float* b_in  = (const float*)d_in[3];
    const float* wq    = (const float*)d_in[4];
    const float* bq    = (const float*)d_in[5];
    const float* wk    = (const float*)d_in[6];
    const float* bk    = (const float*)d_in[7];
    const float* wv    = (const float*)d_in[8];
    const float* bv    = (const float*)d_in[9];
    const float* wo    = (const float*)d_in[10];
    const float* bo    = (const float*)d_in[11];
    const float* w_ff1 = (const float*)d_in[12];
    const float* b_ff1 = (const float*)d_in[13];
    const float* w_ff2 = (const float*)d_in[14];
    const float* b_ff2 = (const float*)d_in[15];
    const float* ln1_g = (const float*)d_in[16];
    const float* ln1_b = (const float*)d_in[17];
    const float* ln2_g = (const float*)d_in[18];
    const float* ln2_b = (const float*)d_in[19];
    const float* w_fc1 = (const float*)d_in[20];
    const float* b_fc1 = (const float*)d_in[21];
    const float* w_fc2 = (const float*)d_in[22];
    const float* b_fc2 = (const float*)d_in[23];
    float* out = (float*)d_out;

    float *h, *q, *k, *v, *nx, *Mv, *vm, *ctxl; int* top;
    __nv_bfloat16 *xhi, *xlo, *hhi, *hlo, *chi, *clo, *fhi, *flo, *whi, *wlo;
    cudaGetSymbolAddress((void**)&h,   g_h);
    cudaGetSymbolAddress((void**)&q,   g_q);
    cudaGetSymbolAddress((void**)&k,   g_k);
    cudaGetSymbolAddress((void**)&v,   g_v);
    cudaGetSymbolAddress((void**)&nx,  g_nx);
    cudaGetSymbolAddress((void**)&Mv,  g_M);
    cudaGetSymbolAddress((void**)&top, g_top);
    cudaGetSymbolAddress((void**)&vm,  g_vm);
    cudaGetSymbolAddress((void**)&ctxl, g_ctxl);
    cudaGetSymbolAddress((void**)&xhi, g_x_hi);  cudaGetSymbolAddress((void**)&xlo, g_x_lo);
    cudaGetSymbolAddress((void**)&hhi, g_h_hi);  cudaGetSymbolAddress((void**)&hlo, g_h_lo);
    cudaGetSymbolAddress((void**)&chi, g_ctx_hi); cudaGetSymbolAddress((void**)&clo, g_ctx_lo);
    cudaGetSymbolAddress((void**)&fhi, g_ff_hi); cudaGetSymbolAddress((void**)&flo, g_ff_lo);
    cudaGetSymbolAddress((void**)&whi, g_wt_hi); cudaGetSymbolAddress((void**)&wlo, g_wt_lo);

    cudaFuncSetAttribute(mma_gemm_bf16, cudaFuncAttributeMaxDynamicSharedMemorySize, GEMM_SMEM_V3);

    const int Mrows = B_ * L_;
    dim3 gD  (D / 128,   Mrows / 128);
    dim3 gQKV(3 * D / 128, Mrows / 128);
    dim3 gFF (DFF / 128, Mrows / 128);
    dim3 tb(32, 8);

    const size_t o_in = 0;
    auto o_q  = [&](int l){ return (size_t)FIN * D + (size_t)l * LYR_SZ; };
    auto o_o  = [&](int l){ return o_q(l) + 196608; };
    auto o_f1 = [&](int l){ return o_q(l) + 262144; };
    auto o_f2 = [&](int l){ return o_q(l) + 524288; };

    split_kernel<<<(B_ * L_ * FIN) / 512, 256>>>(x, xhi, xlo, B_ * L_ * FIN);
    transpose_all_kernel<<<1544, tb>>>(w_in, wq, wk, wv, wo, w_ff1, w_ff2, whi, wlo);
    mma_gemm_bf16<<<gD, 256, GEMM_SMEM_V3>>>(xhi, xlo, whi + o_in, wlo + o_in,
        b_in, nullptr, nullptr, h, nullptr, nullptr, hhi, hlo, nullptr, Mrows, D, FIN, 0, 3, 0);

    // ---------------- layer 0 (full) ----------------
    {
        const int layer = 0;
        const int* ixL = idx;

        mma_gemm_bf16<<<gQKV, 256, GEMM_SMEM_V3>>>(hhi, hlo, whi + o_q(layer), wlo + o_q(layer),
            bq, bk, bv, q, k, v, nullptr, nullptr, nullptr, Mrows, 768, D, 0, 1, 1);

        qkvm_kernel<<<QK_BLOCKS + B_ * H_, 256>>>(q, k, ixL, Mv, v, vm);
        topk_kernel<<<B_ * H_, 256>>>(Mv, top);
        ctxfill_kernel<<<(B_ * L_ * D) / 1024, 256>>>(vm, chi, clo);
        attn_topq_flash<<<B_ * H_, 256>>>(q, k, v, top, chi, clo);

        mma_gemm_bf16<<<gD, 256, GEMM_SMEM_V3>>>(chi, clo, whi + o_o(layer), wlo + o_o(layer),
            bo, nullptr, nullptr, nx, nullptr, nullptr, nullptr, nullptr, h,
            Mrows, D, D, 0, 1, 0);
        add_ln_kernel<<<Mrows / 2, 256>>>(nx, ln1_g, ln1_b, h, hhi, hlo);

        mma_gemm_bf16<<<gFF, 256, GEMM_SMEM_V3>>>(hhi, hlo, whi + o_f1(layer), wlo + o_f1(layer),
            b_ff1, nullptr, nullptr, nullptr, nullptr, nullptr, fhi, flo, nullptr,
            Mrows, DFF, D, 1, 2, 0);
        mma_gemm_bf16<<<gD, 256, GEMM_SMEM_V3>>>(fhi, flo, whi + o_f2(layer), wlo + o_f2(layer),
            b_ff2, nullptr, nullptr, nx, nullptr, nullptr, nullptr, nullptr, h,
            Mrows, D, DFF, 0, 1, 0);
        add_ln_kernel<<<Mrows / 2, 256>>>(nx, ln2_g, ln2_b, h, hhi, hlo);
    }

    // ---------------- layer 1 (output-funnel pruned) ----------------
    {
        const int layer = 1;
        const int* ixL = idx + (size_t)L_ * S_;

        mma_gemm_bf16<<<gQKV, 256, GEMM_SMEM_V3>>>(hhi, hlo, whi + o_q(layer), wlo + o_q(layer),
            bq + D, bk + D, bv + D, q, k, v, nullptr, nullptr, nullptr, Mrows, 768, D, 0, 1, 1);

        qkvm_kernel<<<QK_BLOCKS + B_ * H_, 256>>>(q, k, ixL, Mv, v, vm);
        topk_kernel<<<B_ * H_, 256>>>(Mv, top);
        last_attn_kernel<<<B_ * H_, 256>>>(q, k, v, top, vm, ctxl);

        final_head_kernel<<<B_, 256>>>(h, ctxl,
            wo + (size_t)D * D, bo + D,
            ln1_g + D, ln1_b + D,
            w_ff1 + (size_t)D * DFF, b_ff1 + DFF,
            w_ff2 + (size_t)DFF * D, b_ff2 + D,
            ln2_g + D, ln2_b + D,
            w_fc1, b_fc1, w_fc2, b_fc2, out);
    }
}

// round 10
// speedup vs baseline: 4.2763x; 1.1538x over previous
#include <cuda_runtime.h>
#include <cuda_bf16.h>
#include <cstdint>
#include <math.h>

// Problem constants
#define B_   8
#define L_   2048
#define FIN  32
#define D    256
#define H_   8
#define DH   32
#define DFF  1024
#define S_   40
#define U_   40
#define NL   2

// ---------------- scratch (device globals; no allocation allowed) ----------------
__device__ float g_h  [B_*L_*D];
__device__ float g_q  [B_*L_*D];
__device__ float g_k  [B_*L_*D];
__device__ float g_v  [B_*L_*D];
__device__ float g_nx [B_*L_*D];
__device__ float g_M  [B_*H_*L_];
__device__ int   g_top[B_*H_*U_];
__device__ float g_vm [B_*H_*DH];
__device__ float g_ctxl[B_*H_*DH];
// split-KV attention partials: 64 bh x 4 splits x 40 queries
__device__ float g_am[B_*H_*4*U_];
__device__ float g_al[B_*H_*4*U_];
__device__ float g_av[B_*H_*4*U_*DH];

// bf16 hi/lo planes
__device__ __nv_bfloat16 g_x_hi [B_*L_*FIN], g_x_lo [B_*L_*FIN];
__device__ __nv_bfloat16 g_h_hi [B_*L_*D],   g_h_lo [B_*L_*D];
__device__ __nv_bfloat16 g_ctx_hi[B_*L_*D],  g_ctx_lo[B_*L_*D];
__device__ __nv_bfloat16 g_ff_hi[B_*L_*DFF], g_ff_lo[B_*L_*DFF];
#define LYR_SZ   786432
#define WT_TOTAL (FIN*D + NL*LYR_SZ)
__device__ __nv_bfloat16 g_wt_hi[WT_TOTAL], g_wt_lo[WT_TOTAL];

// =========================== helpers ===============================================
__device__ __forceinline__ uint32_t smem_u32(const void* p) {
    uint32_t a;
    asm("{ .reg .u64 t; cvta.to.shared.u64 t, %1; cvt.u32.u64 %0, t; }" : "=r"(a) : "l"(p));
    return a;
}
__device__ __forceinline__ void split2(float x, float y, uint32_t& hi, uint32_t& lo) {
    __nv_bfloat162 h = __float22bfloat162_rn(make_float2(x, y));
    float2 hf = __bfloat1622float2(h);
    __nv_bfloat162 l = __float22bfloat162_rn(make_float2(x - hf.x, y - hf.y));
    hi = *(uint32_t*)&h; lo = *(uint32_t*)&l;
}
__device__ __forceinline__ void split_scalar(float v, __nv_bfloat16* hp, __nv_bfloat16* lp) {
    __nv_bfloat16 hb = __float2bfloat16(v);
    *hp = hb;
    *lp = __float2bfloat16(v - __bfloat162float(hb));
}

#define MMA_BF16(c, a, b)                                                        \
    asm volatile("mma.sync.aligned.m16n8k16.row.col.f32.bf16.bf16.f32 "          \
        "{%0,%1,%2,%3}, {%4,%5,%6,%7}, {%8,%9}, {%0,%1,%2,%3};"                  \
        : "+f"((c)[0]), "+f"((c)[1]), "+f"((c)[2]), "+f"((c)[3])                  \
        : "r"((a)[0]), "r"((a)[1]), "r"((a)[2]), "r"((a)[3]),                     \
          "r"((b)[0]), "r"((b)[1]))

#define LDM4(r, addr)                                                            \
    asm volatile("ldmatrix.sync.aligned.m8n8.x4.shared.b16 {%0,%1,%2,%3}, [%4];" \
        : "=r"((r)[0]), "=r"((r)[1]), "=r"((r)[2]), "=r"((r)[3]) : "r"(addr))

// =================== 3-stage pipelined bf16x3 GEMM, swizzled smem ==================
#define PLANE_U 2048
#define STAGE_U (4*PLANE_U)
#define STAGE_B (STAGE_U*4)       // 32768 bytes
#define GEMM_SMEM_V3 (3*STAGE_B)  // 98304 bytes

__global__ __launch_bounds__(256, 2)
void mma_gemm_bf16(const __nv_bfloat16* __restrict__ Ahi, const __nv_bfloat16* __restrict__ Alo,
                   const __nv_bfloat16* __restrict__ Bhi, const __nv_bfloat16* __restrict__ Blo,
                   const float* __restrict__ b0, const float* __restrict__ b1,
                   const float* __restrict__ b2,
                   float* __restrict__ C0, float* __restrict__ C1, float* __restrict__ C2,
                   __nv_bfloat16* __restrict__ Chi, __nv_bfloat16* __restrict__ Clo,
                   const float* __restrict__ Radd,
                   int M, int N, int K, int relu, int mode, int split3)
{
    extern __shared__ uint32_t sm[];
    int tid  = threadIdx.x;
    int brow = blockIdx.y * 128;
    int bcol = blockIdx.x * 128;
    int w = tid >> 5, lane = tid & 31;
    int gid = lane >> 2, tig = lane & 3;
    int moff = (w >> 1) * 32, noff = (w & 1) * 64;
    uint32_t smb = smem_u32(sm);

    int mat = lane >> 3, r8 = lane & 7;
    uint32_t aoffk[2][2], boffk[4][2];
    #pragma unroll
    for (int mt = 0; mt < 2; mt++) {
        int row = moff + mt * 16 + (mat & 1) * 8 + r8;
        int sw = (row >> 1) & 3;
        #pragma unroll
        for (int ks = 0; ks < 2; ks++) {
            int u = ks * 2 + (mat >> 1);
            aoffk[mt][ks] = (uint32_t)(row * 16 + ((u ^ sw) << 2)) * 4;
        }
    }
    #pragma unroll
    for (int p = 0; p < 4; p++) {
        int row = noff + p * 16 + (mat >> 1) * 8 + r8;
        int sw = (row >> 1) & 3;
        #pragma unroll
        for (int ks = 0; ks < 2; ks++) {
            int u = ks * 2 + (mat & 1);
            boffk[p][ks] = (uint32_t)(row * 16 + ((u ^ sw) << 2)) * 4;
        }
    }

    float acc[2][8][4] = {};
    const int NC = K >> 5;

    #pragma unroll
    for (int st = 0; st < 2; st++) {
        if (st < NC) {
            uint32_t sb = smb + (uint32_t)st * STAGE_B;
            int k0 = st * 32;
            #pragma unroll
            for (int i = 0; i < 8; i++) {
                int e  = tid + i * 256;
                int pl = e >> 9;
                int r  = (e >> 2) & 127;
                int s  = e & 3;
                const __nv_bfloat16* src;
                if      (pl == 0) src = Ahi + (size_t)(brow + r) * K + k0 + s * 8;
                else if (pl == 1) src = Alo + (size_t)(brow + r) * K + k0 + s * 8;
                else if (pl == 2) src = Bhi + (size_t)(bcol + r) * K + k0 + s * 8;
                else              src = Blo + (size_t)(bcol + r) * K + k0 + s * 8;
                uint32_t dst = sb + (uint32_t)(pl * PLANE_U + r * 16 + ((s ^ ((r >> 1) & 3)) << 2)) * 4;
                asm volatile("cp.async.cg.shared.global [%0], [%1], 16;" :: "r"(dst), "l"(src));
            }
            asm volatile("cp.async.commit_group;" ::: "memory");
        }
    }

    int stage_c = 0;
    for (int c = 0; c < NC; c++) {
        if (c + 1 < NC) {
            asm volatile("cp.async.wait_group 1;" ::: "memory");
        } else {
            asm volatile("cp.async.wait_group 0;" ::: "memory");
        }
        __syncthreads();

        if (c + 2 < NC) {
            int stage_n = stage_c + 2; if (stage_n >= 3) stage_n -= 3;
            uint32_t sb = smb + (uint32_t)stage_n * STAGE_B;
            int k0 = (c + 2) * 32;
            #pragma unroll
            for (int i = 0; i < 8; i++) {
                int e  = tid + i * 256;
                int pl = e >> 9;
                int r  = (e >> 2) & 127;
                int s  = e & 3;
                const __nv_bfloat16* src;
                if      (pl == 0) src = Ahi + (size_t)(brow + r) * K + k0 + s * 8;
                else if (pl == 1) src = Alo + (size_t)(brow + r) * K + k0 + s * 8;
                else if (pl == 2) src = Bhi + (size_t)(bcol + r) * K + k0 + s * 8;
                else              src = Blo + (size_t)(bcol + r) * K + k0 + s * 8;
                uint32_t dst = sb + (uint32_t)(pl * PLANE_U + r * 16 + ((s ^ ((r >> 1) & 3)) << 2)) * 4;
                asm volatile("cp.async.cg.shared.global [%0], [%1], 16;" :: "r"(dst), "l"(src));
            }
            asm volatile("cp.async.commit_group;" ::: "memory");
        }

        uint32_t bb = smb + (uint32_t)stage_c * STAGE_B;
        uint32_t Ahb = bb, Alb = bb + PLANE_U * 4, Bhb = bb + 2 * PLANE_U * 4, Blb = bb + 3 * PLANE_U * 4;

        #pragma unroll
        for (int ks = 0; ks < 2; ks++) {
            uint32_t afh[2][4], afl[2][4];
            #pragma unroll
            for (int mt = 0; mt < 2; mt++) {
                LDM4(afh[mt], Ahb + aoffk[mt][ks]);
                LDM4(afl[mt], Alb + aoffk[mt][ks]);
            }
            #pragma unroll
            for (int p = 0; p < 4; p++) {
                uint32_t bfh[4], bfl[4];
                LDM4(bfh, Bhb + boffk[p][ks]);
                LDM4(bfl, Blb + boffk[p][ks]);
                #pragma unroll
                for (int mt = 0; mt < 2; mt++)
                    #pragma unroll
                    for (int hf = 0; hf < 2; hf++) {
                        int nt = p * 2 + hf;
                        MMA_BF16(acc[mt][nt], afh[mt], &bfh[hf * 2]);
                        MMA_BF16(acc[mt][nt], afh[mt], &bfl[hf * 2]);
                        MMA_BF16(acc[mt][nt], afl[mt], &bfh[hf * 2]);
                    }
            }
        }
        stage_c++; if (stage_c >= 3) stage_c = 0;
    }

    float* Cf; const float* bp_; int cb, Nst;
    if (split3) {
        int mi = bcol >> 8;
        Cf  = (mi == 0) ? C0 : (mi == 1 ? C1 : C2);
        bp_ = (mi == 0) ? b0 : (mi == 1 ? b1 : b2);
        cb = bcol & 255; Nst = 256;
    } else {
        Cf = C0; bp_ = b0; cb = bcol; Nst = N;
    }

    #pragma unroll
    for (int mt = 0; mt < 2; mt++) {
        int r0 = brow + moff + mt * 16 + gid;
        #pragma unroll
        for (int nt = 0; nt < 8; nt++) {
            int c = cb + noff + nt * 8 + tig * 2;
            float bb0 = bp_[c], bb1 = bp_[c + 1];
            float2 o0 = make_float2(acc[mt][nt][0] + bb0, acc[mt][nt][1] + bb1);
            float2 o1 = make_float2(acc[mt][nt][2] + bb0, acc[mt][nt][3] + bb1);
            size_t i0 = (size_t)r0 * Nst + c;
            size_t i1 = (size_t)(r0 + 8) * Nst + c;
            if (Radd) {
                float2 ra0 = *(const float2*)(Radd + i0);
                float2 ra1 = *(const float2*)(Radd + i1);
                o0.x += ra0.x; o0.y += ra0.y;
                o1.x += ra1.x; o1.y += ra1.y;
            }
            if (relu) {
                o0.x = fmaxf(o0.x, 0.f); o0.y = fmaxf(o0.y, 0.f);
                o1.x = fmaxf(o1.x, 0.f); o1.y = fmaxf(o1.y, 0.f);
            }
            if (mode & 1) {
                *(float2*)(Cf + i0) = o0;
                *(float2*)(Cf + i1) = o1;
            }
            if (mode & 2) {
                uint32_t h0, l0, h1, l1;
                split2(o0.x, o0.y, h0, l0);
                split2(o1.x, o1.y, h1, l1);
                *(uint32_t*)(Chi + i0) = h0; *(uint32_t*)(Clo + i0) = l0;
                *(uint32_t*)(Chi + i1) = h1; *(uint32_t*)(Clo + i1) = l1;
            }
        }
    }
}

// ---------------- batched transpose+split of ALL weights --------------------------
__global__ void transpose_all_kernel(const float* __restrict__ w_in,
                                     const float* __restrict__ wq, const float* __restrict__ wk,
                                     const float* __restrict__ wv, const float* __restrict__ wo,
                                     const float* __restrict__ f1, const float* __restrict__ f2,
                                     __nv_bfloat16* __restrict__ hi, __nv_bfloat16* __restrict__ lo)
{
    const int start[14] = {0, 8, 72, 136, 200, 264, 520, 776, 840, 904, 968, 1032, 1288, 1544};
    int t = blockIdx.x;
    int m = 0;
    #pragma unroll
    for (int i = 1; i < 14; i++) if (t >= start[i]) m = i;
    int layer = (m >= 7) ? 1 : 0;
    int mi = (m == 0) ? 0 : ((m - 1) % 6) + 1;
    const float* src; int K, N; size_t dst;
    size_t base = (size_t)FIN * D + (size_t)layer * LYR_SZ;
    switch (mi) {
        case 0: src = w_in;                          K = FIN; N = D;   dst = 0;             break;
        case 1: src = wq + (size_t)layer * D * D;    K = D;   N = D;   dst = base;          break;
        case 2: src = wk + (size_t)layer * D * D;    K = D;   N = D;   dst = base + 65536;  break;
        case 3: src = wv + (size_t)layer * D * D;    K = D;   N = D;   dst = base + 131072; break;
        case 4: src = wo + (size_t)layer * D * D;    K = D;   N = D;   dst = base + 196608; break;
        case 5: src = f1 + (size_t)layer * D * DFF;  K = D;   N = DFF; dst = base + 262144; break;
        default:src = f2 + (size_t)layer * DFF * D;  K = DFF; N = D;   dst = base + 524288; break;
    }
    int lt = t - start[m];
    int ntn = N >> 5;
    int nb = (lt % ntn) << 5, kb = (lt / ntn) << 5;

    __shared__ float tbuf[32][33];
    int tx = threadIdx.x, ty = threadIdx.y;
    #pragma unroll
    for (int i = ty; i < 32; i += 8)
        tbuf[i][tx] = src[(size_t)(kb + i) * N + nb + tx];
    __syncthreads();
    #pragma unroll
    for (int i = ty; i < 32; i += 8) {
        float v = tbuf[tx][i];
        size_t o = dst + (size_t)(nb + i) * K + kb + tx;
        split_scalar(v, hi + o, lo + o);
    }
}

// ---------------- plain split ------------------------------------------------------
__global__ void split_kernel(const float* __restrict__ in,
                             __nv_bfloat16* __restrict__ hi,
                             __nv_bfloat16* __restrict__ lo, int n)
{
    int i = (blockIdx.x * blockDim.x + threadIdx.x) * 2;
    if (i >= n) return;
    float2 v = *(const float2*)(in + i);
    uint32_t h, l;
    split2(v.x, v.y, h, l);
    *(uint32_t*)(hi + i) = h;
    *(uint32_t*)(lo + i) = l;
}

// -------- fused sampled-QK M-score (float4, 4 samples/iter) + v-mean ---------------
#define QK_BLOCKS (B_*H_*L_/8)
__global__ void qkvm_kernel(const float* __restrict__ q, const float* __restrict__ k,
                            const int* __restrict__ idx, float* __restrict__ Mout,
                            const float* __restrict__ v, float* __restrict__ vm)
{
    if (blockIdx.x < QK_BLOCKS) {
        int gw   = (blockIdx.x * blockDim.x + threadIdx.x) >> 5;
        int lane = threadIdx.x & 31;
        int l  = gw & (L_ - 1);
        int bh = gw >> 11;
        int b  = bh >> 3, h = bh & 7;

        int g  = lane >> 3;              // sample group 0..3
        int d4 = (lane & 7) << 2;        // 4 dims per lane
        float4 q4 = *(const float4*)(q + ((size_t)b * L_ + l) * D + h * DH + d4);
        const float* kbase = k + (size_t)b * L_ * D + h * DH;
        const int*   irow  = idx + l * S_;

        float mx = -1e30f, sm = 0.0f;
        #pragma unroll 5
        for (int s0 = 0; s0 < S_; s0 += 4) {
            int ki = __ldg(&irow[s0 + g]);
            float4 kv = *(const float4*)(kbase + (size_t)ki * D + d4);
            float p = q4.x * kv.x + q4.y * kv.y + q4.z * kv.z + q4.w * kv.w;
            p += __shfl_xor_sync(0xffffffffu, p, 1);
            p += __shfl_xor_sync(0xffffffffu, p, 2);
            p += __shfl_xor_sync(0xffffffffu, p, 4);
            mx = fmaxf(mx, p);
            sm += p;
        }
        mx = fmaxf(mx, __shfl_xor_sync(0xffffffffu, mx, 8));
        mx = fmaxf(mx, __shfl_xor_sync(0xffffffffu, mx, 16));
        sm += __shfl_xor_sync(0xffffffffu, sm, 8);
        sm += __shfl_xor_sync(0xffffffffu, sm, 16);
        if (lane == 0) Mout[gw] = mx - sm * (1.0f / (float)L_);
    } else {
        int bh = blockIdx.x - QK_BLOCKS; int b = bh >> 3, h = bh & 7;
        int tid = threadIdx.x;
        int d = tid & 31, seg = tid >> 5;
        const float* vb = v + (size_t)b * L_ * D + h * DH + d;
        float acc = 0.0f;
        for (int l = seg; l < L_; l += 8) acc += vb[(size_t)l * D];
        __shared__ float sp[8][32];
        sp[seg][d] = acc;
        __syncthreads();
        if (tid < 32) {
            float s = 0.0f;
            #pragma unroll
            for (int i = 0; i < 8; i++) s += sp[i][tid];
            vm[bh * DH + tid] = s * (1.0f / (float)L_);
        }
    }
}

// ---------------- top-40 per (b,h) -------------------------------------------------
__global__ void topk_kernel(const float* __restrict__ Mv, int* __restrict__ top)
{
    int bh  = blockIdx.x;
    int tid = threadIdx.x;
    int w = tid >> 5, lane = tid & 31;
    __shared__ float sv[L_];
    __shared__ float wv_[8];
    __shared__ int   wi_[8];
    for (int i = tid; i < L_; i += 256) sv[i] = Mv[(size_t)bh * L_ + i];
    __syncthreads();

    for (int r = 0; r < U_; r++) {
        float bv = -1e30f; int bi = 0x7fffffff;
        #pragma unroll
        for (int j = 0; j < 8; j++) {
            int i = tid + j * 256;
            float v = sv[i];
            if (v > bv || (v == bv && i < bi)) { bv = v; bi = i; }
        }
        #pragma unroll
        for (int o = 16; o; o >>= 1) {
            float ov = __shfl_xor_sync(0xffffffffu, bv, o);
            int   oi = __shfl_xor_sync(0xffffffffu, bi, o);
            if (ov > bv || (ov == bv && oi < bi)) { bv = ov; bi = oi; }
        }
        if (lane == 0) { wv_[w] = bv; wi_[w] = bi; }
        __syncthreads();
        if (tid == 0) {
            float fv = wv_[0]; int fi = wi_[0];
            #pragma unroll
            for (int j = 1; j < 8; j++) {
                float ov = wv_[j]; int oi = wi_[j];
                if (ov > fv || (ov == fv && oi < fi)) { fv = ov; fi = oi; }
            }
            top[bh * U_ + r] = fi;
            sv[fi] = -1e30f;
        }
        __syncthreads();
    }
}

// ---------------- fill ctx planes with broadcast v-mean ----------------------------
__global__ void ctxfill_kernel(const float* __restrict__ vm,
                               __nv_bfloat16* __restrict__ chi,
                               __nv_bfloat16* __restrict__ clo)
{
    int i4 = (blockIdx.x * blockDim.x + threadIdx.x) * 4;
    if (i4 >= B_ * L_ * D) return;
    int dfull = i4 & (D - 1);
    int b = i4 / (L_ * D);
    int h = dfull >> 5, d = dfull & 31;
    float4 v = *(const float4*)(vm + ((b << 3) + h) * DH + d);
    uint32_t h01, h23, l01, l23;
    split2(v.x, v.y, h01, l01);
    split2(v.z, v.w, h23, l23);
    *(uint2*)(chi + i4) = make_uint2(h01, h23);
    *(uint2*)(clo + i4) = make_uint2(l01, l23);
}

// --------- split-KV flash attention part: 4 splits of 512 keys per (b,h) ----------
__global__ __launch_bounds__(256, 1)
void attn_part_kernel(const float* __restrict__ q, const float* __restrict__ k,
                      const float* __restrict__ v, const int* __restrict__ top,
                      float* __restrict__ am, float* __restrict__ al,
                      float* __restrict__ av)
{
    __shared__ float Ks[128][33];
    __shared__ float Vs[128][33];
    __shared__ float qs[40][32];
    __shared__ float ps[8][128];
    __shared__ int   stop[40];

    int blk = blockIdx.x;
    int sp = blk & 3, bh = blk >> 2;
    int b = bh >> 3, h = bh & 7;
    int tid = threadIdx.x, w = tid >> 5, lane = tid & 31;

    if (tid < 40) stop[tid] = top[bh * U_ + tid];
    __syncthreads();
    for (int i = tid; i < 40 * 32; i += 256) {
        int u = i >> 5, d = i & 31;
        qs[u][d] = q[((size_t)b * L_ + stop[u]) * D + h * DH + d];
    }

    float m[5], l[5], acc[5];
    #pragma unroll
    for (int j = 0; j < 5; j++) { m[j] = -1e30f; l[j] = 0.f; acc[j] = 0.f; }
    const float scale = 0.1767766952966369f;
    const float* kb = k + (size_t)b * L_ * D + h * DH;
    const float* vb = v + (size_t)b * L_ * D + h * DH;
    __syncthreads();

    int tstart = sp * 512;
    for (int t0 = tstart; t0 < tstart + 512; t0 += 128) {
        for (int i = tid; i < 128 * 32; i += 256) {
            int r = i >> 5, d = i & 31;
            Ks[r][d] = kb[(size_t)(t0 + r) * D + d];
            Vs[r][d] = vb[(size_t)(t0 + r) * D + d];
        }
        __syncthreads();

        float sj[5][4];
        #pragma unroll
        for (int j = 0; j < 5; j++)
            #pragma unroll
            for (int i = 0; i < 4; i++) sj[j][i] = 0.f;
        #pragma unroll
        for (int d = 0; d < 32; d++) {
            float k0v = Ks[lane][d], k1v = Ks[lane + 32][d];
            float k2v = Ks[lane + 64][d], k3v = Ks[lane + 96][d];
            #pragma unroll
            for (int j = 0; j < 5; j++) {
                float qd = qs[w * 5 + j][d];
                sj[j][0] = fmaf(qd, k0v, sj[j][0]);
                sj[j][1] = fmaf(qd, k1v, sj[j][1]);
                sj[j][2] = fmaf(qd, k2v, sj[j][2]);
                sj[j][3] = fmaf(qd, k3v, sj[j][3]);
            }
        }
        #pragma unroll
        for (int j = 0; j < 5; j++) {
            float s0 = sj[j][0] * scale, s1 = sj[j][1] * scale;
            float s2 = sj[j][2] * scale, s3 = sj[j][3] * scale;
            float tm = fmaxf(fmaxf(s0, s1), fmaxf(s2, s3));
            #pragma unroll
            for (int o = 16; o; o >>= 1) tm = fmaxf(tm, __shfl_xor_sync(0xffffffffu, tm, o));
            float mn   = fmaxf(m[j], tm);
            float corr = __expf(m[j] - mn);
            float p0 = __expf(s0 - mn), p1 = __expf(s1 - mn);
            float p2 = __expf(s2 - mn), p3 = __expf(s3 - mn);
            float psum = p0 + p1 + p2 + p3;
            #pragma unroll
            for (int o = 16; o; o >>= 1) psum += __shfl_xor_sync(0xffffffffu, psum, o);
            l[j] = l[j] * corr + psum;
            m[j] = mn;
            ps[w][lane] = p0; ps[w][lane + 32] = p1; ps[w][lane + 64] = p2; ps[w][lane + 96] = p3;
            __syncwarp();
            float aa = acc[j] * corr;
            const float4* pv4 = (const float4*)ps[w];
            #pragma unroll 8
            for (int kk4 = 0; kk4 < 32; kk4++) {
                float4 p4 = pv4[kk4];
                int kk = kk4 * 4;
                aa = fmaf(p4.x, Vs[kk][lane],     aa);
                aa = fmaf(p4.y, Vs[kk + 1][lane], aa);
                aa = fmaf(p4.z, Vs[kk + 2][lane], aa);
                aa = fmaf(p4.w, Vs[kk + 3][lane], aa);
            }
            acc[j] = aa;
            __syncwarp();
        }
        __syncthreads();
    }
    #pragma unroll
    for (int j = 0; j < 5; j++) {
        int u = w * 5 + j;
        int pidx = (bh * 4 + sp) * U_ + u;
        if (lane == 0) { am[pidx] = m[j]; al[pidx] = l[j]; }
        av[(size_t)pidx * DH + lane] = acc[j];
    }
}

// --------- split-KV combine: merge 4 partials per (bh,u), scatter into ctx planes --
__global__ void attn_combine_kernel(const int* __restrict__ top,
                                    const float* __restrict__ am, const float* __restrict__ al,
                                    const float* __restrict__ av,
                                    __nv_bfloat16* __restrict__ chi, __nv_bfloat16* __restrict__ clo)
{
    int bh = blockIdx.x; int b = bh >> 3, h = bh & 7;
    int tid = threadIdx.x, w = tid >> 5, lane = tid & 31;
    __shared__ int stop[40];
    if (tid < 40) stop[tid] = top[bh * U_ + tid];
    __syncthreads();

    #pragma unroll
    for (int j = 0; j < 5; j++) {
        int u = w * 5 + j;
        int base = bh * 4 * U_ + u;
        float m0 = am[base], m1 = am[base + U_], m2 = am[base + 2*U_], m3 = am[base + 3*U_];
        float ms = fmaxf(fmaxf(m0, m1), fmaxf(m2, m3));
        float e0 = __expf(m0 - ms), e1 = __expf(m1 - ms);
        float e2 = __expf(m2 - ms), e3 = __expf(m3 - ms);
        float Lsum = al[base] * e0 + al[base + U_] * e1 + al[base + 2*U_] * e2 + al[base + 3*U_] * e3;
        float num = av[(size_t)base * DH + lane] * e0
                  + av[(size_t)(base + U_) * DH + lane] * e1
                  + av[(size_t)(base + 2*U_) * DH + lane] * e2
                  + av[(size_t)(base + 3*U_) * DH + lane] * e3;
        float o = num / Lsum;
        size_t off = ((size_t)b * L_ + stop[u]) * D + h * DH + lane;
        split_scalar(o, chi + off, clo + off);
    }
}

// ---------- LayerNorm of pre-summed input + split -----------------------------------
__global__ void add_ln_kernel(const float* __restrict__ sum,
                              const float* __restrict__ g, const float* __restrict__ bb,
                              float* __restrict__ hout,
                              __nv_bfloat16* __restrict__ hhi, __nv_bfloat16* __restrict__ hlo)
{
    int tid = threadIdx.x;
    int rl  = tid >> 7;
    int ct  = tid & 127;
    int row = blockIdx.x * 2 + rl;
    size_t off = (size_t)row * D + ct * 2;
    float2 v = *(const float2*)(sum + off);
    float s1 = v.x + v.y, s2 = v.x * v.x + v.y * v.y;
    #pragma unroll
    for (int o = 16; o; o >>= 1) {
        s1 += __shfl_xor_sync(0xffffffffu, s1, o);
        s2 += __shfl_xor_sync(0xffffffffu, s2, o);
    }
    __shared__ float a1[2][4], a2[2][4], mu[2], rv[2];
    int wr = (tid >> 5) & 3;
    int lane = tid & 31;
    if (lane == 0) { a1[rl][wr] = s1; a2[rl][wr] = s2; }
    __syncthreads();
    if (ct == 0) {
        float t1 = a1[rl][0] + a1[rl][1] + a1[rl][2] + a1[rl][3];
        float t2 = a2[rl][0] + a2[rl][1] + a2[rl][2] + a2[rl][3];
        float m = t1 * (1.0f / (float)D);
        float var = t2 * (1.0f / (float)D) - m * m;
        mu[rl] = m;
        rv[rl] = rsqrtf(var + 1e-5f);
    }
    __syncthreads();
    float m = mu[rl], r = rv[rl];
    float2 gg = *(const float2*)(g + ct * 2);
    float2 b2 = *(const float2*)(bb + ct * 2);
    float2 o;
    o.x = (v.x - m) * r * gg.x + b2.x;
    o.y = (v.y - m) * r * gg.y + b2.y;
    *(float2*)(hout + off) = o;
    uint32_t hi32, lo32;
    split2(o.x, o.y, hi32, lo32);
    *(uint32_t*)(hhi + off) = hi32;
    *(uint32_t*)(hlo + off) = lo32;
}

// --------- last-layer attention for row L-1 only ------------------------------------
__global__ __launch_bounds__(256, 1)
void last_attn_kernel(const float* __restrict__ q, const float* __restrict__ k,
                      const float* __restrict__ v, const int* __restrict__ top,
                      const float* __restrict__ vm, float* __restrict__ ctxl)
{
    int bh = blockIdx.x; int b = bh >> 3, h = bh & 7;
    int tid = threadIdx.x;
    __shared__ int memb;
    __shared__ float qs[DH];
    __shared__ float sc[L_];
    __shared__ float red[256];
    __shared__ float part[8][DH];

    if (tid == 0) memb = 0;
    __syncthreads();
    if (tid < U_ && top[bh * U_ + tid] == (L_ - 1)) memb = 1;
    __syncthreads();
    if (!memb) {
        if (tid < DH) ctxl[bh * DH + tid] = vm[bh * DH + tid];
        return;
    }

    if (tid < DH) qs[tid] = q[((size_t)b * L_ + (L_ - 1)) * D + h * DH + tid];
    __syncthreads();

    const float* kb = k + (size_t)b * L_ * D + h * DH;
    const float scale = 0.1767766952966369f;
    float lmax = -1e30f;
    for (int l = tid; l < L_; l += 256) {
        const float4* kr = (const float4*)(kb + (size_t)l * D);
        float dot = 0.0f;
        #pragma unroll
        for (int j = 0; j < 8; j++) {
            float4 kv = __ldg(&kr[j]);
            dot += qs[4*j+0]*kv.x + qs[4*j+1]*kv.y + qs[4*j+2]*kv.z + qs[4*j+3]*kv.w;
        }
        dot *= scale;
        sc[l] = dot;
        lmax = fmaxf(lmax, dot);
    }
    red[tid] = lmax; __syncthreads();
    for (int s = 128; s; s >>= 1) { if (tid < s) red[tid] = fmaxf(red[tid], red[tid + s]); __syncthreads(); }
    float gmax = red[0];
    __syncthreads();
    float lsum = 0.0f;
    for (int l = tid; l < L_; l += 256) {
        float e = __expf(sc[l] - gmax);
        sc[l] = e;
        lsum += e;
    }
    red[tid] = lsum; __syncthreads();
    for (int s = 128; s; s >>= 1) { if (tid < s) red[tid] += red[tid + s]; __syncthreads(); }
    float inv = 1.0f / red[0];
    __syncthreads();

    int d = tid & 31, seg = tid >> 5;
    const float* vb = v + (size_t)b * L_ * D + h * DH + d;
    float acc = 0.0f;
    for (int l = seg; l < L_; l += 8) acc += sc[l] * vb[(size_t)l * D];
    part[seg][d] = acc;
    __syncthreads();
    if (tid < DH) {
        float s = 0.0f;
        #pragma unroll
        for (int i = 0; i < 8; i++) s += part[i][tid];
        ctxl[bh * DH + tid] = s * inv;
    }
}

// --------- final chain for row L-1 ---------------------------------------------------
__global__ __launch_bounds__(256, 1)
void final_head_kernel(const float* __restrict__ h, const float* __restrict__ ctxl,
                       const float* __restrict__ wo2, const float* __restrict__ bo2,
                       const float* __restrict__ ln1g, const float* __restrict__ ln1b,
                       const float* __restrict__ ff1, const float* __restrict__ bf1,
                       const float* __restrict__ ff2, const float* __restrict__ bf2,
                       const float* __restrict__ ln2g, const float* __restrict__ ln2b,
                       const float* __restrict__ w1, const float* __restrict__ b1,
                       const float* __restrict__ w2, const float* __restrict__ b2,
                       float* __restrict__ out)
{
    int b = blockIdx.x;
    int tid = threadIdx.x;
    int w = tid >> 5, lane = tid & 31;
    __shared__ float row[D], ctxr[D], hb1[D], yb[DFF], hb2[D];
    __shared__ float a1[8], a2[8], stat[2];

    row[tid]  = h[((size_t)b * L_ + (L_ - 1)) * D + tid];
    ctxr[tid] = ctxl[b * D + tid];
    __syncthreads();

    float acc = bo2[tid];
    for (int dd = 0; dd < D; dd++) acc = fmaf(ctxr[dd], wo2[dd * D + tid], acc);
    float val = row[tid] + acc;

    {
        float s1 = val, s2 = val * val;
        #pragma unroll
        for (int o = 16; o; o >>= 1) {
            s1 += __shfl_xor_sync(0xffffffffu, s1, o);
            s2 += __shfl_xor_sync(0xffffffffu, s2, o);
        }
        if (lane == 0) { a1[w] = s1; a2[w] = s2; }
        __syncthreads();
        if (tid == 0) {
            float t1 = 0.f, t2 = 0.f;
            #pragma unroll
            for (int j = 0; j < 8; j++) { t1 += a1[j]; t2 += a2[j]; }
            float mu = t1 * (1.0f / (float)D);
            stat[0] = mu;
            stat[1] = rsqrtf(t2 * (1.0f / (float)D) - mu * mu + 1e-5f);
        }
        __syncthreads();
        hb1[tid] = (val - stat[0]) * stat[1] * ln1g[tid] + ln1b[tid];
        __syncthreads();
    }

    #pragma unroll
    for (int jj = 0; jj < 4; jj++) {
        int j = tid + jj * 256;
        float a = bf1[j];
        for (int dd = 0; dd < D; dd++) a = fmaf(hb1[dd], ff1[(size_t)dd * DFF + j], a);
        yb[j] = fmaxf(a, 0.0f);
    }
    __syncthreads();

    float acc2 = bf2[tid];
    for (int dd = 0; dd < DFF; dd++) acc2 = fmaf(yb[dd], ff2[(size_t)dd * D + tid], acc2);
    float val2 = hb1[tid] + acc2;
    {
        float s1 = val2, s2 = val2 * val2;
        #pragma unroll
        for (int o = 16; o; o >>= 1) {
            s1 += __shfl_xor_sync(0xffffffffu, s1, o);
            s2 += __shfl_xor_sync(0xffffffffu, s2, o);
        }
        __syncthreads();
        if (lane == 0) { a1[w] = s1; a2[w] = s2; }
        __syncthreads();
        if (tid == 0) {
            float t1 = 0.f, t2 = 0.f;
            #pragma unroll
            for (int j = 0; j < 8; j++) { t1 += a1[j]; t2 += a2[j]; }
            float mu = t1 * (1.0f / (float)D);
            stat[0] = mu;
            stat[1] = rsqrtf(t2 * (1.0f / (float)D) - mu * mu + 1e-5f);
        }
        __syncthreads();
        hb2[tid] = (val2 - stat[0]) * stat[1] * ln2g[tid] + ln2b[tid];
        __syncthreads();
    }

    __shared__ float th[64];
    if (tid < 64) {
        float a = b1[tid];
        for (int dd = 0; dd < D; dd++) a = fmaf(hb2[dd], w1[dd * 64 + tid], a);
        th[tid] = fmaxf(a, 0.0f) * w2[tid];
    }
    __syncthreads();
    if (tid < 32) {
        float s = th[tid] + th[tid + 32];
        #pragma unroll
        for (int o = 16; o; o >>= 1) s += __shfl_xor_sync(0xffffffffu, s, o);
        if (tid == 0) out[b] = s + b2[0];
    }
}

// ===================================================================================
extern "C" void kernel_launch(void* const* d_in, const int* in_sizes, int n_in,
                              void* d_out, int out_size)
{
    const float* x     = (const float*)d_in[0];
    const int*   idx   = (const int*)  d_in[1];
    const float* w_in  = (const float*)d_in[2];
    const float* b_in  = (const float*)d_in[3];
    const float* wq    = (const float*)d_in[4];
    const float* bq    = (const float*)d_in[5];
    const float* wk    = (const float*)d_in[6];
    const float* bk    = (const float*)d_in[7];
    const float* wv    = (const float*)d_in[8];
    const float* bv    = (const float*)d_in[9];
    const float* wo    = (const float*)d_in[10];
    const float* bo    = (const float*)d_in[11];
    const float* w_ff1 = (const float*)d_in[12];
    const float* b_ff1 = (const float*)d_in[13];
    const float* w_ff2 = (const float*)d_in[14];
    const float* b_ff2 = (const float*)d_in[15];
    const float* ln1_g = (const float*)d_in[16];
    const float* ln1_b = (const float*)d_in[17];
    const float* ln2_g = (const float*)d_in[18];
    const float* ln2_b = (const float*)d_in[19];
    const float* w_fc1 = (const float*)d_in[20];
    const float* b_fc1 = (const float*)d_in[21];
    const float* w_fc2 = (const float*)d_in[22];
    const float* b_fc2 = (const float*)d_in[23];
    float* out = (float*)d_out;

    float *h, *q, *k, *v, *nx, *Mv, *vm, *ctxl, *am, *al, *av; int* top;
    __nv_bfloat16 *xhi, *xlo, *hhi, *hlo, *chi, *clo, *fhi, *flo, *whi, *wlo;
    cudaGetSymbolAddress((void**)&h,   g_h);
    cudaGetSymbolAddress((void**)&q,   g_q);
    cudaGetSymbolAddress((void**)&k,   g_k);
    cudaGetSymbolAddress((void**)&v,   g_v);
    cudaGetSymbolAddress((void**)&nx,  g_nx);
    cudaGetSymbolAddress((void**)&Mv,  g_M);
    cudaGetSymbolAddress((void**)&top, g_top);
    cudaGetSymbolAddress((void**)&vm,  g_vm);
    cudaGetSymbolAddress((void**)&ctxl, g_ctxl);
    cudaGetSymbolAddress((void**)&am,  g_am);
    cudaGetSymbolAddress((void**)&al,  g_al);
    cudaGetSymbolAddress((void**)&av,  g_av);
    cudaGetSymbolAddress((void**)&xhi, g_x_hi);  cudaGetSymbolAddress((void**)&xlo, g_x_lo);
    cudaGetSymbolAddress((void**)&hhi, g_h_hi);  cudaGetSymbolAddress((void**)&hlo, g_h_lo);
    cudaGetSymbolAddress((void**)&chi, g_ctx_hi); cudaGetSymbolAddress((void**)&clo, g_ctx_lo);
    cudaGetSymbolAddress((void**)&fhi, g_ff_hi); cudaGetSymbolAddress((void**)&flo, g_ff_lo);
    cudaGetSymbolAddress((void**)&whi, g_wt_hi); cudaGetSymbolAddress((void**)&wlo, g_wt_lo);

    cudaFuncSetAttribute(mma_gemm_bf16, cudaFuncAttributeMaxDynamicSharedMemorySize, GEMM_SMEM_V3);

    const int Mrows = B_ * L_;
    dim3 gD  (D / 128,   Mrows / 128);
    dim3 gQKV(3 * D / 128, Mrows / 128);
    dim3 gFF (DFF / 128, Mrows / 128);
    dim3 tb(32, 8);

    const size_t o_in = 0;
    auto o_q  = [&](int l){ return (size_t)FIN * D + (size_t)l * LYR_SZ; };
    auto o_o  = [&](int l){ return o_q(l) + 196608; };
    auto o_f1 = [&](int l){ return o_q(l) + 262144; };
    auto o_f2 = [&](int l){ return o_q(l) + 524288; };

    split_kernel<<<(B_ * L_ * FIN) / 512, 256>>>(x, xhi, xlo, B_ * L_ * FIN);
    transpose_all_kernel<<<1544, tb>>>(w_in, wq, wk, wv, wo, w_ff1, w_ff2, whi, wlo);
    mma_gemm_bf16<<<gD, 256, GEMM_SMEM_V3>>>(xhi, xlo, whi + o_in, wlo + o_in,
        b_in, nullptr, nullptr, h, nullptr, nullptr, hhi, hlo, nullptr, Mrows, D, FIN, 0, 3, 0);

    // ---------------- layer 0 (full) ----------------
    {
        const int layer = 0;
        const int* ixL = idx;

        mma_gemm_bf16<<<gQKV, 256, GEMM_SMEM_V3>>>(hhi, hlo, whi + o_q(layer), wlo + o_q(layer),
            bq, bk, bv, q, k, v, nullptr, nullptr, nullptr, Mrows, 768, D, 0, 1, 1);

        qkvm_kernel<<<QK_BLOCKS + B_ * H_, 256>>>(q, k, ixL, Mv, v, vm);
        topk_kernel<<<B_ * H_, 256>>>(Mv, top);
        ctxfill_kernel<<<(B_ * L_ * D) / 1024, 256>>>(vm, chi, clo);
        attn_part_kernel<<<B_ * H_ * 4, 256>>>(q, k, v, top, am, al, av);
        attn_combine_kernel<<<B_ * H_, 256>>>(top, am, al, av, chi, clo);

        mma_gemm_bf16<<<gD, 256, GEMM_SMEM_V3>>>(chi, clo, whi + o_o(layer), wlo + o_o(layer),
            bo, nullptr, nullptr, nx, nullptr, nullptr, nullptr, nullptr, h,
            Mrows, D, D, 0, 1, 0);
        add_ln_kernel<<<Mrows / 2, 256>>>(nx, ln1_g, ln1_b, h, hhi, hlo);

        mma_gemm_bf16<<<gFF, 256, GEMM_SMEM_V3>>>(hhi, hlo, whi + o_f1(layer), wlo + o_f1(layer),
            b_ff1, nullptr, nullptr, nullptr, nullptr, nullptr, fhi, flo, nullptr,
            Mrows, DFF, D, 1, 2, 0);
        mma_gemm_bf16<<<gD, 256, GEMM_SMEM_V3>>>(fhi, flo, whi + o_f2(layer), wlo + o_f2(layer),
            b_ff2, nullptr, nullptr, nx, nullptr, nullptr, nullptr, nullptr, h,
            Mrows, D, DFF, 0, 1, 0);
        add_ln_kernel<<<Mrows / 2, 256>>>(nx, ln2_g, ln2_b, h, hhi, hlo);
    }

    // ---------------- layer 1 (output-funnel pruned) ----------------
    {
        const int layer = 1;
        const int* ixL = idx + (size_t)L_ * S_;

        mma_gemm_bf16<<<gQKV, 256, GEMM_SMEM_V3>>>(hhi, hlo, whi + o_q(layer), wlo + o_q(layer),
            bq + D, bk + D, bv + D, q, k, v, nullptr, nullptr, nullptr, Mrows, 768, D, 0, 1, 1);

        qkvm_kernel<<<QK_BLOCKS + B_ * H_, 256>>>(q, k, ixL, Mv, v, vm);
        topk_kernel<<<B_ * H_, 256>>>(Mv, top);
        last_attn_kernel<<<B_ * H_, 256>>>(q, k, v, top, vm, ctxl);

        final_head_kernel<<<B_, 256>>>(h, ctxl,
            wo + (size_t)D * D, bo + D,
            ln1_g + D, ln1_b + D,
            w_ff1 + (size_t)D * DFF, b_ff1 + DFF,
            w_ff2 + (size_t)DFF * D, b_ff2 + D,
            ln2_g + D, ln2_b + D,
            w_fc1, b_fc1, w_fc2, b_fc2, out);
    }
}

// round 11
// speedup vs baseline: 4.4484x; 1.0403x over previous
#include <cuda_runtime.h>
#include <cuda_bf16.h>
#include <cstdint>
#include <math.h>

// Problem constants
#define B_   8
#define L_   2048
#define FIN  32
#define D    256
#define H_   8
#define DH   32
#define DFF  1024
#define S_   40
#define U_   40
#define NL   2

// ---------------- scratch (device globals; no allocation allowed) ----------------
__device__ float g_h  [B_*L_*D];
__device__ float g_q  [B_*L_*D];
__device__ float g_k  [B_*L_*D];
__device__ float g_v  [B_*L_*D];
__device__ float g_nx [B_*L_*D];
__device__ float g_M  [B_*H_*L_];
__device__ int   g_top[B_*H_*U_];
__device__ float g_vm [B_*H_*DH];
__device__ float g_ctxl[B_*H_*DH];
__device__ float g_am[B_*H_*4*U_];
__device__ float g_al[B_*H_*4*U_];
__device__ float g_av[B_*H_*4*U_*DH];

// bf16 hi/lo planes (K-chunked layout: [K/32][rows][32] with in-chunk swizzle)
__device__ __nv_bfloat16 g_x_hi [B_*L_*FIN], g_x_lo [B_*L_*FIN];
__device__ __nv_bfloat16 g_h_hi [B_*L_*D],   g_h_lo [B_*L_*D];
__device__ __nv_bfloat16 g_ctx_hi[B_*L_*D],  g_ctx_lo[B_*L_*D];
__device__ __nv_bfloat16 g_ff_hi[B_*L_*DFF], g_ff_lo[B_*L_*DFF];
#define LYR_SZ   786432
#define WT_TOTAL (FIN*D + NL*LYR_SZ)
__device__ __nv_bfloat16 g_wt_hi[WT_TOTAL], g_wt_lo[WT_TOTAL];

// =========================== helpers ===============================================
__device__ __forceinline__ uint32_t smem_u32(const void* p) {
    uint32_t a;
    asm("{ .reg .u64 t; cvta.to.shared.u64 t, %1; cvt.u32.u64 %0, t; }" : "=r"(a) : "l"(p));
    return a;
}
__device__ __forceinline__ void split2(float x, float y, uint32_t& hi, uint32_t& lo) {
    __nv_bfloat162 h = __float22bfloat162_rn(make_float2(x, y));
    float2 hf = __bfloat1622float2(h);
    __nv_bfloat162 l = __float22bfloat162_rn(make_float2(x - hf.x, y - hf.y));
    hi = *(uint32_t*)&h; lo = *(uint32_t*)&l;
}
__device__ __forceinline__ void split_scalar(float v, __nv_bfloat16* hp, __nv_bfloat16* lp) {
    __nv_bfloat16 hb = __float2bfloat16(v);
    *hp = hb;
    *lp = __float2bfloat16(v - __bfloat162float(hb));
}

// chunked-plane index: element (row, k) in a tensor with Md rows
__device__ __forceinline__ size_t pidx(int row, int k, int Md) {
    int c = k >> 5, u = (k >> 3) & 3, e = k & 7;
    int u2 = u ^ ((row >> 1) & 3);
    return ((size_t)c * Md + row) * 32 + u2 * 8 + e;
}

#define MMA_BF16(c, a, b)                                                        \
    asm volatile("mma.sync.aligned.m16n8k16.row.col.f32.bf16.bf16.f32 "          \
        "{%0,%1,%2,%3}, {%4,%5,%6,%7}, {%8,%9}, {%0,%1,%2,%3};"                  \
        : "+f"((c)[0]), "+f"((c)[1]), "+f"((c)[2]), "+f"((c)[3])                  \
        : "r"((a)[0]), "r"((a)[1]), "r"((a)[2]), "r"((a)[3]),                     \
          "r"((b)[0]), "r"((b)[1]))

#define LDM4(r, addr)                                                            \
    asm volatile("ldmatrix.sync.aligned.m8n8.x4.shared.b16 {%0,%1,%2,%3}, [%4];" \
        : "=r"((r)[0]), "=r"((r)[1]), "=r"((r)[2]), "=r"((r)[3]) : "r"(addr))

#define MBAR_INIT(mb, n)  asm volatile("mbarrier.init.shared.b64 [%0], %1;" :: "r"(mb), "r"(n) : "memory")
#define MBAR_EXPECT(mb, tx) asm volatile("mbarrier.arrive.expect_tx.shared.b64 _, [%0], %1;" :: "r"(mb), "r"(tx) : "memory")
#define MBAR_WAIT(mb, ph) do {                                                          \
    asm volatile("{ .reg .pred P;\n\t"                                                  \
        "W_%=: mbarrier.try_wait.parity.acquire.cta.shared::cta.b64 P, [%0], %1, 0x989680;\n\t" \
        "@P bra.uni DN_%=; bra.uni W_%=; DN_%=: }"                                      \
        :: "r"(mb), "r"(ph) : "memory");                                                \
} while (0)
#define BULK_LD(dst, src, bytes, mb)                                                    \
    asm volatile("cp.async.bulk.shared::cluster.global.mbarrier::complete_tx::bytes "   \
        "[%0], [%1], %2, [%3];" :: "r"(dst), "l"(src), "r"(bytes), "r"(mb) : "memory")

// ======= 3-stage pipelined bf16x3 GEMM: bulk-copy loads, chunked operand planes ====
#define STAGE_B 32768             // 4 planes x 8192 bytes
#define GEMM_SMEM_V4 (1024 + 3*STAGE_B)   // 99328 bytes (barriers in first 1 KB)

__global__ __launch_bounds__(256, 2)
void mma_gemm_bf16(const __nv_bfloat16* __restrict__ Ahi, const __nv_bfloat16* __restrict__ Alo,
                   const __nv_bfloat16* __restrict__ Bhi, const __nv_bfloat16* __restrict__ Blo,
                   const float* __restrict__ b0, const float* __restrict__ b1,
                   const float* __restrict__ b2,
                   float* __restrict__ C0, float* __restrict__ C1, float* __restrict__ C2,
                   __nv_bfloat16* __restrict__ Chi, __nv_bfloat16* __restrict__ Clo,
                   const float* __restrict__ Radd,
                   int M, int N, int K, int relu, int mode, int split3)
{
    extern __shared__ uint32_t sm[];
    int tid  = threadIdx.x;
    int brow = blockIdx.y * 128;
    int bcol = blockIdx.x * 128;
    int w = tid >> 5, lane = tid & 31;
    int gid = lane >> 2, tig = lane & 3;
    int moff = (w >> 1) * 32, noff = (w & 1) * 64;
    uint32_t smb = smem_u32(sm);
    uint32_t stg = smb + 1024;

    if (tid == 0) {
        MBAR_INIT(smb,      1);
        MBAR_INIT(smb + 8,  1);
        MBAR_INIT(smb + 16, 1);
    }
    __syncthreads();

    // ldmatrix byte offsets within a plane: off(row,u) = row*64 + ((u^((row>>1)&3))<<4)
    int mat = lane >> 3, r8 = lane & 7;
    uint32_t aoffk[2][2], boffk[4][2];
    #pragma unroll
    for (int mt = 0; mt < 2; mt++) {
        int row = moff + mt * 16 + (mat & 1) * 8 + r8;
        int sw = (row >> 1) & 3;
        #pragma unroll
        for (int ks = 0; ks < 2; ks++) {
            int u = ks * 2 + (mat >> 1);
            aoffk[mt][ks] = (uint32_t)(row * 64 + ((u ^ sw) << 4));
        }
    }
    #pragma unroll
    for (int p = 0; p < 4; p++) {
        int row = noff + p * 16 + (mat >> 1) * 8 + r8;
        int sw = (row >> 1) & 3;
        #pragma unroll
        for (int ks = 0; ks < 2; ks++) {
            int u = ks * 2 + (mat & 1);
            boffk[p][ks] = (uint32_t)(row * 64 + ((u ^ sw) << 4));
        }
    }

    const int NC = K >> 5;

    auto issue = [&](int c) {
        int s = c % 3;
        uint32_t sb = stg + (uint32_t)s * STAGE_B;
        uint32_t mb = smb + (uint32_t)s * 8;
        MBAR_EXPECT(mb, 32768u);
        const __nv_bfloat16* a0 = Ahi + ((size_t)c * M + brow) * 32;
        const __nv_bfloat16* a1 = Alo + ((size_t)c * M + brow) * 32;
        const __nv_bfloat16* b0p = Bhi + ((size_t)c * N + bcol) * 32;
        const __nv_bfloat16* b1p = Blo + ((size_t)c * N + bcol) * 32;
        BULK_LD(sb,          a0,  8192u, mb);
        BULK_LD(sb + 8192,   a1,  8192u, mb);
        BULK_LD(sb + 16384,  b0p, 8192u, mb);
        BULK_LD(sb + 24576,  b1p, 8192u, mb);
    };

    if (tid == 0) {
        issue(0);
        if (NC > 1) issue(1);
    }

    float acc[2][8][4] = {};

    for (int c = 0; c < NC; c++) {
        __syncthreads();                       // all readers done with stage (c+2)%3
        if (tid == 0 && c + 2 < NC) issue(c + 2);
        MBAR_WAIT(smb + (uint32_t)(c % 3) * 8, (c / 3) & 1);

        uint32_t bb = stg + (uint32_t)(c % 3) * STAGE_B;
        uint32_t Ahb = bb, Alb = bb + 8192, Bhb = bb + 16384, Blb = bb + 24576;

        #pragma unroll
        for (int ks = 0; ks < 2; ks++) {
            uint32_t afh[2][4], afl[2][4];
            #pragma unroll
            for (int mt = 0; mt < 2; mt++) {
                LDM4(afh[mt], Ahb + aoffk[mt][ks]);
                LDM4(afl[mt], Alb + aoffk[mt][ks]);
            }
            #pragma unroll
            for (int p = 0; p < 4; p++) {
                uint32_t bfh[4], bfl[4];
                LDM4(bfh, Bhb + boffk[p][ks]);
                LDM4(bfl, Blb + boffk[p][ks]);
                #pragma unroll
                for (int mt = 0; mt < 2; mt++)
                    #pragma unroll
                    for (int hf = 0; hf < 2; hf++) {
                        int nt = p * 2 + hf;
                        MMA_BF16(acc[mt][nt], afh[mt], &bfh[hf * 2]);
                        MMA_BF16(acc[mt][nt], afh[mt], &bfl[hf * 2]);
                        MMA_BF16(acc[mt][nt], afl[mt], &bfh[hf * 2]);
                    }
            }
        }
    }

    // epilogue
    float* Cf; const float* bp_; int cb, Nst;
    if (split3) {
        int mi = bcol >> 8;
        Cf  = (mi == 0) ? C0 : (mi == 1 ? C1 : C2);
        bp_ = (mi == 0) ? b0 : (mi == 1 ? b1 : b2);
        cb = bcol & 255; Nst = 256;
    } else {
        Cf = C0; bp_ = b0; cb = bcol; Nst = N;
    }

    #pragma unroll
    for (int mt = 0; mt < 2; mt++) {
        int r0 = brow + moff + mt * 16 + gid;
        #pragma unroll
        for (int nt = 0; nt < 8; nt++) {
            int c = cb + noff + nt * 8 + tig * 2;
            float bb0 = bp_[c], bb1 = bp_[c + 1];
            float2 o0 = make_float2(acc[mt][nt][0] + bb0, acc[mt][nt][1] + bb1);
            float2 o1 = make_float2(acc[mt][nt][2] + bb0, acc[mt][nt][3] + bb1);
            size_t i0 = (size_t)r0 * Nst + c;
            size_t i1 = (size_t)(r0 + 8) * Nst + c;
            if (Radd) {
                float2 ra0 = *(const float2*)(Radd + i0);
                float2 ra1 = *(const float2*)(Radd + i1);
                o0.x += ra0.x; o0.y += ra0.y;
                o1.x += ra1.x; o1.y += ra1.y;
            }
            if (relu) {
                o0.x = fmaxf(o0.x, 0.f); o0.y = fmaxf(o0.y, 0.f);
                o1.x = fmaxf(o1.x, 0.f); o1.y = fmaxf(o1.y, 0.f);
            }
            if (mode & 1) {
                *(float2*)(Cf + i0) = o0;
                *(float2*)(Cf + i1) = o1;
            }
            if (mode & 2) {
                uint32_t h0, l0, h1, l1;
                split2(o0.x, o0.y, h0, l0);
                split2(o1.x, o1.y, h1, l1);
                size_t p0 = pidx(r0,     c, 16384);
                size_t p1 = pidx(r0 + 8, c, 16384);
                *(uint32_t*)(Chi + p0) = h0; *(uint32_t*)(Clo + p0) = l0;
                *(uint32_t*)(Chi + p1) = h1; *(uint32_t*)(Clo + p1) = l1;
            }
        }
    }
}

// ---------------- batched transpose+split of ALL weights (chunked layout) ----------
__global__ void transpose_all_kernel(const float* __restrict__ w_in,
                                     const float* __restrict__ wq, const float* __restrict__ wk,
                                     const float* __restrict__ wv, const float* __restrict__ wo,
                                     const float* __restrict__ f1, const float* __restrict__ f2,
                                     __nv_bfloat16* __restrict__ hi, __nv_bfloat16* __restrict__ lo)
{
    const int start[14] = {0, 8, 72, 136, 200, 264, 520, 776, 840, 904, 968, 1032, 1288, 1544};
    int t = blockIdx.x;
    int m = 0;
    #pragma unroll
    for (int i = 1; i < 14; i++) if (t >= start[i]) m = i;
    int layer = (m >= 7) ? 1 : 0;
    int mi = (m == 0) ? 0 : ((m - 1) % 6) + 1;
    const float* src; int K, N, Nchunk, nofs; size_t dst;
    size_t base = (size_t)FIN * D + (size_t)layer * LYR_SZ;
    switch (mi) {
        case 0: src = w_in;                          K = FIN; N = D;   Nchunk = 256;  nofs = 0;   dst = 0;             break;
        case 1: src = wq + (size_t)layer * D * D;    K = D;   N = D;   Nchunk = 768;  nofs = 0;   dst = base;          break;
        case 2: src = wk + (size_t)layer * D * D;    K = D;   N = D;   Nchunk = 768;  nofs = 256; dst = base;          break;
        case 3: src = wv + (size_t)layer * D * D;    K = D;   N = D;   Nchunk = 768;  nofs = 512; dst = base;          break;
        case 4: src = wo + (size_t)layer * D * D;    K = D;   N = D;   Nchunk = 256;  nofs = 0;   dst = base + 196608; break;
        case 5: src = f1 + (size_t)layer * D * DFF;  K = D;   N = DFF; Nchunk = 1024; nofs = 0;   dst = base + 262144; break;
        default:src = f2 + (size_t)layer * DFF * D;  K = DFF; N = D;   Nchunk = 256;  nofs = 0;   dst = base + 524288; break;
    }
    int lt = t - start[m];
    int ntn = N >> 5;
    int nb = (lt % ntn) << 5, kb = (lt / ntn) << 5;

    __shared__ float tbuf[32][33];
    int tx = threadIdx.x, ty = threadIdx.y;
    #pragma unroll
    for (int i = ty; i < 32; i += 8)
        tbuf[i][tx] = src[(size_t)(kb + i) * N + nb + tx];
    __syncthreads();
    #pragma unroll
    for (int i = ty; i < 32; i += 8) {
        float v = tbuf[tx][i];
        size_t o = dst + pidx(nofs + nb + i, kb + tx, Nchunk);
        split_scalar(v, hi + o, lo + o);
    }
}

// ---------------- plain split (x planes: K-dim 32, chunked) ------------------------
__global__ void split_kernel(const float* __restrict__ in,
                             __nv_bfloat16* __restrict__ hi,
                             __nv_bfloat16* __restrict__ lo, int n)
{
    int i = (blockIdx.x * blockDim.x + threadIdx.x) * 2;
    if (i >= n) return;
    float2 v = *(const float2*)(in + i);
    uint32_t h, l;
    split2(v.x, v.y, h, l);
    size_t o = pidx(i >> 5, i & 31, 16384);
    *(uint32_t*)(hi + o) = h;
    *(uint32_t*)(lo + o) = l;
}

// -------- fused sampled-QK M-score (float4, 4 samples/iter) + v-mean ---------------
#define QK_BLOCKS (B_*H_*L_/8)
__global__ void qkvm_kernel(const float* __restrict__ q, const float* __restrict__ k,
                            const int* __restrict__ idx, float* __restrict__ Mout,
                            const float* __restrict__ v, float* __restrict__ vm)
{
    if (blockIdx.x < QK_BLOCKS) {
        int gw   = (blockIdx.x * blockDim.x + threadIdx.x) >> 5;
        int lane = threadIdx.x & 31;
        int l  = gw & (L_ - 1);
        int bh = gw >> 11;
        int b  = bh >> 3, h = bh & 7;

        int g  = lane >> 3;
        int d4 = (lane & 7) << 2;
        float4 q4 = *(const float4*)(q + ((size_t)b * L_ + l) * D + h * DH + d4);
        const float* kbase = k + (size_t)b * L_ * D + h * DH;
        const int*   irow  = idx + l * S_;

        float mx = -1e30f, sm = 0.0f;
        #pragma unroll 5
        for (int s0 = 0; s0 < S_; s0 += 4) {
            int ki = __ldg(&irow[s0 + g]);
            float4 kv = *(const float4*)(kbase + (size_t)ki * D + d4);
            float p = q4.x * kv.x + q4.y * kv.y + q4.z * kv.z + q4.w * kv.w;
            p += __shfl_xor_sync(0xffffffffu, p, 1);
            p += __shfl_xor_sync(0xffffffffu, p, 2);
            p += __shfl_xor_sync(0xffffffffu, p, 4);
            mx = fmaxf(mx, p);
            sm += p;
        }
        mx = fmaxf(mx, __shfl_xor_sync(0xffffffffu, mx, 8));
        mx = fmaxf(mx, __shfl_xor_sync(0xffffffffu, mx, 16));
        sm += __shfl_xor_sync(0xffffffffu, sm, 8);
        sm += __shfl_xor_sync(0xffffffffu, sm, 16);
        if (lane == 0) Mout[gw] = mx - sm * (1.0f / (float)L_);
    } else {
        int bh = blockIdx.x - QK_BLOCKS; int b = bh >> 3, h = bh & 7;
        int tid = threadIdx.x;
        int d = tid & 31, seg = tid >> 5;
        const float* vb = v + (size_t)b * L_ * D + h * DH + d;
        float acc = 0.0f;
        for (int l = seg; l < L_; l += 8) acc += vb[(size_t)l * D];
        __shared__ float sp[8][32];
        sp[seg][d] = acc;
        __syncthreads();
        if (tid < 32) {
            float s = 0.0f;
            #pragma unroll
            for (int i = 0; i < 8; i++) s += sp[i][tid];
            vm[bh * DH + tid] = s * (1.0f / (float)L_);
        }
    }
}

// ---------------- top-40 per (b,h) -------------------------------------------------
__global__ void topk_kernel(const float* __restrict__ Mv, int* __restrict__ top)
{
    int bh  = blockIdx.x;
    int tid = threadIdx.x;
    int w = tid >> 5, lane = tid & 31;
    __shared__ float sv[L_];
    __shared__ float wv_[8];
    __shared__ int   wi_[8];
    for (int i = tid; i < L_; i += 256) sv[i] = Mv[(size_t)bh * L_ + i];
    __syncthreads();

    for (int r = 0; r < U_; r++) {
        float bv = -1e30f; int bi = 0x7fffffff;
        #pragma unroll
        for (int j = 0; j < 8; j++) {
            int i = tid + j * 256;
            float v = sv[i];
            if (v > bv || (v == bv && i < bi)) { bv = v; bi = i; }
        }
        #pragma unroll
        for (int o = 16; o; o >>= 1) {
            float ov = __shfl_xor_sync(0xffffffffu, bv, o);
            int   oi = __shfl_xor_sync(0xffffffffu, bi, o);
            if (ov > bv || (ov == bv && oi < bi)) { bv = ov; bi = oi; }
        }
        if (lane == 0) { wv_[w] = bv; wi_[w] = bi; }
        __syncthreads();
        if (tid == 0) {
            float fv = wv_[0]; int fi = wi_[0];
            #pragma unroll
            for (int j = 1; j < 8; j++) {
                float ov = wv_[j]; int oi = wi_[j];
                if (ov > fv || (ov == fv && oi < fi)) { fv = ov; fi = oi; }
            }
            top[bh * U_ + r] = fi;
            sv[fi] = -1e30f;
        }
        __syncthreads();
    }
}

// ---------------- fill ctx planes with broadcast v-mean (chunked) ------------------
__global__ void ctxfill_kernel(const float* __restrict__ vm,
                               __nv_bfloat16* __restrict__ chi,
                               __nv_bfloat16* __restrict__ clo)
{
    int i4 = (blockIdx.x * blockDim.x + threadIdx.x) * 4;
    if (i4 >= B_ * L_ * D) return;
    int dfull = i4 & (D - 1);
    int b = i4 / (L_ * D);
    int h = dfull >> 5, d = dfull & 31;
    float4 v = *(const float4*)(vm + ((b << 3) + h) * DH + d);
    uint32_t h01, h23, l01, l23;
    split2(v.x, v.y, h01, l01);
    split2(v.z, v.w, h23, l23);
    size_t o = pidx(i4 >> 8, dfull, 16384);
    *(uint2*)(chi + o) = make_uint2(h01, h23);
    *(uint2*)(clo + o) = make_uint2(l01, l23);
}

// --------- split-KV flash attention part: 4 splits of 512 keys per (b,h) ----------
__global__ __launch_bounds__(256, 1)
void attn_part_kernel(const float* __restrict__ q, const float* __restrict__ k,
                      const float* __restrict__ v, const int* __restrict__ top,
                      float* __restrict__ am, float* __restrict__ al,
                      float* __restrict__ av)
{
    __shared__ float Ks[128][33];
    __shared__ float Vs[128][33];
    __shared__ float qs[40][32];
    __shared__ float ps[8][128];
    __shared__ int   stop[40];

    int blk = blockIdx.x;
    int sp = blk & 3, bh = blk >> 2;
    int b = bh >> 3, h = bh & 7;
    int tid = threadIdx.x, w = tid >> 5, lane = tid & 31;

    if (tid < 40) stop[tid] = top[bh * U_ + tid];
    __syncthreads();
    for (int i = tid; i < 40 * 32; i += 256) {
        int u = i >> 5, d = i & 31;
        qs[u][d] = q[((size_t)b * L_ + stop[u]) * D + h * DH + d];
    }

    float m[5], l[5], acc[5];
    #pragma unroll
    for (int j = 0; j < 5; j++) { m[j] = -1e30f; l[j] = 0.f; acc[j] = 0.f; }
    const float scale = 0.1767766952966369f;
    const float* kb = k + (size_t)b * L_ * D + h * DH;
    const float* vb = v + (size_t)b * L_ * D + h * DH;
    __syncthreads();

    int tstart = sp * 512;
    for (int t0 = tstart; t0 < tstart + 512; t0 += 128) {
        for (int i = tid; i < 128 * 32; i += 256) {
            int r = i >> 5, d = i & 31;
            Ks[r][d] = kb[(size_t)(t0 + r) * D + d];
            Vs[r][d] = vb[(size_t)(t0 + r) * D + d];
        }
        __syncthreads();

        float sj[5][4];
        #pragma unroll
        for (int j = 0; j < 5; j++)
            #pragma unroll
            for (int i = 0; i < 4; i++) sj[j][i] = 0.f;
        #pragma unroll
        for (int d = 0; d < 32; d++) {
            float k0v = Ks[lane][d], k1v = Ks[lane + 32][d];
            float k2v = Ks[lane + 64][d], k3v = Ks[lane + 96][d];
            #pragma unroll
            for (int j = 0; j < 5; j++) {
                float qd = qs[w * 5 + j][d];
                sj[j][0] = fmaf(qd, k0v, sj[j][0]);
                sj[j][1] = fmaf(qd, k1v, sj[j][1]);
                sj[j][2] = fmaf(qd, k2v, sj[j][2]);
                sj[j][3] = fmaf(qd, k3v, sj[j][3]);
            }
        }
        #pragma unroll
        for (int j = 0; j < 5; j++) {
            float s0 = sj[j][0] * scale, s1 = sj[j][1] * scale;
            float s2 = sj[j][2] * scale, s3 = sj[j][3] * scale;
            float tm = fmaxf(fmaxf(s0, s1), fmaxf(s2, s3));
            #pragma unroll
            for (int o = 16; o; o >>= 1) tm = fmaxf(tm, __shfl_xor_sync(0xffffffffu, tm, o));
            float mn   = fmaxf(m[j], tm);
            float corr = __expf(m[j] - mn);
            float p0 = __expf(s0 - mn), p1 = __expf(s1 - mn);
            float p2 = __expf(s2 - mn), p3 = __expf(s3 - mn);
            float psum = p0 + p1 + p2 + p3;
            #pragma unroll
            for (int o = 16; o; o >>= 1) psum += __shfl_xor_sync(0xffffffffu, psum, o);
            l[j] = l[j] * corr + psum;
            m[j] = mn;
            ps[w][lane] = p0; ps[w][lane + 32] = p1; ps[w][lane + 64] = p2; ps[w][lane + 96] = p3;
            __syncwarp();
            float aa = acc[j] * corr;
            const float4* pv4 = (const float4*)ps[w];
            #pragma unroll 8
            for (int kk4 = 0; kk4 < 32; kk4++) {
                float4 p4 = pv4[kk4];
                int kk = kk4 * 4;
                aa = fmaf(p4.x, Vs[kk][lane],     aa);
                aa = fmaf(p4.y, Vs[kk + 1][lane], aa);
                aa = fmaf(p4.z, Vs[kk + 2][lane], aa);
                aa = fmaf(p4.w, Vs[kk + 3][lane], aa);
            }
            acc[j] = aa;
            __syncwarp();
        }
        __syncthreads();
    }
    #pragma unroll
    for (int j = 0; j < 5; j++) {
        int u = w * 5 + j;
        int pidx_ = (bh * 4 + sp) * U_ + u;
        if (lane == 0) { am[pidx_] = m[j]; al[pidx_] = l[j]; }
        av[(size_t)pidx_ * DH + lane] = acc[j];
    }
}

// --------- split-KV combine: merge partials, scatter into ctx planes (chunked) -----
__global__ void attn_combine_kernel(const int* __restrict__ top,
                                    const float* __restrict__ am, const float* __restrict__ al,
                                    const float* __restrict__ av,
                                    __nv_bfloat16* __restrict__ chi, __nv_bfloat16* __restrict__ clo)
{
    int bh = blockIdx.x; int b = bh >> 3, h = bh & 7;
    int tid = threadIdx.x, w = tid >> 5, lane = tid & 31;
    __shared__ int stop[40];
    if (tid < 40) stop[tid] = top[bh * U_ + tid];
    __syncthreads();

    #pragma unroll
    for (int j = 0; j < 5; j++) {
        int u = w * 5 + j;
        int base = bh * 4 * U_ + u;
        float m0 = am[base], m1 = am[base + U_], m2 = am[base + 2*U_], m3 = am[base + 3*U_];
        float ms = fmaxf(fmaxf(m0, m1), fmaxf(m2, m3));
        float e0 = __expf(m0 - ms), e1 = __expf(m1 - ms);
        float e2 = __expf(m2 - ms), e3 = __expf(m3 - ms);
        float Lsum = al[base] * e0 + al[base + U_] * e1 + al[base + 2*U_] * e2 + al[base + 3*U_] * e3;
        float num = av[(size_t)base * DH + lane] * e0
                  + av[(size_t)(base + U_) * DH + lane] * e1
                  + av[(size_t)(base + 2*U_) * DH + lane] * e2
                  + av[(size_t)(base + 3*U_) * DH + lane] * e3;
        float o = num / Lsum;
        size_t off = pidx(b * L_ + stop[u], h * DH + lane, 16384);
        split_scalar(o, chi + off, clo + off);
    }
}

// ---------- LayerNorm of pre-summed input + split (chunked plane writes) -----------
__global__ void add_ln_kernel(const float* __restrict__ sum,
                              const float* __restrict__ g, const float* __restrict__ bb,
                              float* __restrict__ hout,
                              __nv_bfloat16* __restrict__ hhi, __nv_bfloat16* __restrict__ hlo)
{
    int tid = threadIdx.x;
    int rl  = tid >> 7;
    int ct  = tid & 127;
    int row = blockIdx.x * 2 + rl;
    size_t off = (size_t)row * D + ct * 2;
    float2 v = *(const float2*)(sum + off);
    float s1 = v.x + v.y, s2 = v.x * v.x + v.y * v.y;
    #pragma unroll
    for (int o = 16; o; o >>= 1) {
        s1 += __shfl_xor_sync(0xffffffffu, s1, o);
        s2 += __shfl_xor_sync(0xffffffffu, s2, o);
    }
    __shared__ float a1[2][4], a2[2][4], mu[2], rv[2];
    int wr = (tid >> 5) & 3;
    int lane = tid & 31;
    if (lane == 0) { a1[rl][wr] = s1; a2[rl][wr] = s2; }
    __syncthreads();
    if (ct == 0) {
        float t1 = a1[rl][0] + a1[rl][1] + a1[rl][2] + a1[rl][3];
        float t2 = a2[rl][0] + a2[rl][1] + a2[rl][2] + a2[rl][3];
        float m = t1 * (1.0f / (float)D);
        float var = t2 * (1.0f / (float)D) - m * m;
        mu[rl] = m;
        rv[rl] = rsqrtf(var + 1e-5f);
    }
    __syncthreads();
    float m = mu[rl], r = rv[rl];
    float2 gg = *(const float2*)(g + ct * 2);
    float2 b2 = *(const float2*)(bb + ct * 2);
    float2 o;
    o.x = (v.x - m) * r * gg.x + b2.x;
    o.y = (v.y - m) * r * gg.y + b2.y;
    *(float2*)(hout + off) = o;
    uint32_t hi32, lo32;
    split2(o.x, o.y, hi32, lo32);
    size_t po = pidx(row, ct * 2, 16384);
    *(uint32_t*)(hhi + po) = hi32;
    *(uint32_t*)(hlo + po) = lo32;
}

// --------- last-layer attention for row L-1 only ------------------------------------
__global__ __launch_bounds__(256, 1)
void last_attn_kernel(const float* __restrict__ q, const float* __restrict__ k,
                      const float* __restrict__ v, const int* __restrict__ top,
                      const float* __restrict__ vm, float* __restrict__ ctxl)
{
    int bh = blockIdx.x; int b = bh >> 3, h = bh & 7;
    int tid = threadIdx.x;
    __shared__ int memb;
    __shared__ float qs[DH];
    __shared__ float sc[L_];
    __shared__ float red[256];
    __shared__ float part[8][DH];

    if (tid == 0) memb = 0;
    __syncthreads();
    if (tid < U_ && top[bh * U_ + tid] == (L_ - 1)) memb = 1;
    __syncthreads();
    if (!memb) {
        if (tid < DH) ctxl[bh * DH + tid] = vm[bh * DH + tid];
        return;
    }

    if (tid < DH) qs[tid] = q[((size_t)b * L_ + (L_ - 1)) * D + h * DH + tid];
    __syncthreads();

    const float* kb = k + (size_t)b * L_ * D + h * DH;
    const float scale = 0.1767766952966369f;
    float lmax = -1e30f;
    for (int l = tid; l < L_; l += 256) {
        const float4* kr = (const float4*)(kb + (size_t)l * D);
        float dot = 0.0f;
        #pragma unroll
        for (int j = 0; j < 8; j++) {
            float4 kv = __ldg(&kr[j]);
            dot += qs[4*j+0]*kv.x + qs[4*j+1]*kv.y + qs[4*j+2]*kv.z + qs[4*j+3]*kv.w;
        }
        dot *= scale;
        sc[l] = dot;
        lmax = fmaxf(lmax, dot);
    }
    red[tid] = lmax; __syncthreads();
    for (int s = 128; s; s >>= 1) { if (tid < s) red[tid] = fmaxf(red[tid], red[tid + s]); __syncthreads(); }
    float gmax = red[0];
    __syncthreads();
    float lsum = 0.0f;
    for (int l = tid; l < L_; l += 256) {
        float e = __expf(sc[l] - gmax);
        sc[l] = e;
        lsum += e;
    }
    red[tid] = lsum; __syncthreads();
    for (int s = 128; s; s >>= 1) { if (tid < s) red[tid] += red[tid + s]; __syncthreads(); }
    float inv = 1.0f / red[0];
    __syncthreads();

    int d = tid & 31, seg = tid >> 5;
    const float* vb = v + (size_t)b * L_ * D + h * DH + d;
    float acc = 0.0f;
    for (int l = seg; l < L_; l += 8) acc += sc[l] * vb[(size_t)l * D];
    part[seg][d] = acc;
    __syncthreads();
    if (tid < DH) {
        float s = 0.0f;
        #pragma unroll
        for (int i = 0; i < 8; i++) s += part[i][tid];
        ctxl[bh * DH + tid] = s * inv;
    }
}

// --------- final chain for row L-1 ---------------------------------------------------
__global__ __launch_bounds__(256, 1)
void final_head_kernel(const float* __restrict__ h, const float* __restrict__ ctxl,
                       const float* __restrict__ wo2, const float* __restrict__ bo2,
                       const float* __restrict__ ln1g, const float* __restrict__ ln1b,
                       const float* __restrict__ ff1, const float* __restrict__ bf1,
                       const float* __restrict__ ff2, const float* __restrict__ bf2,
                       const float* __restrict__ ln2g, const float* __restrict__ ln2b,
                       const float* __restrict__ w1, const float* __restrict__ b1,
                       const float* __restrict__ w2, const float* __restrict__ b2,
                       float* __restrict__ out)
{
    int b = blockIdx.x;
    int tid = threadIdx.x;
    int w = tid >> 5, lane = tid & 31;
    __shared__ float row[D], ctxr[D], hb1[D], yb[DFF], hb2[D];
    __shared__ float a1[8], a2[8], stat[2];

    row[tid]  = h[((size_t)b * L_ + (L_ - 1)) * D + tid];
    ctxr[tid] = ctxl[b * D + tid];
    __syncthreads();

    float acc = bo2[tid];
    for (int dd = 0; dd < D; dd++) acc = fmaf(ctxr[dd], wo2[dd * D + tid], acc);
    float val = row[tid] + acc;

    {
        float s1 = val, s2 = val * val;
        #pragma unroll
        for (int o = 16; o; o >>= 1) {
            s1 += __shfl_xor_sync(0xffffffffu, s1, o);
            s2 += __shfl_xor_sync(0xffffffffu, s2, o);
        }
        if (lane == 0) { a1[w] = s1; a2[w] = s2; }
        __syncthreads();
        if (tid == 0) {
            float t1 = 0.f, t2 = 0.f;
            #pragma unroll
            for (int j = 0; j < 8; j++) { t1 += a1[j]; t2 += a2[j]; }
            float mu = t1 * (1.0f / (float)D);
            stat[0] = mu;
            stat[1] = rsqrtf(t2 * (1.0f / (float)D) - mu * mu + 1e-5f);
        }
        __syncthreads();
        hb1[tid] = (val - stat[0]) * stat[1] * ln1g[tid] + ln1b[tid];
        __syncthreads();
    }

    #pragma unroll
    for (int jj = 0; jj < 4; jj++) {
        int j = tid + jj * 256;
        float a = bf1[j];
        for (int dd = 0; dd < D; dd++) a = fmaf(hb1[dd], ff1[(size_t)dd * DFF + j], a);
        yb[j] = fmaxf(a, 0.0f);
    }
    __syncthreads();

    float acc2 = bf2[tid];
    for (int dd = 0; dd < DFF; dd++) acc2 = fmaf(yb[dd], ff2[(size_t)dd * D + tid], acc2);
    float val2 = hb1[tid] + acc2;
    {
        float s1 = val2, s2 = val2 * val2;
        #pragma unroll
        for (int o = 16; o; o >>= 1) {
            s1 += __shfl_xor_sync(0xffffffffu, s1, o);
            s2 += __shfl_xor_sync(0xffffffffu, s2, o);
        }
        __syncthreads();
        if (lane == 0) { a1[w] = s1; a2[w] = s2; }
        __syncthreads();
        if (tid == 0) {
            float t1 = 0.f, t2 = 0.f;
            #pragma unroll
            for (int j = 0; j < 8; j++) { t1 += a1[j]; t2 += a2[j]; }
            float mu = t1 * (1.0f / (float)D);
            stat[0] = mu;
            stat[1] = rsqrtf(t2 * (1.0f / (float)D) - mu * mu + 1e-5f);
        }
        __syncthreads();
        hb2[tid] = (val2 - stat[0]) * stat[1] * ln2g[tid] + ln2b[tid];
        __syncthreads();
    }

    __shared__ float th[64];
    if (tid < 64) {
        float a = b1[tid];
        for (int dd = 0; dd < D; dd++) a = fmaf(hb2[dd], w1[dd * 64 + tid], a);
        th[tid] = fmaxf(a, 0.0f) * w2[tid];
    }
    __syncthreads();
    if (tid < 32) {
        float s = th[tid] + th[tid + 32];
        #pragma unroll
        for (int o = 16; o; o >>= 1) s += __shfl_xor_sync(0xffffffffu, s, o);
        if (tid == 0) out[b] = s + b2[0];
    }
}

// ===================================================================================
extern "C" void kernel_launch(void* const* d_in, const int* in_sizes, int n_in,
                              void* d_out, int out_size)
{
    const float* x     = (const float*)d_in[0];
    const int*   idx   = (const int*)  d_in[1];
    const float* w_in  = (const float*)d_in[2];
    const float* b_in  = (const float*)d_in[3];
    const float* wq    = (const float*)d_in[4];
    const float* bq    = (const float*)d_in[5];
    const float* wk    = (const float*)d_in[6];
    const float* bk    = (const float*)d_in[7];
    const float* wv    = (const float*)d_in[8];
    const float* bv    = (const float*)d_in[9];
    const float* wo    = (const float*)d_in[10];
    const float* bo    = (const float*)d_in[11];
    const float* w_ff1 = (const float*)d_in[12];
    const float* b_ff1 = (const float*)d_in[13];
    const float* w_ff2 = (const float*)d_in[14];
    const float* b_ff2 = (const float*)d_in[15];
    const float* ln1_g = (const float*)d_in[16];
    const float* ln1_b = (const float*)d_in[17];
    const float* ln2_g = (const float*)d_in[18];
    const float* ln2_b = (const float*)d_in[19];
    const float* w_fc1 = (const float*)d_in[20];
    const float* b_fc1 = (const float*)d_in[21];
    const float* w_fc2 = (const float*)d_in[22];
    const float* b_fc2 = (const float*)d_in[23];
    float* out = (float*)d_out;

    float *h, *q, *k, *v, *nx, *Mv, *vm, *ctxl, *am, *al, *av; int* top;
    __nv_bfloat16 *xhi, *xlo, *hhi, *hlo, *chi, *clo, *fhi, *flo, *whi, *wlo;
    cudaGetSymbolAddress((void**)&h,   g_h);
    cudaGetSymbolAddress((void**)&q,   g_q);
    cudaGetSymbolAddress((void**)&k,   g_k);
    cudaGetSymbolAddress((void**)&v,   g_v);
    cudaGetSymbolAddress((void**)&nx,  g_nx);
    cudaGetSymbolAddress((void**)&Mv,  g_M);
    cudaGetSymbolAddress((void**)&top, g_top);
    cudaGetSymbolAddress((void**)&vm,  g_vm);
    cudaGetSymbolAddress((void**)&ctxl, g_ctxl);
    cudaGetSymbolAddress((void**)&am,  g_am);
    cudaGetSymbolAddress((void**)&al,  g_al);
    cudaGetSymbolAddress((void**)&av,  g_av);
    cudaGetSymbolAddress((void**)&xhi, g_x_hi);  cudaGetSymbolAddress((void**)&xlo, g_x_lo);
    cudaGetSymbolAddress((void**)&hhi, g_h_hi);  cudaGetSymbolAddress((void**)&hlo, g_h_lo);
    cudaGetSymbolAddress((void**)&chi, g_ctx_hi); cudaGetSymbolAddress((void**)&clo, g_ctx_lo);
    cudaGetSymbolAddress((void**)&fhi, g_ff_hi); cudaGetSymbolAddress((void**)&flo, g_ff_lo);
    cudaGetSymbolAddress((void**)&whi, g_wt_hi); cudaGetSymbolAddress((void**)&wlo, g_wt_lo);

    cudaFuncSetAttribute(mma_gemm_bf16, cudaFuncAttributeMaxDynamicSharedMemorySize, GEMM_SMEM_V4);

    const int Mrows = B_ * L_;
    dim3 gD  (D / 128,   Mrows / 128);
    dim3 gQKV(3 * D / 128, Mrows / 128);
    dim3 gFF (DFF / 128, Mrows / 128);
    dim3 tb(32, 8);

    const size_t o_in = 0;
    auto o_q  = [&](int l){ return (size_t)FIN * D + (size_t)l * LYR_SZ; };
    auto o_o  = [&](int l){ return o_q(l) + 196608; };
    auto o_f1 = [&](int l){ return o_q(l) + 262144; };
    auto o_f2 = [&](int l){ return o_q(l) + 524288; };

    split_kernel<<<(B_ * L_ * FIN) / 512, 256>>>(x, xhi, xlo, B_ * L_ * FIN);
    transpose_all_kernel<<<1544, tb>>>(w_in, wq, wk, wv, wo, w_ff1, w_ff2, whi, wlo);
    mma_gemm_bf16<<<gD, 256, GEMM_SMEM_V4>>>(xhi, xlo, whi + o_in, wlo + o_in,
        b_in, nullptr, nullptr, h, nullptr, nullptr, hhi, hlo, nullptr, Mrows, D, FIN, 0, 3, 0);

    // ---------------- layer 0 (full) ----------------
    {
        const int layer = 0;
        const int* ixL = idx;

        mma_gemm_bf16<<<gQKV, 256, GEMM_SMEM_V4>>>(hhi, hlo, whi + o_q(layer), wlo + o_q(layer),
            bq, bk, bv, q, k, v, nullptr, nullptr, nullptr, Mrows, 768, D, 0, 1, 1);

        qkvm_kernel<<<QK_BLOCKS + B_ * H_, 256>>>(q, k, ixL, Mv, v, vm);
        topk_kernel<<<B_ * H_, 256>>>(Mv, top);
        ctxfill_kernel<<<(B_ * L_ * D) / 1024, 256>>>(vm, chi, clo);
        attn_part_kernel<<<B_ * H_ * 4, 256>>>(q, k, v, top, am, al, av);
        attn_combine_kernel<<<B_ * H_, 256>>>(top, am, al, av, chi, clo);

        mma_gemm_bf16<<<gD, 256, GEMM_SMEM_V4>>>(chi, clo, whi + o_o(layer), wlo + o_o(layer),
            bo, nullptr, nullptr, nx, nullptr, nullptr, nullptr, nullptr, h,
            Mrows, D, D, 0, 1, 0);
        add_ln_kernel<<<Mrows / 2, 256>>>(nx, ln1_g, ln1_b, h, hhi, hlo);

        mma_gemm_bf16<<<gFF, 256, GEMM_SMEM_V4>>>(hhi, hlo, whi + o_f1(layer), wlo + o_f1(layer),
            b_ff1, nullptr, nullptr, nullptr, nullptr, nullptr, fhi, flo, nullptr,
            Mrows, DFF, D, 1, 2, 0);
        mma_gemm_bf16<<<gD, 256, GEMM_SMEM_V4>>>(fhi, flo, whi + o_f2(layer), wlo + o_f2(layer),
            b_ff2, nullptr, nullptr, nx, nullptr, nullptr, nullptr, nullptr, h,
            Mrows, D, DFF, 0, 1, 0);
        add_ln_kernel<<<Mrows / 2, 256>>>(nx, ln2_g, ln2_b, h, hhi, hlo);
    }

    // ---------------- layer 1 (output-funnel pruned) ----------------
    {
        const int layer = 1;
        const int* ixL = idx + (size_t)L_ * S_;

        mma_gemm_bf16<<<gQKV, 256, GEMM_SMEM_V4>>>(hhi, hlo, whi + o_q(layer), wlo + o_q(layer),
            bq + D, bk + D, bv + D, q, k, v, nullptr, nullptr, nullptr, Mrows, 768, D, 0, 1, 1);

        qkvm_kernel<<<QK_BLOCKS + B_ * H_, 256>>>(q, k, ixL, Mv, v, vm);
        topk_kernel<<<B_ * H_, 256>>>(Mv, top);
        last_attn_kernel<<<B_ * H_, 256>>>(q, k, v, top, vm, ctxl);

        final_head_kernel<<<B_, 256>>>(h, ctxl,
            wo + (size_t)D * D, bo + D,
            ln1_g + D, ln1_b + D,
            w_ff1 + (size_t)D * DFF, b_ff1 + DFF,
            w_ff2 + (size_t)DFF * D, b_ff2 + D,
            ln2_g + D, ln2_b + D,
            w_fc1, b_fc1, w_fc2, b_fc2, out);
    }
}